// round 1
// baseline (speedup 1.0000x reference)
#include <cuda_runtime.h>
#include <math.h>

#define B_   2
#define N_   2048
#define D_   1024
#define INT_ 256
#define H_   4
#define HD_  64
#define HID_ 512
#define L_   6
#define M_   (B_*N_)   // 4096 rows

// ---------------- scratch (no allocation allowed) ----------------
__device__ float g_X  [M_ * D_];        // running trunk activations
__device__ float g_H  [M_ * INT_];      // h (post down-proj / residual stream)
__device__ float g_HN [M_ * INT_];      // layernorm output
__device__ float g_QKV[M_ * 3 * INT_];  // qkv
__device__ float g_ATT[M_ * INT_];      // attention output (b,n,h,d flattened)
__device__ float g_G1 [M_ * HID_];      // mlp hidden

// ---------------- GEMM: C = A @ W^T (+bias, epilogue variants) ----------------
// A: [M,K] row-major, W: [N,K] row-major. M=4096 always. BM=128, BN=64, BK=16.
// EPI: 0 = +bias ; 1 = gelu(+bias) ; 2 = res + (+bias) ; 3 = res + gamma*( +bias )
#define BM 128
#define BN 64
#define BK 16

__device__ __forceinline__ float gelu_f(float x) {
    return 0.5f * x * (1.0f + erff(x * 0.70710678118654752440f));
}

template<int EPI>
__global__ __launch_bounds__(256) void gemm_kernel(
    const float* __restrict__ A, const float* __restrict__ W,
    const float* __restrict__ bias, const float* __restrict__ res,
    const float* __restrict__ gamma, float* __restrict__ C,
    int K, int N)
{
    __shared__ float As[BK][BM + 4];
    __shared__ float Bs[BK][BN + 4];
    const int tid = threadIdx.x;
    const int tx = tid & 15;        // 0..15 -> 4 output cols
    const int ty = tid >> 4;        // 0..15 -> 8 output rows
    const int bm = blockIdx.y * BM;
    const int bn = blockIdx.x * BN;

    float acc[8][4];
#pragma unroll
    for (int i = 0; i < 8; i++)
#pragma unroll
        for (int j = 0; j < 4; j++) acc[i][j] = 0.f;

    const float* Ap = A + (size_t)bm * K;
    const float* Wp = W + (size_t)bn * K;

    for (int k0 = 0; k0 < K; k0 += BK) {
        // A tile: 128x16 floats = 512 float4, 2 per thread, stored transposed
#pragma unroll
        for (int i = 0; i < 2; i++) {
            int fi = tid + i * 256;
            int r  = fi >> 2;                 // 0..127
            int kc = (fi & 3) << 2;           // 0,4,8,12
            float4 v = *(const float4*)(Ap + (size_t)r * K + k0 + kc);
            As[kc    ][r] = v.x;
            As[kc + 1][r] = v.y;
            As[kc + 2][r] = v.z;
            As[kc + 3][r] = v.w;
        }
        // W tile: 64x16 floats = 256 float4, 1 per thread, stored transposed
        {
            int r  = tid >> 2;                // 0..63
            int kc = (tid & 3) << 2;
            float4 v = *(const float4*)(Wp + (size_t)r * K + k0 + kc);
            Bs[kc    ][r] = v.x;
            Bs[kc + 1][r] = v.y;
            Bs[kc + 2][r] = v.z;
            Bs[kc + 3][r] = v.w;
        }
        __syncthreads();
#pragma unroll
        for (int kk = 0; kk < BK; kk++) {
            float4 a0 = *(const float4*)&As[kk][ty * 8];
            float4 a1 = *(const float4*)&As[kk][ty * 8 + 4];
            float4 bv = *(const float4*)&Bs[kk][tx * 4];
            float a[8] = {a0.x, a0.y, a0.z, a0.w, a1.x, a1.y, a1.z, a1.w};
            float bb[4] = {bv.x, bv.y, bv.z, bv.w};
#pragma unroll
            for (int i = 0; i < 8; i++)
#pragma unroll
                for (int j = 0; j < 4; j++)
                    acc[i][j] = fmaf(a[i], bb[j], acc[i][j]);
        }
        __syncthreads();
    }

    const int col = bn + tx * 4;
    float bvals[4] = {0.f, 0.f, 0.f, 0.f};
    if (bias) {
        float4 b4 = *(const float4*)(bias + col);
        bvals[0] = b4.x; bvals[1] = b4.y; bvals[2] = b4.z; bvals[3] = b4.w;
    }
    float gvals[4] = {0.f, 0.f, 0.f, 0.f};
    if (EPI == 3) {
        float4 g4 = *(const float4*)(gamma + col);
        gvals[0] = g4.x; gvals[1] = g4.y; gvals[2] = g4.z; gvals[3] = g4.w;
    }
#pragma unroll
    for (int i = 0; i < 8; i++) {
        int row = bm + ty * 8 + i;
        size_t off = (size_t)row * N + col;
        float rr[4] = {0.f, 0.f, 0.f, 0.f};
        if (EPI == 2 || EPI == 3) {
            float4 r4 = *(const float4*)(res + off);
            rr[0] = r4.x; rr[1] = r4.y; rr[2] = r4.z; rr[3] = r4.w;
        }
        float o[4];
#pragma unroll
        for (int j = 0; j < 4; j++) {
            float v = acc[i][j] + bvals[j];
            if (EPI == 1) v = gelu_f(v);
            else if (EPI == 2) v = rr[j] + v;
            else if (EPI == 3) v = rr[j] + gvals[j] * v;
            o[j] = v;
        }
        float4 o4 = make_float4(o[0], o[1], o[2], o[3]);
        *(float4*)(C + off) = o4;
    }
}

// ---------------- LayerNorm over rows of 256, one warp per row ----------------
__global__ __launch_bounds__(256) void ln_kernel(
    const float* __restrict__ in, const float* __restrict__ s,
    const float* __restrict__ b, float* __restrict__ out)
{
    int gw   = (blockIdx.x * blockDim.x + threadIdx.x) >> 5;
    int lane = threadIdx.x & 31;
    if (gw >= M_) return;
    const float* x = in + (size_t)gw * INT_;
    float v[8];
    float sum = 0.f, sq = 0.f;
#pragma unroll
    for (int i = 0; i < 8; i++) {
        v[i] = x[lane + 32 * i];
        sum += v[i];
        sq  += v[i] * v[i];
    }
#pragma unroll
    for (int o = 16; o > 0; o >>= 1) {
        sum += __shfl_xor_sync(0xffffffffu, sum, o);
        sq  += __shfl_xor_sync(0xffffffffu, sq,  o);
    }
    float mean = sum * (1.f / 256.f);
    float var  = sq * (1.f / 256.f) - mean * mean;
    float rstd = rsqrtf(var + 1e-5f);
    float* y = out + (size_t)gw * INT_;
#pragma unroll
    for (int i = 0; i < 8; i++) {
        int d = lane + 32 * i;
        y[d] = (v[i] - mean) * rstd * s[d] + b[d];
    }
}

// ---------------- RoPE + logn scaling, in-place on qkv ----------------
// thread idx encodes (b, n, h, d) with d in 0..31; handles pairs (d, d+32) for q and k.
__global__ __launch_bounds__(256) void rope_kernel(float* __restrict__ qkv)
{
    int idx = blockIdx.x * blockDim.x + threadIdx.x;   // < B*N*H*32 = 524288
    int d = idx & 31;
    int h = (idx >> 5) & (H_ - 1);
    int n = (idx >> 7) & (N_ - 1);
    int b = idx >> 18;

    float inv = expf(-(float)d * (logf(10000.0f) * (1.0f / 32.0f)));
    float ph  = (float)n * inv;
    float sn, cs;
    sincosf(ph, &sn, &cs);
    float pos = (float)(n + 1);
    float lns = fmaxf(1.0f, logf(pos) * (1.0f / logf(64.0f)));

    size_t base = ((size_t)(b * N_ + n)) * 768 + h * 64 + d;
    float q0 = qkv[base], q1 = qkv[base + 32];
    qkv[base]      = (q0 * cs - q1 * sn) * lns;
    qkv[base + 32] = (q1 * cs + q0 * sn) * lns;
    float k0 = qkv[base + 256], k1 = qkv[base + 288];
    qkv[base + 256] = k0 * cs - k1 * sn;
    qkv[base + 288] = k1 * cs + k0 * sn;
}

// ---------------- Flash attention: full (non-causal), fp32 ----------------
// grid: (N/64, B*H). 256 threads (16x16), 4x4 per thread for both 64x64x64 GEMMs.
// smem: Qt[64][68] d-major, KPt[64][68] (K^T then reused for P^T), Vs[64][64].
#define ATT_SMEM ((2 * 64 * 68 + 64 * 64) * 4)

__global__ __launch_bounds__(256) void attn_kernel(
    const float* __restrict__ qkv, float* __restrict__ out)
{
    extern __shared__ float sm[];
    float* Qt  = sm;                  // [64][68], indexed [d][r]
    float* KPt = sm + 64 * 68;        // [64][68], [d][c] for K, [k][r] for P
    float* Vs  = sm + 2 * 64 * 68;    // [64][64], [k][d]

    const int tid = threadIdx.x;
    const int tx = tid & 15;          // key-col / value-col group
    const int ty = tid >> 4;          // query-row group
    const int bh = blockIdx.y;
    const int b = bh >> 2, h = bh & 3;
    const int q0 = blockIdx.x * 64;
    const float* base = qkv + (size_t)b * N_ * 768 + h * 64;

    // load Q tile transposed (d-major)
#pragma unroll
    for (int i = 0; i < 4; i++) {
        int fi = tid + i * 256;       // 0..1023
        int r  = fi >> 4;             // 0..63
        int dc = (fi & 15) << 2;
        float4 v = *(const float4*)(base + (size_t)(q0 + r) * 768 + dc);
        Qt[(dc    ) * 68 + r] = v.x;
        Qt[(dc + 1) * 68 + r] = v.y;
        Qt[(dc + 2) * 68 + r] = v.z;
        Qt[(dc + 3) * 68 + r] = v.w;
    }

    float m_i[4], l_i[4], O[4][4];
#pragma unroll
    for (int i = 0; i < 4; i++) {
        m_i[i] = -INFINITY;
        l_i[i] = 0.f;
#pragma unroll
        for (int j = 0; j < 4; j++) O[i][j] = 0.f;
    }
    const float scale = 0.125f;   // 1/sqrt(64)

    for (int kt = 0; kt < N_ / 64; kt++) {
        __syncthreads();   // Q visible (iter 0); prior PV reads of KPt/Vs done
        // load K (transposed) and V tiles
#pragma unroll
        for (int i = 0; i < 4; i++) {
            int fi = tid + i * 256;
            int r  = fi >> 4;
            int dc = (fi & 15) << 2;
            const float* kp = base + (size_t)(kt * 64 + r) * 768 + dc;
            float4 kv = *(const float4*)(kp + 256);
            KPt[(dc    ) * 68 + r] = kv.x;
            KPt[(dc + 1) * 68 + r] = kv.y;
            KPt[(dc + 2) * 68 + r] = kv.z;
            KPt[(dc + 3) * 68 + r] = kv.w;
            float4 vv = *(const float4*)(kp + 512);
            *(float4*)&Vs[r * 64 + dc] = vv;
        }
        __syncthreads();

        // S = Q K^T  (4x4 per thread)
        float S[4][4];
#pragma unroll
        for (int i = 0; i < 4; i++)
#pragma unroll
            for (int j = 0; j < 4; j++) S[i][j] = 0.f;
#pragma unroll
        for (int d = 0; d < 64; d++) {
            float4 a  = *(const float4*)&Qt [d * 68 + ty * 4];
            float4 bb = *(const float4*)&KPt[d * 68 + tx * 4];
            float av[4] = {a.x, a.y, a.z, a.w};
            float bv[4] = {bb.x, bb.y, bb.z, bb.w};
#pragma unroll
            for (int i = 0; i < 4; i++)
#pragma unroll
                for (int j = 0; j < 4; j++)
                    S[i][j] = fmaf(av[i], bv[j], S[i][j]);
        }

        // online softmax per query row (reduce over 16-lane groups)
        float P[4][4];
#pragma unroll
        for (int i = 0; i < 4; i++) {
            float mt = fmaxf(fmaxf(S[i][0], S[i][1]), fmaxf(S[i][2], S[i][3])) * scale;
#pragma unroll
            for (int o = 8; o > 0; o >>= 1)
                mt = fmaxf(mt, __shfl_xor_sync(0xffffffffu, mt, o));
            float mn = fmaxf(m_i[i], mt);
            float alpha = __expf(m_i[i] - mn);
            m_i[i] = mn;
            float rs = 0.f;
#pragma unroll
            for (int j = 0; j < 4; j++) {
                float p = __expf(fmaf(S[i][j], scale, -mn));
                P[i][j] = p;
                rs += p;
            }
#pragma unroll
            for (int o = 8; o > 0; o >>= 1)
                rs += __shfl_xor_sync(0xffffffffu, rs, o);
            l_i[i] = l_i[i] * alpha + rs;
#pragma unroll
            for (int j = 0; j < 4; j++) O[i][j] *= alpha;
        }
        __syncthreads();   // everyone done reading KPt as K^T

        // write P transposed: Pt[k][r]
#pragma unroll
        for (int j = 0; j < 4; j++) {
            float4 pv = make_float4(P[0][j], P[1][j], P[2][j], P[3][j]);
            *(float4*)&KPt[(tx * 4 + j) * 68 + ty * 4] = pv;
        }
        __syncthreads();

        // O += P V
#pragma unroll
        for (int k = 0; k < 64; k++) {
            float4 a  = *(const float4*)&KPt[k * 68 + ty * 4];
            float4 vv = *(const float4*)&Vs [k * 64 + tx * 4];
            float av[4] = {a.x, a.y, a.z, a.w};
            float bv[4] = {vv.x, vv.y, vv.z, vv.w};
#pragma unroll
            for (int i = 0; i < 4; i++)
#pragma unroll
                for (int j = 0; j < 4; j++)
                    O[i][j] = fmaf(av[i], bv[j], O[i][j]);
        }
    }

    // write normalized output: out[(b*N+row)*256 + h*64 + col]
#pragma unroll
    for (int i = 0; i < 4; i++) {
        float inv = 1.0f / l_i[i];
        int row = q0 + ty * 4 + i;
        float4 o4 = make_float4(O[i][0] * inv, O[i][1] * inv,
                                O[i][2] * inv, O[i][3] * inv);
        *(float4*)&out[((size_t)(b * N_ + row)) * INT_ + h * 64 + tx * 4] = o4;
    }
}

// ---------------- host ----------------
extern "C" void kernel_launch(void* const* d_in, const int* in_sizes, int n_in,
                              void* d_out, int out_size)
{
    (void)in_sizes; (void)n_in; (void)out_size;
    const float* x   = (const float*)d_in[0];
    const float* dw  = (const float*)d_in[1];
    const float* db  = (const float*)d_in[2];
    const float* nds = (const float*)d_in[3];
    const float* ndb = (const float*)d_in[4];
    const float* qw  = (const float*)d_in[5];
    const float* pw  = (const float*)d_in[6];
    const float* pb  = (const float*)d_in[7];
    const float* nms = (const float*)d_in[8];
    const float* nmb = (const float*)d_in[9];
    const float* m1w = (const float*)d_in[10];
    const float* m1b = (const float*)d_in[11];
    const float* m2w = (const float*)d_in[12];
    const float* m2b = (const float*)d_in[13];
    const float* uw  = (const float*)d_in[14];
    const float* ub  = (const float*)d_in[15];
    const float* gm  = (const float*)d_in[16];

    float *X, *Hb, *HN, *QKV, *ATT, *G1;
    cudaGetSymbolAddress((void**)&X,   g_X);
    cudaGetSymbolAddress((void**)&Hb,  g_H);
    cudaGetSymbolAddress((void**)&HN,  g_HN);
    cudaGetSymbolAddress((void**)&QKV, g_QKV);
    cudaGetSymbolAddress((void**)&ATT, g_ATT);
    cudaGetSymbolAddress((void**)&G1,  g_G1);

    cudaFuncSetAttribute(attn_kernel,
                         cudaFuncAttributeMaxDynamicSharedMemorySize, ATT_SMEM);

    const dim3 thr(256);
    const int gy = M_ / BM;   // 32

    for (int l = 0; l < L_; l++) {
        const float* xin = (l == 0) ? x : X;
        float* xout = (l == L_ - 1) ? (float*)d_out : X;

        // h = x @ down_w^T + down_b
        gemm_kernel<0><<<dim3(INT_ / BN, gy), thr>>>(
            xin, dw + (size_t)l * INT_ * D_, db + (size_t)l * INT_,
            nullptr, nullptr, Hb, D_, INT_);
        // hn = LN(h)
        ln_kernel<<<(M_ * 32) / 256, thr>>>(Hb, nds + (size_t)l * INT_,
                                            ndb + (size_t)l * INT_, HN);
        // qkv = hn @ qkv_w^T
        gemm_kernel<0><<<dim3((3 * INT_) / BN, gy), thr>>>(
            HN, qw + (size_t)l * 3 * INT_ * INT_, nullptr,
            nullptr, nullptr, QKV, INT_, 3 * INT_);
        // rope + logn (in place)
        rope_kernel<<<(B_ * N_ * H_ * 32) / 256, thr>>>(QKV);
        // attention
        attn_kernel<<<dim3(N_ / 64, B_ * H_), thr, ATT_SMEM>>>(QKV, ATT);
        // h = res + (o @ proj_w^T + proj_b)
        gemm_kernel<2><<<dim3(INT_ / BN, gy), thr>>>(
            ATT, pw + (size_t)l * INT_ * INT_, pb + (size_t)l * INT_,
            Hb, nullptr, Hb, INT_, INT_);
        // m = LN(h)
        ln_kernel<<<(M_ * 32) / 256, thr>>>(Hb, nms + (size_t)l * INT_,
                                            nmb + (size_t)l * INT_, HN);
        // g1 = gelu(m @ m1^T + b1)
        gemm_kernel<1><<<dim3(HID_ / BN, gy), thr>>>(
            HN, m1w + (size_t)l * HID_ * INT_, m1b + (size_t)l * HID_,
            nullptr, nullptr, G1, INT_, HID_);
        // h = h + (g1 @ m2^T + b2)
        gemm_kernel<2><<<dim3(INT_ / BN, gy), thr>>>(
            G1, m2w + (size_t)l * INT_ * HID_, m2b + (size_t)l * INT_,
            Hb, nullptr, Hb, HID_, INT_);
        // x = shortcut + gamma * (h @ up^T + ub)
        gemm_kernel<3><<<dim3(D_ / BN, gy), thr>>>(
            Hb, uw + (size_t)l * D_ * INT_, ub + (size_t)l * D_,
            xin, gm + (size_t)l * D_, xout, INT_, D_);
    }
}

// round 4
// speedup vs baseline: 3.6867x; 3.6867x over previous
#include <cuda_runtime.h>
#include <cuda_bf16.h>
#include <math.h>
#include <stdint.h>

#define B_   2
#define N_   2048
#define D_   1024
#define INT_ 256
#define H_   4
#define HD_  64
#define HID_ 512
#define L_   6
#define M_   (B_*N_)   // 4096 rows

typedef __nv_bfloat16 bf16;

// ==================== scratch ====================
__device__ float g_X  [M_ * D_];
__device__ float g_H  [M_ * INT_];
__device__ float g_QKV[M_ * 3 * INT_];
__device__ bf16  g_qkvbf[M_ * 3 * INT_];
__device__ bf16  g_xbf [M_ * D_];
__device__ bf16  g_hnbf[M_ * INT_];
__device__ bf16  g_attbf[M_ * INT_];
__device__ bf16  g_g1bf[M_ * HID_];
__device__ bf16  g_hbf [M_ * INT_];
// bf16 weights
__device__ bf16 g_wdown[L_ * INT_ * D_];
__device__ bf16 g_wqkv [L_ * 3 * INT_ * INT_];
__device__ bf16 g_wproj[L_ * INT_ * INT_];
__device__ bf16 g_wm1  [L_ * HID_ * INT_];
__device__ bf16 g_wm2  [L_ * INT_ * HID_];
__device__ bf16 g_wup  [L_ * D_ * INT_];

// ==================== helpers ====================
__device__ __forceinline__ uint32_t packbf(float a, float b) {
    __nv_bfloat162 t = __floats2bfloat162_rn(a, b);
    return *reinterpret_cast<uint32_t*>(&t);
}

__device__ __forceinline__ void mma16816(float* d, const uint32_t* a, uint32_t b0, uint32_t b1) {
    asm volatile(
        "mma.sync.aligned.m16n8k16.row.col.f32.bf16.bf16.f32 "
        "{%0,%1,%2,%3}, {%4,%5,%6,%7}, {%8,%9}, {%0,%1,%2,%3};"
        : "+f"(d[0]), "+f"(d[1]), "+f"(d[2]), "+f"(d[3])
        : "r"(a[0]), "r"(a[1]), "r"(a[2]), "r"(a[3]), "r"(b0), "r"(b1));
}

__device__ __forceinline__ uint32_t smem_u32(const void* p) {
    uint32_t a;
    asm("{ .reg .u64 t; cvta.to.shared.u64 t, %1; cvt.u32.u64 %0, t; }" : "=r"(a) : "l"(p));
    return a;
}

// ==================== fp32 -> bf16 convert ====================
__global__ __launch_bounds__(256) void f2bf_kernel(const float* __restrict__ in,
                                                   bf16* __restrict__ out, int n)
{
    int i = (blockIdx.x * 256 + threadIdx.x) * 4;
    if (i >= n) return;
    float4 v = *(const float4*)(in + i);
    uint2 u = make_uint2(packbf(v.x, v.y), packbf(v.z, v.w));
    *reinterpret_cast<uint2*>(out + i) = u;
}

// ==================== mma.sync bf16 GEMM ====================
// C[M,N] = A[M,K] @ W[N,K]^T. Block 128x128, 8 warps, warp 64x32, K chunk 64.
// EPI: 0 = +bias -> fp32 C ; 1 = gelu(+bias) -> bf16 Cbf only ;
//      2 = res + (+bias) -> fp32 C (+ optional bf16 Cbf) ;
//      3 = res + gamma*(+bias) -> fp32 C (+ optional bf16 Cbf)
__device__ __forceinline__ float gelu_f(float x) {
    return 0.5f * x * (1.0f + erff(x * 0.70710678118654752440f));
}

template<int EPI>
__global__ __launch_bounds__(256) void gemm_mma(
    const bf16* __restrict__ A, const bf16* __restrict__ W,
    const float* __restrict__ bias, const float* __restrict__ res,
    const float* __restrict__ gamma, float* __restrict__ C,
    bf16* __restrict__ Cbf, int K, int N)
{
    __shared__ __align__(16) bf16 As[128][72];
    __shared__ __align__(16) bf16 Bs[128][72];

    const int tid  = threadIdx.x;
    const int lane = tid & 31;
    const int wid  = tid >> 5;
    const int g  = lane >> 2;
    const int tg = lane & 3;
    const int wm = wid & 1;       // 0..1  -> 64 rows
    const int wn = wid >> 1;      // 0..3  -> 32 cols
    const int bm = blockIdx.y * 128;
    const int bn = blockIdx.x * 128;

    float acc[4][4][4];
#pragma unroll
    for (int ma = 0; ma < 4; ma++)
#pragma unroll
        for (int na = 0; na < 4; na++)
#pragma unroll
            for (int r = 0; r < 4; r++) acc[ma][na][r] = 0.f;

    const bf16* Ab = A + (size_t)bm * K;
    const bf16* Wb = W + (size_t)bn * K;

    for (int k0 = 0; k0 < K; k0 += 64) {
        __syncthreads();
#pragma unroll
        for (int i = 0; i < 4; i++) {
            int v = tid + i * 256;
            int r = v >> 3, s = v & 7;
            *(uint4*)&As[r][s * 8] = *(const uint4*)(Ab + (size_t)r * K + k0 + s * 8);
        }
#pragma unroll
        for (int i = 0; i < 4; i++) {
            int v = tid + i * 256;
            int r = v >> 3, s = v & 7;
            *(uint4*)&Bs[r][s * 8] = *(const uint4*)(Wb + (size_t)r * K + k0 + s * 8);
        }
        __syncthreads();

#pragma unroll
        for (int kc = 0; kc < 4; kc++) {
            uint32_t bfr[4][2];
#pragma unroll
            for (int na = 0; na < 4; na++) {
                const int rb = wn * 32 + na * 8 + g;
                bfr[na][0] = *(const uint32_t*)&Bs[rb][kc * 16 + tg * 2];
                bfr[na][1] = *(const uint32_t*)&Bs[rb][kc * 16 + 8 + tg * 2];
            }
#pragma unroll
            for (int ma = 0; ma < 4; ma++) {
                const int r0 = wm * 64 + ma * 16 + g;
                uint32_t af[4];
                af[0] = *(const uint32_t*)&As[r0    ][kc * 16 + tg * 2];
                af[1] = *(const uint32_t*)&As[r0 + 8][kc * 16 + tg * 2];
                af[2] = *(const uint32_t*)&As[r0    ][kc * 16 + 8 + tg * 2];
                af[3] = *(const uint32_t*)&As[r0 + 8][kc * 16 + 8 + tg * 2];
#pragma unroll
                for (int na = 0; na < 4; na++)
                    mma16816(acc[ma][na], af, bfr[na][0], bfr[na][1]);
            }
        }
    }

    // ---------------- epilogue ----------------
#pragma unroll
    for (int ma = 0; ma < 4; ma++) {
        const int row0 = bm + wm * 64 + ma * 16 + g;
        const int row1 = row0 + 8;
#pragma unroll
        for (int na = 0; na < 4; na++) {
            const int col = bn + wn * 32 + na * 8 + tg * 2;
            float bx = 0.f, by = 0.f;
            if (bias) {
                float2 b2 = *(const float2*)(bias + col);
                bx = b2.x; by = b2.y;
            }
            float v00 = acc[ma][na][0] + bx, v01 = acc[ma][na][1] + by;
            float v10 = acc[ma][na][2] + bx, v11 = acc[ma][na][3] + by;
            const size_t o0 = (size_t)row0 * N + col;
            const size_t o1 = (size_t)row1 * N + col;
            if (EPI == 1) {
                v00 = gelu_f(v00); v01 = gelu_f(v01);
                v10 = gelu_f(v10); v11 = gelu_f(v11);
            } else if (EPI == 2) {
                float2 r0 = *(const float2*)(res + o0);
                float2 r1 = *(const float2*)(res + o1);
                v00 += r0.x; v01 += r0.y; v10 += r1.x; v11 += r1.y;
            } else if (EPI == 3) {
                float2 r0 = *(const float2*)(res + o0);
                float2 r1 = *(const float2*)(res + o1);
                float2 g2 = *(const float2*)(gamma + col);
                v00 = r0.x + g2.x * v00; v01 = r0.y + g2.y * v01;
                v10 = r1.x + g2.x * v10; v11 = r1.y + g2.y * v11;
            }
            if (EPI != 1) {
                *(float2*)(C + o0) = make_float2(v00, v01);
                *(float2*)(C + o1) = make_float2(v10, v11);
            }
            if (EPI == 1 || Cbf != nullptr) {
                *(uint32_t*)(Cbf + o0) = packbf(v00, v01);
                *(uint32_t*)(Cbf + o1) = packbf(v10, v11);
            }
        }
    }
}

// ==================== LayerNorm (rows of 256) -> bf16 ====================
__global__ __launch_bounds__(256) void ln_kernel(
    const float* __restrict__ in, const float* __restrict__ s,
    const float* __restrict__ b, bf16* __restrict__ out)
{
    int gw   = (blockIdx.x * blockDim.x + threadIdx.x) >> 5;
    int lane = threadIdx.x & 31;
    if (gw >= M_) return;
    const float* x = in + (size_t)gw * INT_;
    float v[8], sum = 0.f, sq = 0.f;
#pragma unroll
    for (int i = 0; i < 8; i++) {
        v[i] = x[lane + 32 * i];
        sum += v[i]; sq += v[i] * v[i];
    }
#pragma unroll
    for (int o = 16; o > 0; o >>= 1) {
        sum += __shfl_xor_sync(0xffffffffu, sum, o);
        sq  += __shfl_xor_sync(0xffffffffu, sq,  o);
    }
    float mean = sum * (1.f / 256.f);
    float var  = sq * (1.f / 256.f) - mean * mean;
    float rstd = rsqrtf(var + 1e-5f);
    bf16* y = out + (size_t)gw * INT_;
#pragma unroll
    for (int i = 0; i < 8; i++) {
        int d = lane + 32 * i;
        y[d] = __float2bfloat16((v[i] - mean) * rstd * s[d] + b[d]);
    }
}

// ==================== RoPE + logn + 1/sqrt(hd) fold -> bf16 qkv ====================
__global__ __launch_bounds__(256) void rope_kernel(const float* __restrict__ qkv,
                                                   bf16* __restrict__ qbf)
{
    int idx = blockIdx.x * blockDim.x + threadIdx.x;   // B*N*H*32
    int d = idx & 31;
    int h = (idx >> 5) & (H_ - 1);
    int n = (idx >> 7) & (N_ - 1);
    int b = idx >> 18;

    float inv = expf(-(float)d * (logf(10000.0f) * (1.0f / 32.0f)));
    float ph  = (float)n * inv;
    float sn, cs;
    sincosf(ph, &sn, &cs);
    float lns = fmaxf(1.0f, logf((float)(n + 1)) * (1.0f / logf(64.0f)));
    lns *= 0.125f;   // fold softmax scale 1/sqrt(64) into q

    size_t base = ((size_t)(b * N_ + n)) * 768 + h * 64 + d;
    float q0 = qkv[base], q1 = qkv[base + 32];
    qbf[base]       = __float2bfloat16((q0 * cs - q1 * sn) * lns);
    qbf[base + 32]  = __float2bfloat16((q1 * cs + q0 * sn) * lns);
    float k0 = qkv[base + 256], k1 = qkv[base + 288];
    qbf[base + 256] = __float2bfloat16(k0 * cs - k1 * sn);
    qbf[base + 288] = __float2bfloat16(k1 * cs + k0 * sn);
    qbf[base + 512] = __float2bfloat16(qkv[base + 512]);
    qbf[base + 544] = __float2bfloat16(qkv[base + 544]);
}

// ==================== Flash attention, mma.sync bf16 ====================
// CTA: 128 threads (4 warps), 64-query tile. grid (N/64, B*H).
__global__ __launch_bounds__(128) void attn_mma(const bf16* __restrict__ qkv,
                                                bf16* __restrict__ out)
{
    __shared__ __align__(16) bf16 Qs[64][72];
    __shared__ __align__(16) bf16 Ks[64][72];
    __shared__ __align__(16) bf16 Vs[64][72];

    const int tid  = threadIdx.x;
    const int lane = tid & 31;
    const int w    = tid >> 5;
    const int g  = lane >> 2;
    const int tg = lane & 3;
    const int bh = blockIdx.y;
    const int b = bh >> 2, h = bh & 3;
    const int q0 = blockIdx.x * 64;
    const bf16* base = qkv + (size_t)b * N_ * 768 + h * 64;

    // load Q tile (row-major, 64x64 bf16)
#pragma unroll
    for (int i = 0; i < 4; i++) {
        int v = tid + i * 128;
        int r = v >> 3, s = v & 7;
        *(uint4*)&Qs[r][s * 8] = *(const uint4*)(base + (size_t)(q0 + r) * 768 + s * 8);
    }
    __syncthreads();

    // hoist Q fragments (row block = w*16)
    uint32_t qf[4][4];
    {
        const int r0 = w * 16 + g;
#pragma unroll
        for (int kc = 0; kc < 4; kc++) {
            qf[kc][0] = *(const uint32_t*)&Qs[r0    ][kc * 16 + tg * 2];
            qf[kc][1] = *(const uint32_t*)&Qs[r0 + 8][kc * 16 + tg * 2];
            qf[kc][2] = *(const uint32_t*)&Qs[r0    ][kc * 16 + 8 + tg * 2];
            qf[kc][3] = *(const uint32_t*)&Qs[r0 + 8][kc * 16 + 8 + tg * 2];
        }
    }

    // ldmatrix lane address pieces for V (x4.trans)
    const uint32_t vs_base = smem_u32(&Vs[0][0]);
    const int q4 = lane >> 3;                       // quadrant
    const int v_rowpart = (lane & 7) + 8 * (q4 & 1);
    const int v_colpart = 8 * (q4 >> 1);

    float m0 = -INFINITY, m1 = -INFINITY, l0 = 0.f, l1 = 0.f;
    float o[8][4];
#pragma unroll
    for (int nh = 0; nh < 8; nh++)
#pragma unroll
        for (int r = 0; r < 4; r++) o[nh][r] = 0.f;

    for (int kt = 0; kt < N_ / 64; kt++) {
        __syncthreads();
        const bf16* kb = base + (size_t)(kt * 64) * 768 + 256;
#pragma unroll
        for (int i = 0; i < 4; i++) {
            int v = tid + i * 128;
            int r = v >> 3, s = v & 7;
            *(uint4*)&Ks[r][s * 8] = *(const uint4*)(kb + (size_t)r * 768 + s * 8);
            *(uint4*)&Vs[r][s * 8] = *(const uint4*)(kb + (size_t)r * 768 + 256 + s * 8);
        }
        __syncthreads();

        // ---- S = Q K^T ----
        float s[8][4];
#pragma unroll
        for (int na = 0; na < 8; na++)
#pragma unroll
            for (int r = 0; r < 4; r++) s[na][r] = 0.f;
#pragma unroll
        for (int kc = 0; kc < 4; kc++) {
#pragma unroll
            for (int na = 0; na < 8; na++) {
                const int rb = na * 8 + g;
                uint32_t b0 = *(const uint32_t*)&Ks[rb][kc * 16 + tg * 2];
                uint32_t b1 = *(const uint32_t*)&Ks[rb][kc * 16 + 8 + tg * 2];
                mma16816(s[na], qf[kc], b0, b1);
            }
        }

        // ---- online softmax (rows g and g+8 of this warp's 16-row tile) ----
        float mt0 = -INFINITY, mt1 = -INFINITY;
#pragma unroll
        for (int na = 0; na < 8; na++) {
            mt0 = fmaxf(mt0, fmaxf(s[na][0], s[na][1]));
            mt1 = fmaxf(mt1, fmaxf(s[na][2], s[na][3]));
        }
#pragma unroll
        for (int x = 1; x <= 2; x <<= 1) {
            mt0 = fmaxf(mt0, __shfl_xor_sync(0xffffffffu, mt0, x));
            mt1 = fmaxf(mt1, __shfl_xor_sync(0xffffffffu, mt1, x));
        }
        float mn0 = fmaxf(m0, mt0), mn1 = fmaxf(m1, mt1);
        float al0 = __expf(m0 - mn0), al1 = __expf(m1 - mn1);
        m0 = mn0; m1 = mn1;

        float rs0 = 0.f, rs1 = 0.f;
#pragma unroll
        for (int na = 0; na < 8; na++) {
            s[na][0] = __expf(s[na][0] - mn0);
            s[na][1] = __expf(s[na][1] - mn0);
            s[na][2] = __expf(s[na][2] - mn1);
            s[na][3] = __expf(s[na][3] - mn1);
            rs0 += s[na][0] + s[na][1];
            rs1 += s[na][2] + s[na][3];
        }
        uint32_t pf[4][4];
#pragma unroll
        for (int kc = 0; kc < 4; kc++) {
            pf[kc][0] = packbf(s[2 * kc][0],     s[2 * kc][1]);
            pf[kc][1] = packbf(s[2 * kc][2],     s[2 * kc][3]);
            pf[kc][2] = packbf(s[2 * kc + 1][0], s[2 * kc + 1][1]);
            pf[kc][3] = packbf(s[2 * kc + 1][2], s[2 * kc + 1][3]);
        }
#pragma unroll
        for (int x = 1; x <= 2; x <<= 1) {
            rs0 += __shfl_xor_sync(0xffffffffu, rs0, x);
            rs1 += __shfl_xor_sync(0xffffffffu, rs1, x);
        }
        l0 = l0 * al0 + rs0;
        l1 = l1 * al1 + rs1;
#pragma unroll
        for (int nh = 0; nh < 8; nh++) {
            o[nh][0] *= al0; o[nh][1] *= al0;
            o[nh][2] *= al1; o[nh][3] *= al1;
        }

        // ---- O += P V  (V B-fragments via ldmatrix.x4.trans) ----
#pragma unroll
        for (int kc = 0; kc < 4; kc++) {
#pragma unroll
            for (int nh = 0; nh < 8; nh += 2) {
                uint32_t addr = vs_base +
                    (uint32_t)((16 * kc + v_rowpart) * 144 + (nh * 8 + v_colpart) * 2);
                uint32_t b0, b1, b2, b3;
                asm volatile(
                    "ldmatrix.sync.aligned.m8n8.x4.trans.shared.b16 {%0,%1,%2,%3}, [%4];"
                    : "=r"(b0), "=r"(b1), "=r"(b2), "=r"(b3) : "r"(addr));
                mma16816(o[nh],     pf[kc], b0, b1);
                mma16816(o[nh + 1], pf[kc], b2, b3);
            }
        }
    }

    // ---- write normalized output ----
    const float i0 = 1.0f / l0, i1 = 1.0f / l1;
    const int row0 = q0 + w * 16 + g;
    const int row1 = row0 + 8;
#pragma unroll
    for (int nh = 0; nh < 8; nh++) {
        const int col = h * 64 + nh * 8 + tg * 2;
        *(uint32_t*)(out + ((size_t)(b * N_ + row0)) * INT_ + col) =
            packbf(o[nh][0] * i0, o[nh][1] * i0);
        *(uint32_t*)(out + ((size_t)(b * N_ + row1)) * INT_ + col) =
            packbf(o[nh][2] * i1, o[nh][3] * i1);
    }
}

// ==================== host ====================
static inline void conv(const float* in, bf16* out, int n) {
    f2bf_kernel<<<(n / 4 + 255) / 256, 256>>>(in, out, n);
}

extern "C" void kernel_launch(void* const* d_in, const int* in_sizes, int n_in,
                              void* d_out, int out_size)
{
    (void)in_sizes; (void)n_in; (void)out_size;
    const float* x   = (const float*)d_in[0];
    const float* dw  = (const float*)d_in[1];
    const float* db  = (const float*)d_in[2];
    const float* nds = (const float*)d_in[3];
    const float* ndb = (const float*)d_in[4];
    const float* qw  = (const float*)d_in[5];
    const float* pw  = (const float*)d_in[6];
    const float* pb  = (const float*)d_in[7];
    const float* nms = (const float*)d_in[8];
    const float* nmb = (const float*)d_in[9];
    const float* m1w = (const float*)d_in[10];
    const float* m1b = (const float*)d_in[11];
    const float* m2w = (const float*)d_in[12];
    const float* m2b = (const float*)d_in[13];
    const float* uw  = (const float*)d_in[14];
    const float* ub  = (const float*)d_in[15];
    const float* gm  = (const float*)d_in[16];

    float *X, *Hb, *QKV;
    bf16 *qkvbf, *xbf, *hnbf, *attbf, *g1bf, *hbf;
    bf16 *wd, *wq, *wp, *w1, *w2, *wu;
    cudaGetSymbolAddress((void**)&X,     g_X);
    cudaGetSymbolAddress((void**)&Hb,    g_H);
    cudaGetSymbolAddress((void**)&QKV,   g_QKV);
    cudaGetSymbolAddress((void**)&qkvbf, g_qkvbf);
    cudaGetSymbolAddress((void**)&xbf,   g_xbf);
    cudaGetSymbolAddress((void**)&hnbf,  g_hnbf);
    cudaGetSymbolAddress((void**)&attbf, g_attbf);
    cudaGetSymbolAddress((void**)&g1bf,  g_g1bf);
    cudaGetSymbolAddress((void**)&hbf,   g_hbf);
    cudaGetSymbolAddress((void**)&wd,    g_wdown);
    cudaGetSymbolAddress((void**)&wq,    g_wqkv);
    cudaGetSymbolAddress((void**)&wp,    g_wproj);
    cudaGetSymbolAddress((void**)&w1,    g_wm1);
    cudaGetSymbolAddress((void**)&w2,    g_wm2);
    cudaGetSymbolAddress((void**)&wu,    g_wup);

    // weight + input conversions (every call; deterministic)
    conv(x,   xbf, M_ * D_);
    conv(dw,  wd,  L_ * INT_ * D_);
    conv(qw,  wq,  L_ * 3 * INT_ * INT_);
    conv(pw,  wp,  L_ * INT_ * INT_);
    conv(m1w, w1,  L_ * HID_ * INT_);
    conv(m2w, w2,  L_ * INT_ * HID_);
    conv(uw,  wu,  L_ * D_ * INT_);

    const dim3 thr(256);
    for (int l = 0; l < L_; l++) {
        const float* xin = (l == 0) ? x : X;
        float* xout = (l == L_ - 1) ? (float*)d_out : X;
        bf16* xbf_out = (l == L_ - 1) ? nullptr : xbf;

        // h = x @ down_w^T + down_b
        gemm_mma<0><<<dim3(INT_ / 128, M_ / 128), thr>>>(
            xbf, wd + (size_t)l * INT_ * D_, db + (size_t)l * INT_,
            nullptr, nullptr, Hb, nullptr, D_, INT_);
        // hn = LN(h) -> bf16
        ln_kernel<<<(M_ * 32) / 256, thr>>>(Hb, nds + (size_t)l * INT_,
                                            ndb + (size_t)l * INT_, hnbf);
        // qkv = hn @ qkv_w^T
        gemm_mma<0><<<dim3(3 * INT_ / 128, M_ / 128), thr>>>(
            hnbf, wq + (size_t)l * 3 * INT_ * INT_, nullptr,
            nullptr, nullptr, QKV, nullptr, INT_, 3 * INT_);
        // rope + logn + scale -> bf16 qkv
        rope_kernel<<<(B_ * N_ * H_ * 32) / 256, thr>>>(QKV, qkvbf);
        // attention -> bf16
        attn_mma<<<dim3(N_ / 64, B_ * H_), 128>>>(qkvbf, attbf);
        // h = res + (o @ proj_w^T + proj_b)
        gemm_mma<2><<<dim3(INT_ / 128, M_ / 128), thr>>>(
            attbf, wp + (size_t)l * INT_ * INT_, pb + (size_t)l * INT_,
            Hb, nullptr, Hb, nullptr, INT_, INT_);
        // m = LN(h) -> bf16
        ln_kernel<<<(M_ * 32) / 256, thr>>>(Hb, nms + (size_t)l * INT_,
                                            nmb + (size_t)l * INT_, hnbf);
        // g1 = gelu(m @ m1^T + b1) -> bf16 only
        gemm_mma<1><<<dim3(HID_ / 128, M_ / 128), thr>>>(
            hnbf, w1 + (size_t)l * HID_ * INT_, m1b + (size_t)l * HID_,
            nullptr, nullptr, nullptr, g1bf, INT_, HID_);
        // h = h + (g1 @ m2^T + b2) -> fp32 Hb + bf16 hbf
        gemm_mma<2><<<dim3(INT_ / 128, M_ / 128), thr>>>(
            g1bf, w2 + (size_t)l * INT_ * HID_, m2b + (size_t)l * INT_,
            Hb, nullptr, Hb, hbf, HID_, INT_);
        // x = shortcut + gamma * (h @ up^T + ub)
        gemm_mma<3><<<dim3(D_ / 128, M_ / 128), thr>>>(
            hbf, wu + (size_t)l * D_ * INT_, ub + (size_t)l * D_,
            xin, gm + (size_t)l * D_, xout, xbf_out, INT_, D_);
    }
}

// round 5
// speedup vs baseline: 4.8314x; 1.3105x over previous
#include <cuda_runtime.h>
#include <cuda_bf16.h>
#include <math.h>
#include <stdint.h>

#define B_   2
#define N_   2048
#define D_   1024
#define INT_ 256
#define H_   4
#define HD_  64
#define HID_ 512
#define L_   6
#define M_   (B_*N_)   // 4096 rows

typedef __nv_bfloat16 bf16;

// ==================== scratch ====================
__device__ float g_X  [M_ * D_];
__device__ float g_H  [M_ * INT_];
__device__ float g_QKV[M_ * 3 * INT_];
__device__ bf16  g_qkvbf[M_ * 3 * INT_];
__device__ bf16  g_xbf [M_ * D_];
__device__ bf16  g_hnbf[M_ * INT_];
__device__ bf16  g_attbf[M_ * INT_];
__device__ bf16  g_g1bf[M_ * HID_];
__device__ bf16  g_hbf [M_ * INT_];
__device__ float g_Opart[4 * 8 * N_ * 64];   // [chunk][bh][row][64]
__device__ float g_ml   [4 * 8 * N_ * 2];    // [chunk][bh][row][{m,l}]
// bf16 weights
__device__ bf16 g_wdown[L_ * INT_ * D_];
__device__ bf16 g_wqkv [L_ * 3 * INT_ * INT_];
__device__ bf16 g_wproj[L_ * INT_ * INT_];
__device__ bf16 g_wm1  [L_ * HID_ * INT_];
__device__ bf16 g_wm2  [L_ * INT_ * HID_];
__device__ bf16 g_wup  [L_ * D_ * INT_];

// ==================== helpers ====================
__device__ __forceinline__ uint32_t packbf(float a, float b) {
    __nv_bfloat162 t = __floats2bfloat162_rn(a, b);
    return *reinterpret_cast<uint32_t*>(&t);
}
__device__ __forceinline__ void mma16816(float* d, const uint32_t* a, uint32_t b0, uint32_t b1) {
    asm volatile(
        "mma.sync.aligned.m16n8k16.row.col.f32.bf16.bf16.f32 "
        "{%0,%1,%2,%3}, {%4,%5,%6,%7}, {%8,%9}, {%0,%1,%2,%3};"
        : "+f"(d[0]), "+f"(d[1]), "+f"(d[2]), "+f"(d[3])
        : "r"(a[0]), "r"(a[1]), "r"(a[2]), "r"(a[3]), "r"(b0), "r"(b1));
}
__device__ __forceinline__ uint32_t smem_u32(const void* p) {
    uint32_t a;
    asm("{ .reg .u64 t; cvta.to.shared.u64 t, %1; cvt.u32.u64 %0, t; }" : "=r"(a) : "l"(p));
    return a;
}
__device__ __forceinline__ void cp16(uint32_t dst, const void* src) {
    asm volatile("cp.async.cg.shared.global [%0], [%1], 16;" :: "r"(dst), "l"(src));
}
#define CP_COMMIT() asm volatile("cp.async.commit_group;")
#define CP_WAIT(n)  asm volatile("cp.async.wait_group %0;" :: "n"(n))

// ==================== fp32 -> bf16 convert ====================
__global__ __launch_bounds__(256) void f2bf_kernel(const float* __restrict__ in,
                                                   bf16* __restrict__ out, int n)
{
    int i = (blockIdx.x * 256 + threadIdx.x) * 4;
    if (i >= n) return;
    float4 v = *(const float4*)(in + i);
    uint2 u = make_uint2(packbf(v.x, v.y), packbf(v.z, v.w));
    *reinterpret_cast<uint2*>(out + i) = u;
}

// ==================== cp.async double-buffered mma GEMM ====================
// C[M,N] = A[M,K] @ W[N,K]^T. Tile BM x BN, warp tile WM x 32, K chunk 64.
// EPI: 0 = +bias -> fp32 C ; 1 = gelu(+bias) -> bf16 Cbf only ;
//      2 = res + (+bias) -> fp32 C (+ optional bf16 Cbf) ;
//      3 = res + gamma*(+bias) -> fp32 C (+ optional bf16 Cbf)
__device__ __forceinline__ float gelu_f(float x) {
    return 0.5f * x * (1.0f + erff(x * 0.70710678118654752440f));
}

template<int EPI, int BM, int BN, int WM>
__global__ __launch_bounds__((BM/WM)*(BN/32)*32) void gemm_cp(
    const bf16* __restrict__ A, const bf16* __restrict__ W,
    const float* __restrict__ bias, const float* __restrict__ res,
    const float* __restrict__ gamma, float* __restrict__ C,
    bf16* __restrict__ Cbf, int K, int N)
{
    constexpr int WARPS_M = BM / WM;
    constexpr int THREADS = WARPS_M * (BN / 32) * 32;
    constexpr int MA = WM / 16;
    constexpr int ALOOP = BM * 8 / THREADS;
    constexpr int BLOOP = BN * 8 / THREADS;

    extern __shared__ bf16 sm[];
    bf16* As = sm;                    // [2][BM][72]
    bf16* Bs = sm + 2 * BM * 72;      // [2][BN][72]
    const uint32_t sA = smem_u32(As);
    const uint32_t sB = smem_u32(Bs);

    const int tid  = threadIdx.x;
    const int lane = tid & 31;
    const int wid  = tid >> 5;
    const int g  = lane >> 2;
    const int tg = lane & 3;
    const int wm = wid % WARPS_M;
    const int wn = wid / WARPS_M;
    const int bm = blockIdx.y * BM;
    const int bn = blockIdx.x * BN;

    float acc[MA][4][4];
#pragma unroll
    for (int ma = 0; ma < MA; ma++)
#pragma unroll
        for (int na = 0; na < 4; na++)
#pragma unroll
            for (int r = 0; r < 4; r++) acc[ma][na][r] = 0.f;

    const bf16* Ab = A + (size_t)bm * K;
    const bf16* Wb = W + (size_t)bn * K;
    const int CH = K >> 6;

    auto issue = [&](int c) {
        const int p = c & 1;
        const int kof = c * 64;
#pragma unroll
        for (int i = 0; i < ALOOP; i++) {
            int v = tid + i * THREADS;
            int r = v >> 3, s = v & 7;
            cp16(sA + (uint32_t)((p * BM + r) * 72 + s * 8) * 2,
                 Ab + (size_t)r * K + kof + s * 8);
        }
#pragma unroll
        for (int i = 0; i < BLOOP; i++) {
            int v = tid + i * THREADS;
            int r = v >> 3, s = v & 7;
            cp16(sB + (uint32_t)((p * BN + r) * 72 + s * 8) * 2,
                 Wb + (size_t)r * K + kof + s * 8);
        }
        CP_COMMIT();
    };

    issue(0);
    for (int c = 0; c < CH; c++) {
        const int p = c & 1;
        if (c + 1 < CH) { issue(c + 1); CP_WAIT(1); }
        else           { CP_WAIT(0); }
        __syncthreads();

        const bf16* Ap = As + p * BM * 72;
        const bf16* Bp = Bs + p * BN * 72;
#pragma unroll
        for (int kc = 0; kc < 4; kc++) {
            uint32_t bfr[4][2];
#pragma unroll
            for (int na = 0; na < 4; na++) {
                const int rb = wn * 32 + na * 8 + g;
                bfr[na][0] = *(const uint32_t*)&Bp[rb * 72 + kc * 16 + tg * 2];
                bfr[na][1] = *(const uint32_t*)&Bp[rb * 72 + kc * 16 + 8 + tg * 2];
            }
#pragma unroll
            for (int ma = 0; ma < MA; ma++) {
                const int r0 = wm * WM + ma * 16 + g;
                uint32_t af[4];
                af[0] = *(const uint32_t*)&Ap[r0 * 72 + kc * 16 + tg * 2];
                af[1] = *(const uint32_t*)&Ap[(r0 + 8) * 72 + kc * 16 + tg * 2];
                af[2] = *(const uint32_t*)&Ap[r0 * 72 + kc * 16 + 8 + tg * 2];
                af[3] = *(const uint32_t*)&Ap[(r0 + 8) * 72 + kc * 16 + 8 + tg * 2];
#pragma unroll
                for (int na = 0; na < 4; na++)
                    mma16816(acc[ma][na], af, bfr[na][0], bfr[na][1]);
            }
        }
        __syncthreads();
    }

    // ---------------- epilogue ----------------
#pragma unroll
    for (int ma = 0; ma < MA; ma++) {
        const int row0 = bm + wm * WM + ma * 16 + g;
        const int row1 = row0 + 8;
#pragma unroll
        for (int na = 0; na < 4; na++) {
            const int col = bn + wn * 32 + na * 8 + tg * 2;
            float bx = 0.f, by = 0.f;
            if (bias) {
                float2 b2 = *(const float2*)(bias + col);
                bx = b2.x; by = b2.y;
            }
            float v00 = acc[ma][na][0] + bx, v01 = acc[ma][na][1] + by;
            float v10 = acc[ma][na][2] + bx, v11 = acc[ma][na][3] + by;
            const size_t o0 = (size_t)row0 * N + col;
            const size_t o1 = (size_t)row1 * N + col;
            if (EPI == 1) {
                v00 = gelu_f(v00); v01 = gelu_f(v01);
                v10 = gelu_f(v10); v11 = gelu_f(v11);
            } else if (EPI == 2) {
                float2 r0 = *(const float2*)(res + o0);
                float2 r1 = *(const float2*)(res + o1);
                v00 += r0.x; v01 += r0.y; v10 += r1.x; v11 += r1.y;
            } else if (EPI == 3) {
                float2 r0 = *(const float2*)(res + o0);
                float2 r1 = *(const float2*)(res + o1);
                float2 g2 = *(const float2*)(gamma + col);
                v00 = r0.x + g2.x * v00; v01 = r0.y + g2.y * v01;
                v10 = r1.x + g2.x * v10; v11 = r1.y + g2.y * v11;
            }
            if (EPI != 1) {
                *(float2*)(C + o0) = make_float2(v00, v01);
                *(float2*)(C + o1) = make_float2(v10, v11);
            }
            if (EPI == 1 || Cbf != nullptr) {
                *(uint32_t*)(Cbf + o0) = packbf(v00, v01);
                *(uint32_t*)(Cbf + o1) = packbf(v10, v11);
            }
        }
    }
}

// ==================== LayerNorm (rows of 256) -> bf16 ====================
__global__ __launch_bounds__(256) void ln_kernel(
    const float* __restrict__ in, const float* __restrict__ s,
    const float* __restrict__ b, bf16* __restrict__ out)
{
    int gw   = (blockIdx.x * blockDim.x + threadIdx.x) >> 5;
    int lane = threadIdx.x & 31;
    if (gw >= M_) return;
    const float* x = in + (size_t)gw * INT_;
    float v[8], sum = 0.f, sq = 0.f;
#pragma unroll
    for (int i = 0; i < 8; i++) {
        v[i] = x[lane + 32 * i];
        sum += v[i]; sq += v[i] * v[i];
    }
#pragma unroll
    for (int o = 16; o > 0; o >>= 1) {
        sum += __shfl_xor_sync(0xffffffffu, sum, o);
        sq  += __shfl_xor_sync(0xffffffffu, sq,  o);
    }
    float mean = sum * (1.f / 256.f);
    float var  = sq * (1.f / 256.f) - mean * mean;
    float rstd = rsqrtf(var + 1e-5f);
    bf16* y = out + (size_t)gw * INT_;
#pragma unroll
    for (int i = 0; i < 8; i++) {
        int d = lane + 32 * i;
        y[d] = __float2bfloat16((v[i] - mean) * rstd * s[d] + b[d]);
    }
}

// ==================== RoPE + logn + 1/sqrt(hd) fold -> bf16 qkv ====================
__global__ __launch_bounds__(256) void rope_kernel(const float* __restrict__ qkv,
                                                   bf16* __restrict__ qbf)
{
    int idx = blockIdx.x * blockDim.x + threadIdx.x;   // B*N*H*32
    int d = idx & 31;
    int h = (idx >> 5) & (H_ - 1);
    int n = (idx >> 7) & (N_ - 1);
    int b = idx >> 18;

    float inv = expf(-(float)d * (logf(10000.0f) * (1.0f / 32.0f)));
    float ph  = (float)n * inv;
    float sn, cs;
    sincosf(ph, &sn, &cs);
    float lns = fmaxf(1.0f, logf((float)(n + 1)) * (1.0f / logf(64.0f)));
    lns *= 0.125f;   // fold softmax scale 1/sqrt(64) into q

    size_t base = ((size_t)(b * N_ + n)) * 768 + h * 64 + d;
    float q0 = qkv[base], q1 = qkv[base + 32];
    qbf[base]       = __float2bfloat16((q0 * cs - q1 * sn) * lns);
    qbf[base + 32]  = __float2bfloat16((q1 * cs + q0 * sn) * lns);
    float k0 = qkv[base + 256], k1 = qkv[base + 288];
    qbf[base + 256] = __float2bfloat16(k0 * cs - k1 * sn);
    qbf[base + 288] = __float2bfloat16(k1 * cs + k0 * sn);
    qbf[base + 512] = __float2bfloat16(qkv[base + 512]);
    qbf[base + 544] = __float2bfloat16(qkv[base + 544]);
}

// ==================== Flash attention, split-KV, cp.async pipelined ====================
// grid (N/64, B*H, 4 chunks), block 128 (4 warps). Each chunk covers 512 keys.
#define KT_PER_CHUNK 8

__global__ __launch_bounds__(128) void attn_part(const bf16* __restrict__ qkv,
                                                 float* __restrict__ Opart,
                                                 float* __restrict__ ml)
{
    __shared__ __align__(16) bf16 Qs[64][72];
    __shared__ __align__(16) bf16 Ks[2][64][72];
    __shared__ __align__(16) bf16 Vs[2][64][72];

    const int tid  = threadIdx.x;
    const int lane = tid & 31;
    const int w    = tid >> 5;
    const int g  = lane >> 2;
    const int tg = lane & 3;
    const int bh = blockIdx.y;
    const int b = bh >> 2, h = bh & 3;
    const int q0 = blockIdx.x * 64;
    const int ck = blockIdx.z;
    const bf16* base = qkv + (size_t)b * N_ * 768 + h * 64;
    const uint32_t ks_base = smem_u32(&Ks[0][0][0]);
    const uint32_t vs_base = smem_u32(&Vs[0][0][0]);

    auto issueKV = [&](int kt) {
        const int p = kt & 1;
        const bf16* kb = base + (size_t)((ck * KT_PER_CHUNK + kt) * 64) * 768 + 256;
#pragma unroll
        for (int i = 0; i < 4; i++) {
            int v = tid + i * 128;
            int r = v >> 3, s = v & 7;
            cp16(ks_base + (uint32_t)((p * 64 + r) * 72 + s * 8) * 2, kb + (size_t)r * 768 + s * 8);
            cp16(vs_base + (uint32_t)((p * 64 + r) * 72 + s * 8) * 2, kb + (size_t)r * 768 + 256 + s * 8);
        }
        CP_COMMIT();
    };

    issueKV(0);

    // load Q tile (sync loads)
#pragma unroll
    for (int i = 0; i < 4; i++) {
        int v = tid + i * 128;
        int r = v >> 3, s = v & 7;
        *(uint4*)&Qs[r][s * 8] = *(const uint4*)(base + (size_t)(q0 + r) * 768 + s * 8);
    }
    __syncthreads();

    // hoist Q fragments (row block = w*16)
    uint32_t qf[4][4];
    {
        const int r0 = w * 16 + g;
#pragma unroll
        for (int kc = 0; kc < 4; kc++) {
            qf[kc][0] = *(const uint32_t*)&Qs[r0    ][kc * 16 + tg * 2];
            qf[kc][1] = *(const uint32_t*)&Qs[r0 + 8][kc * 16 + tg * 2];
            qf[kc][2] = *(const uint32_t*)&Qs[r0    ][kc * 16 + 8 + tg * 2];
            qf[kc][3] = *(const uint32_t*)&Qs[r0 + 8][kc * 16 + 8 + tg * 2];
        }
    }

    const int q4 = lane >> 3;
    const int v_rowpart = (lane & 7) + 8 * (q4 & 1);
    const int v_colpart = 8 * (q4 >> 1);

    float m0 = -INFINITY, m1 = -INFINITY, l0 = 0.f, l1 = 0.f;
    float o[8][4];
#pragma unroll
    for (int nh = 0; nh < 8; nh++)
#pragma unroll
        for (int r = 0; r < 4; r++) o[nh][r] = 0.f;

    for (int kt = 0; kt < KT_PER_CHUNK; kt++) {
        const int p = kt & 1;
        if (kt + 1 < KT_PER_CHUNK) { issueKV(kt + 1); CP_WAIT(1); }
        else                       { CP_WAIT(0); }
        __syncthreads();

        // ---- S = Q K^T ----
        float s[8][4];
#pragma unroll
        for (int na = 0; na < 8; na++)
#pragma unroll
            for (int r = 0; r < 4; r++) s[na][r] = 0.f;
#pragma unroll
        for (int kc = 0; kc < 4; kc++) {
#pragma unroll
            for (int na = 0; na < 8; na++) {
                const int rb = na * 8 + g;
                uint32_t b0 = *(const uint32_t*)&Ks[p][rb][kc * 16 + tg * 2];
                uint32_t b1 = *(const uint32_t*)&Ks[p][rb][kc * 16 + 8 + tg * 2];
                mma16816(s[na], qf[kc], b0, b1);
            }
        }

        // ---- online softmax ----
        float mt0 = -INFINITY, mt1 = -INFINITY;
#pragma unroll
        for (int na = 0; na < 8; na++) {
            mt0 = fmaxf(mt0, fmaxf(s[na][0], s[na][1]));
            mt1 = fmaxf(mt1, fmaxf(s[na][2], s[na][3]));
        }
#pragma unroll
        for (int x = 1; x <= 2; x <<= 1) {
            mt0 = fmaxf(mt0, __shfl_xor_sync(0xffffffffu, mt0, x));
            mt1 = fmaxf(mt1, __shfl_xor_sync(0xffffffffu, mt1, x));
        }
        float mn0 = fmaxf(m0, mt0), mn1 = fmaxf(m1, mt1);
        float al0 = __expf(m0 - mn0), al1 = __expf(m1 - mn1);
        m0 = mn0; m1 = mn1;

        float rs0 = 0.f, rs1 = 0.f;
#pragma unroll
        for (int na = 0; na < 8; na++) {
            s[na][0] = __expf(s[na][0] - mn0);
            s[na][1] = __expf(s[na][1] - mn0);
            s[na][2] = __expf(s[na][2] - mn1);
            s[na][3] = __expf(s[na][3] - mn1);
            rs0 += s[na][0] + s[na][1];
            rs1 += s[na][2] + s[na][3];
        }
        uint32_t pf[4][4];
#pragma unroll
        for (int kc = 0; kc < 4; kc++) {
            pf[kc][0] = packbf(s[2 * kc][0],     s[2 * kc][1]);
            pf[kc][1] = packbf(s[2 * kc][2],     s[2 * kc][3]);
            pf[kc][2] = packbf(s[2 * kc + 1][0], s[2 * kc + 1][1]);
            pf[kc][3] = packbf(s[2 * kc + 1][2], s[2 * kc + 1][3]);
        }
#pragma unroll
        for (int x = 1; x <= 2; x <<= 1) {
            rs0 += __shfl_xor_sync(0xffffffffu, rs0, x);
            rs1 += __shfl_xor_sync(0xffffffffu, rs1, x);
        }
        l0 = l0 * al0 + rs0;
        l1 = l1 * al1 + rs1;
#pragma unroll
        for (int nh = 0; nh < 8; nh++) {
            o[nh][0] *= al0; o[nh][1] *= al0;
            o[nh][2] *= al1; o[nh][3] *= al1;
        }

        // ---- O += P V ----
        const uint32_t vpb = vs_base + (uint32_t)(p * 64 * 72) * 2;
#pragma unroll
        for (int kc = 0; kc < 4; kc++) {
#pragma unroll
            for (int nh = 0; nh < 8; nh += 2) {
                uint32_t addr = vpb +
                    (uint32_t)((16 * kc + v_rowpart) * 144 + (nh * 8 + v_colpart) * 2);
                uint32_t b0, b1, b2, b3;
                asm volatile(
                    "ldmatrix.sync.aligned.m8n8.x4.trans.shared.b16 {%0,%1,%2,%3}, [%4];"
                    : "=r"(b0), "=r"(b1), "=r"(b2), "=r"(b3) : "r"(addr));
                mma16816(o[nh],     pf[kc], b0, b1);
                mma16816(o[nh + 1], pf[kc], b2, b3);
            }
        }
        __syncthreads();
    }

    // ---- write partial O (unnormalized) + m,l ----
    const int r0l = w * 16 + g;
    float* Obase = Opart + ((size_t)(ck * 8 + bh) * N_ + q0) * 64;
#pragma unroll
    for (int nh = 0; nh < 8; nh++) {
        const int col = nh * 8 + tg * 2;
        *(float2*)(Obase + (size_t)r0l * 64 + col)       = make_float2(o[nh][0], o[nh][1]);
        *(float2*)(Obase + (size_t)(r0l + 8) * 64 + col) = make_float2(o[nh][2], o[nh][3]);
    }
    if (tg == 0) {
        size_t mi0 = ((size_t)(ck * 8 + bh) * N_ + q0 + r0l) * 2;
        size_t mi1 = ((size_t)(ck * 8 + bh) * N_ + q0 + r0l + 8) * 2;
        ml[mi0] = m0; ml[mi0 + 1] = l0;
        ml[mi1] = m1; ml[mi1 + 1] = l1;
    }
}

// ==================== attention combine ====================
__global__ __launch_bounds__(256) void attn_combine(const float* __restrict__ Opart,
                                                    const float* __restrict__ ml,
                                                    bf16* __restrict__ out)
{
    int gw   = blockIdx.x * 8 + (threadIdx.x >> 5);   // 0..16383
    int lane = threadIdx.x & 31;
    int bh  = gw >> 11;
    int row = gw & 2047;
    int b = bh >> 2, h = bh & 3;

    float m[4], l[4];
#pragma unroll
    for (int c = 0; c < 4; c++) {
        size_t idx = ((size_t)(c * 8 + bh) * N_ + row) * 2;
        m[c] = ml[idx]; l[c] = ml[idx + 1];
    }
    float ms = fmaxf(fmaxf(m[0], m[1]), fmaxf(m[2], m[3]));
    float wsum = 0.f, a0 = 0.f, a1 = 0.f;
#pragma unroll
    for (int c = 0; c < 4; c++) {
        float wc = __expf(m[c] - ms);
        wsum += wc * l[c];
        float2 v = *(const float2*)(Opart + ((size_t)(c * 8 + bh) * N_ + row) * 64 + lane * 2);
        a0 += wc * v.x; a1 += wc * v.y;
    }
    float inv = 1.f / wsum;
    *(uint32_t*)(out + ((size_t)(b * N_ + row)) * INT_ + h * 64 + lane * 2) =
        packbf(a0 * inv, a1 * inv);
}

// ==================== host ====================
static inline void conv(const float* in, bf16* out, int n) {
    f2bf_kernel<<<(n / 4 + 255) / 256, 256>>>(in, out, n);
}

extern "C" void kernel_launch(void* const* d_in, const int* in_sizes, int n_in,
                              void* d_out, int out_size)
{
    (void)in_sizes; (void)n_in; (void)out_size;
    const float* x   = (const float*)d_in[0];
    const float* dw  = (const float*)d_in[1];
    const float* db  = (const float*)d_in[2];
    const float* nds = (const float*)d_in[3];
    const float* ndb = (const float*)d_in[4];
    const float* qw  = (const float*)d_in[5];
    const float* pw  = (const float*)d_in[6];
    const float* pb  = (const float*)d_in[7];
    const float* nms = (const float*)d_in[8];
    const float* nmb = (const float*)d_in[9];
    const float* m1w = (const float*)d_in[10];
    const float* m1b = (const float*)d_in[11];
    const float* m2w = (const float*)d_in[12];
    const float* m2b = (const float*)d_in[13];
    const float* uw  = (const float*)d_in[14];
    const float* ub  = (const float*)d_in[15];
    const float* gm  = (const float*)d_in[16];

    float *X, *Hb, *QKV, *Opart, *mlp;
    bf16 *qkvbf, *xbf, *hnbf, *attbf, *g1bf, *hbf;
    bf16 *wd, *wq, *wp, *w1, *w2, *wu;
    cudaGetSymbolAddress((void**)&X,     g_X);
    cudaGetSymbolAddress((void**)&Hb,    g_H);
    cudaGetSymbolAddress((void**)&QKV,   g_QKV);
    cudaGetSymbolAddress((void**)&Opart, g_Opart);
    cudaGetSymbolAddress((void**)&mlp,   g_ml);
    cudaGetSymbolAddress((void**)&qkvbf, g_qkvbf);
    cudaGetSymbolAddress((void**)&xbf,   g_xbf);
    cudaGetSymbolAddress((void**)&hnbf,  g_hnbf);
    cudaGetSymbolAddress((void**)&attbf, g_attbf);
    cudaGetSymbolAddress((void**)&g1bf,  g_g1bf);
    cudaGetSymbolAddress((void**)&hbf,   g_hbf);
    cudaGetSymbolAddress((void**)&wd,    g_wdown);
    cudaGetSymbolAddress((void**)&wq,    g_wqkv);
    cudaGetSymbolAddress((void**)&wp,    g_wproj);
    cudaGetSymbolAddress((void**)&w1,    g_wm1);
    cudaGetSymbolAddress((void**)&w2,    g_wm2);
    cudaGetSymbolAddress((void**)&wu,    g_wup);

    // dynamic smem sizes: 2*(BM+BN)*72*2 bytes
    const int SM_6464   = 2 * (64 + 64)  * 72 * 2;   // 36864
    const int SM_12864  = 2 * (128 + 64) * 72 * 2;   // 55296
    const int SM_128128 = 2 * (128 + 128)* 72 * 2;   // 73728
    cudaFuncSetAttribute(gemm_cp<0,64,64,32>,   cudaFuncAttributeMaxDynamicSharedMemorySize, SM_6464);
    cudaFuncSetAttribute(gemm_cp<2,64,64,32>,   cudaFuncAttributeMaxDynamicSharedMemorySize, SM_6464);
    cudaFuncSetAttribute(gemm_cp<1,128,64,32>,  cudaFuncAttributeMaxDynamicSharedMemorySize, SM_12864);
    cudaFuncSetAttribute(gemm_cp<0,128,128,64>, cudaFuncAttributeMaxDynamicSharedMemorySize, SM_128128);
    cudaFuncSetAttribute(gemm_cp<3,128,128,64>, cudaFuncAttributeMaxDynamicSharedMemorySize, SM_128128);

    // weight + input conversions (every call; deterministic)
    conv(x,   xbf, M_ * D_);
    conv(dw,  wd,  L_ * INT_ * D_);
    conv(qw,  wq,  L_ * 3 * INT_ * INT_);
    conv(pw,  wp,  L_ * INT_ * INT_);
    conv(m1w, w1,  L_ * HID_ * INT_);
    conv(m2w, w2,  L_ * INT_ * HID_);
    conv(uw,  wu,  L_ * D_ * INT_);

    for (int l = 0; l < L_; l++) {
        const float* xin = (l == 0) ? x : X;
        float* xout = (l == L_ - 1) ? (float*)d_out : X;
        bf16* xbf_out = (l == L_ - 1) ? nullptr : xbf;

        // h = x @ down_w^T + down_b   [4096x256, K=1024] -> 256 CTAs
        gemm_cp<0,64,64,32><<<dim3(INT_ / 64, M_ / 64), 128, SM_6464>>>(
            xbf, wd + (size_t)l * INT_ * D_, db + (size_t)l * INT_,
            nullptr, nullptr, Hb, nullptr, D_, INT_);
        // hn = LN(h) -> bf16
        ln_kernel<<<(M_ * 32) / 256, 256>>>(Hb, nds + (size_t)l * INT_,
                                            ndb + (size_t)l * INT_, hnbf);
        // qkv = hn @ qkv_w^T   [4096x768, K=256] -> 192 CTAs
        gemm_cp<0,128,128,64><<<dim3(3 * INT_ / 128, M_ / 128), 256, SM_128128>>>(
            hnbf, wq + (size_t)l * 3 * INT_ * INT_, nullptr,
            nullptr, nullptr, QKV, nullptr, INT_, 3 * INT_);
        // rope + logn + scale -> bf16 qkv
        rope_kernel<<<(B_ * N_ * H_ * 32) / 256, 256>>>(QKV, qkvbf);
        // attention: 4 KV chunks -> 1024 CTAs, then combine
        attn_part<<<dim3(N_ / 64, B_ * H_, 4), 128>>>(qkvbf, Opart, mlp);
        attn_combine<<<(8 * N_) / 8, 256>>>(Opart, mlp, attbf);
        // h = res + (o @ proj_w^T + proj_b)   [4096x256, K=256] -> 256 CTAs
        gemm_cp<2,64,64,32><<<dim3(INT_ / 64, M_ / 64), 128, SM_6464>>>(
            attbf, wp + (size_t)l * INT_ * INT_, pb + (size_t)l * INT_,
            Hb, nullptr, Hb, nullptr, INT_, INT_);
        // m = LN(h) -> bf16
        ln_kernel<<<(M_ * 32) / 256, 256>>>(Hb, nms + (size_t)l * INT_,
                                            nmb + (size_t)l * INT_, hnbf);
        // g1 = gelu(m @ m1^T + b1) -> bf16 only  [4096x512, K=256] -> 256 CTAs
        gemm_cp<1,128,64,32><<<dim3(HID_ / 64, M_ / 128), 256, SM_12864>>>(
            hnbf, w1 + (size_t)l * HID_ * INT_, m1b + (size_t)l * HID_,
            nullptr, nullptr, nullptr, g1bf, INT_, HID_);
        // h = h + (g1 @ m2^T + b2) -> fp32 Hb + bf16 hbf  [4096x256, K=512] -> 256 CTAs
        gemm_cp<2,64,64,32><<<dim3(INT_ / 64, M_ / 64), 128, SM_6464>>>(
            g1bf, w2 + (size_t)l * INT_ * HID_, m2b + (size_t)l * INT_,
            Hb, nullptr, Hb, hbf, HID_, INT_);
        // x = shortcut + gamma * (h @ up^T + ub)  [4096x1024, K=256] -> 256 CTAs
        gemm_cp<3,128,128,64><<<dim3(D_ / 128, M_ / 128), 256, SM_128128>>>(
            hbf, wu + (size_t)l * D_ * INT_, ub + (size_t)l * D_,
            xin, gm + (size_t)l * D_, xout, xbf_out, INT_, D_);
    }
}

// round 8
// speedup vs baseline: 5.0645x; 1.0482x over previous
#include <cuda_runtime.h>
#include <cuda_bf16.h>
#include <cuda_fp16.h>
#include <math.h>
#include <stdint.h>

#define B_   2
#define N_   2048
#define D_   1024
#define INT_ 256
#define H_   4
#define HD_  64
#define HID_ 512
#define L_   6
#define M_   (B_*N_)   // 4096 rows

typedef __nv_bfloat16 bf16;

// ==================== scratch ====================
__device__ float g_X  [M_ * D_];
__device__ float g_H  [M_ * INT_];
__device__ bf16  g_qkbf[M_ * 512];           // [row][ Qh0..Qh3 | Kh0..Kh3 ] (rope+scale applied)
__device__ __half g_vh [M_ * 256];           // [row][ Vh0..Vh3 ] fp16
__device__ bf16  g_xbf [M_ * D_];
__device__ bf16  g_hnbf[M_ * INT_];
__device__ bf16  g_attbf[M_ * INT_];
__device__ bf16  g_g1bf[M_ * HID_];
__device__ bf16  g_hbf [M_ * INT_];
__device__ float g_Opart[4 * 8 * N_ * 64];   // [chunk][bh][row][64]
__device__ float g_ml   [4 * 8 * N_ * 2];    // [chunk][bh][row][{m,l}]  (m in log2 domain)
// bf16 weights
__device__ bf16 g_wdown[L_ * INT_ * D_];
__device__ bf16 g_wqkv [L_ * 3 * INT_ * INT_];
__device__ bf16 g_wproj[L_ * INT_ * INT_];
__device__ bf16 g_wm1  [L_ * HID_ * INT_];
__device__ bf16 g_wm2  [L_ * INT_ * HID_];
__device__ bf16 g_wup  [L_ * D_ * INT_];

// ==================== helpers ====================
__device__ __forceinline__ uint32_t packbf(float a, float b) {
    __nv_bfloat162 t = __floats2bfloat162_rn(a, b);
    return *reinterpret_cast<uint32_t*>(&t);
}
__device__ __forceinline__ void mma16816(float* d, const uint32_t* a, uint32_t b0, uint32_t b1) {
    asm volatile(
        "mma.sync.aligned.m16n8k16.row.col.f32.bf16.bf16.f32 "
        "{%0,%1,%2,%3}, {%4,%5,%6,%7}, {%8,%9}, {%0,%1,%2,%3};"
        : "+f"(d[0]), "+f"(d[1]), "+f"(d[2]), "+f"(d[3])
        : "r"(a[0]), "r"(a[1]), "r"(a[2]), "r"(a[3]), "r"(b0), "r"(b1));
}
__device__ __forceinline__ void mma16816h(float* d, const uint32_t* a, uint32_t b0, uint32_t b1) {
    asm volatile(
        "mma.sync.aligned.m16n8k16.row.col.f32.f16.f16.f32 "
        "{%0,%1,%2,%3}, {%4,%5,%6,%7}, {%8,%9}, {%0,%1,%2,%3};"
        : "+f"(d[0]), "+f"(d[1]), "+f"(d[2]), "+f"(d[3])
        : "r"(a[0]), "r"(a[1]), "r"(a[2]), "r"(a[3]), "r"(b0), "r"(b1));
}
// two exp2's in one MUFU op; input floats, output packed f16x2
__device__ __forceinline__ uint32_t ex2_h2(float a, float b) {
    __half2 h = __floats2half2_rn(a, b);
    uint32_t u = *reinterpret_cast<uint32_t*>(&h);
    asm("ex2.approx.f16x2 %0, %0;" : "+r"(u));
    return u;
}
__device__ __forceinline__ uint32_t smem_u32(const void* p) {
    uint32_t a;
    asm("{ .reg .u64 t; cvta.to.shared.u64 t, %1; cvt.u32.u64 %0, t; }" : "=r"(a) : "l"(p));
    return a;
}
__device__ __forceinline__ void cp16(uint32_t dst, const void* src) {
    asm volatile("cp.async.cg.shared.global [%0], [%1], 16;" :: "r"(dst), "l"(src));
}
#define CP_COMMIT() asm volatile("cp.async.commit_group;")
#define CP_WAIT(n)  asm volatile("cp.async.wait_group %0;" :: "n"(n))

// ==================== batched fp32 -> bf16 convert (one launch) ====================
struct ConvArgs {
    const float* src[7];
    bf16* dst[7];
    unsigned end[7];    // prefix ends, float4 units
};
__global__ __launch_bounds__(256) void conv_all(ConvArgs a, unsigned total) {
    unsigned f4 = blockIdx.x * 256 + threadIdx.x;
    if (f4 >= total) return;
    int s = 0;
#pragma unroll
    for (int i = 0; i < 6; i++) if (f4 >= a.end[s]) s++;
    unsigned lo = f4 - (s ? a.end[s - 1] : 0);
    float4 v = ((const float4*)a.src[s])[lo];
    uint2 u = make_uint2(packbf(v.x, v.y), packbf(v.z, v.w));
    ((uint2*)a.dst[s])[lo] = u;
}

// ==================== cp.async double-buffered mma GEMM ====================
// C[M,N] = A[M,K] @ W[N,K]^T. Tile BM x BN, warp tile WM x 32, K chunk 64.
// EPI: 0 = +bias -> fp32 C ; 1 = gelu(+bias) -> bf16 Cbf only ;
//      2 = res + (+bias) -> fp32 C (+ optional bf16 Cbf) ;
//      3 = res + gamma*(+bias) -> fp32 C (+ optional bf16 Cbf) ;
//      5 = fused qkv rope epilogue -> bf16 Q/K (Cbf, stride 512), f16 V (Vh, stride 256)
__device__ __forceinline__ float gelu_f(float x) {
    return 0.5f * x * (1.0f + erff(x * 0.70710678118654752440f));
}

template<int EPI, int BM, int BN, int WM>
__global__ __launch_bounds__((BM/WM)*(BN/32)*32) void gemm_cp(
    const bf16* __restrict__ A, const bf16* __restrict__ W,
    const float* __restrict__ bias, const float* __restrict__ res,
    const float* __restrict__ gamma, float* __restrict__ C,
    bf16* __restrict__ Cbf, __half* __restrict__ Vh, int K, int N)
{
    constexpr int WARPS_M = BM / WM;
    constexpr int THREADS = WARPS_M * (BN / 32) * 32;
    constexpr int MA = WM / 16;
    constexpr int ALOOP = BM * 8 / THREADS;
    constexpr int BLOOP = BN * 8 / THREADS;

    extern __shared__ bf16 sm[];
    bf16* As = sm;                    // [2][BM][72]
    bf16* Bs = sm + 2 * BM * 72;      // [2][BN][72]
    const uint32_t sA = smem_u32(As);
    const uint32_t sB = smem_u32(Bs);

    const int tid  = threadIdx.x;
    const int lane = tid & 31;
    const int wid  = tid >> 5;
    const int g  = lane >> 2;
    const int tg = lane & 3;
    const int wm = wid % WARPS_M;
    const int wn = wid / WARPS_M;
    const int bm = blockIdx.y * BM;
    const int bn = blockIdx.x * BN;

    float acc[MA][4][4];
#pragma unroll
    for (int ma = 0; ma < MA; ma++)
#pragma unroll
        for (int na = 0; na < 4; na++)
#pragma unroll
            for (int r = 0; r < 4; r++) acc[ma][na][r] = 0.f;

    const bf16* Ab = A + (size_t)bm * K;
    const bf16* Wb = W + (size_t)bn * K;
    const int CH = K >> 6;

    auto issue = [&](int c) {
        const int p = c & 1;
        const int kof = c * 64;
#pragma unroll
        for (int i = 0; i < ALOOP; i++) {
            int v = tid + i * THREADS;
            int r = v >> 3, s = v & 7;
            cp16(sA + (uint32_t)((p * BM + r) * 72 + s * 8) * 2,
                 Ab + (size_t)r * K + kof + s * 8);
        }
#pragma unroll
        for (int i = 0; i < BLOOP; i++) {
            int v = tid + i * THREADS;
            int r = v >> 3, s = v & 7;
            cp16(sB + (uint32_t)((p * BN + r) * 72 + s * 8) * 2,
                 Wb + (size_t)r * K + kof + s * 8);
        }
        CP_COMMIT();
    };

    issue(0);
    for (int c = 0; c < CH; c++) {
        const int p = c & 1;
        if (c + 1 < CH) { issue(c + 1); CP_WAIT(1); }
        else           { CP_WAIT(0); }
        __syncthreads();

        const bf16* Ap = As + p * BM * 72;
        const bf16* Bp = Bs + p * BN * 72;
#pragma unroll
        for (int kc = 0; kc < 4; kc++) {
            uint32_t bfr[4][2];
#pragma unroll
            for (int na = 0; na < 4; na++) {
                const int rb = wn * 32 + na * 8 + g;
                bfr[na][0] = *(const uint32_t*)&Bp[rb * 72 + kc * 16 + tg * 2];
                bfr[na][1] = *(const uint32_t*)&Bp[rb * 72 + kc * 16 + 8 + tg * 2];
            }
#pragma unroll
            for (int ma = 0; ma < MA; ma++) {
                const int r0 = wm * WM + ma * 16 + g;
                uint32_t af[4];
                af[0] = *(const uint32_t*)&Ap[r0 * 72 + kc * 16 + tg * 2];
                af[1] = *(const uint32_t*)&Ap[(r0 + 8) * 72 + kc * 16 + tg * 2];
                af[2] = *(const uint32_t*)&Ap[r0 * 72 + kc * 16 + 8 + tg * 2];
                af[3] = *(const uint32_t*)&Ap[(r0 + 8) * 72 + kc * 16 + 8 + tg * 2];
#pragma unroll
                for (int na = 0; na < 4; na++)
                    mma16816(acc[ma][na], af, bfr[na][0], bfr[na][1]);
            }
        }
        __syncthreads();
    }

    // ---------------- epilogue ----------------
    if (EPI == 5) {
        // qkv GEMM: bn in {0,128}=Q, {256,384}=K, {512,640}=V (N=768, no bias)
        if (bn >= 512) {
            // V: direct fp16 store, layout [row][256]
#pragma unroll
            for (int ma = 0; ma < MA; ma++) {
                const int row0 = bm + wm * WM + ma * 16 + g;
#pragma unroll
                for (int na = 0; na < 4; na++) {
                    const int vcol = (bn - 512) + wn * 32 + na * 8 + tg * 2;
                    __half2 h0 = __floats2half2_rn(acc[ma][na][0], acc[ma][na][1]);
                    __half2 h1 = __floats2half2_rn(acc[ma][na][2], acc[ma][na][3]);
                    *(uint32_t*)(Vh + (size_t)row0 * 256 + vcol) = *reinterpret_cast<uint32_t*>(&h0);
                    *(uint32_t*)(Vh + (size_t)(row0 + 8) * 256 + vcol) = *reinterpret_cast<uint32_t*>(&h1);
                }
            }
        } else {
            // stage fp32 tile in smem, then rope pass
            float* fbuf = (float*)sm;   // [128][132]
#pragma unroll
            for (int ma = 0; ma < MA; ma++) {
                const int r0 = wm * WM + ma * 16 + g;
#pragma unroll
                for (int na = 0; na < 4; na++) {
                    const int col = wn * 32 + na * 8 + tg * 2;
                    *(float2*)&fbuf[r0 * 132 + col]       = make_float2(acc[ma][na][0], acc[ma][na][1]);
                    *(float2*)&fbuf[(r0 + 8) * 132 + col] = make_float2(acc[ma][na][2], acc[ma][na][3]);
                }
            }
            __syncthreads();
            const float LOG2E = 1.4426950408889634f;
            const bool isQ = (bn < 256);
#pragma unroll 4
            for (int i = 0; i < 32; i++) {
                int pi = tid + i * THREADS;    // 0..8191
                int row = pi >> 6;
                int rem = pi & 63;
                int hh = rem >> 5;
                int d  = rem & 31;
                float f0 = fbuf[row * 132 + hh * 64 + d];
                float f1 = fbuf[row * 132 + hh * 64 + d + 32];
                int n = (bm + row) & (N_ - 1);
                // inv_freq = 10000^(-d/32) = 2^(-d*log2(10000)/32)
                float ph = (float)n * exp2f((float)d * (-13.287712379549449f / 32.f));
                float sn, cs;
                sincosf(ph, &sn, &cs);
                float sc = 1.f;
                if (isQ) {
                    float lg = log2f((float)(n + 1)) * (1.f / 6.f);
                    sc = fmaxf(1.f, lg) * (0.125f * LOG2E);
                }
                size_t R = (size_t)(bm + row);
                Cbf[R * 512 + bn + hh * 64 + d]      = __float2bfloat16((f0 * cs - f1 * sn) * sc);
                Cbf[R * 512 + bn + hh * 64 + d + 32] = __float2bfloat16((f1 * cs + f0 * sn) * sc);
            }
        }
        return;
    }

#pragma unroll
    for (int ma = 0; ma < MA; ma++) {
        const int row0 = bm + wm * WM + ma * 16 + g;
        const int row1 = row0 + 8;
#pragma unroll
        for (int na = 0; na < 4; na++) {
            const int col = bn + wn * 32 + na * 8 + tg * 2;
            float bx = 0.f, by = 0.f;
            if (bias) {
                float2 b2 = *(const float2*)(bias + col);
                bx = b2.x; by = b2.y;
            }
            float v00 = acc[ma][na][0] + bx, v01 = acc[ma][na][1] + by;
            float v10 = acc[ma][na][2] + bx, v11 = acc[ma][na][3] + by;
            const size_t o0 = (size_t)row0 * N + col;
            const size_t o1 = (size_t)row1 * N + col;
            if (EPI == 1) {
                v00 = gelu_f(v00); v01 = gelu_f(v01);
                v10 = gelu_f(v10); v11 = gelu_f(v11);
            } else if (EPI == 2) {
                float2 r0 = *(const float2*)(res + o0);
                float2 r1 = *(const float2*)(res + o1);
                v00 += r0.x; v01 += r0.y; v10 += r1.x; v11 += r1.y;
            } else if (EPI == 3) {
                float2 r0 = *(const float2*)(res + o0);
                float2 r1 = *(const float2*)(res + o1);
                float2 g2 = *(const float2*)(gamma + col);
                v00 = r0.x + g2.x * v00; v01 = r0.y + g2.y * v01;
                v10 = r1.x + g2.x * v10; v11 = r1.y + g2.y * v11;
            }
            if (EPI != 1) {
                *(float2*)(C + o0) = make_float2(v00, v01);
                *(float2*)(C + o1) = make_float2(v10, v11);
            }
            if (EPI == 1 || Cbf != nullptr) {
                *(uint32_t*)(Cbf + o0) = packbf(v00, v01);
                *(uint32_t*)(Cbf + o1) = packbf(v10, v11);
            }
        }
    }
}

// ==================== LayerNorm (rows of 256) -> bf16 ====================
__global__ __launch_bounds__(256) void ln_kernel(
    const float* __restrict__ in, const float* __restrict__ s,
    const float* __restrict__ b, bf16* __restrict__ out)
{
    int gw   = (blockIdx.x * blockDim.x + threadIdx.x) >> 5;
    int lane = threadIdx.x & 31;
    if (gw >= M_) return;
    const float* x = in + (size_t)gw * INT_;
    float v[8], sum = 0.f, sq = 0.f;
#pragma unroll
    for (int i = 0; i < 8; i++) {
        v[i] = x[lane + 32 * i];
        sum += v[i]; sq += v[i] * v[i];
    }
#pragma unroll
    for (int o = 16; o > 0; o >>= 1) {
        sum += __shfl_xor_sync(0xffffffffu, sum, o);
        sq  += __shfl_xor_sync(0xffffffffu, sq,  o);
    }
    float mean = sum * (1.f / 256.f);
    float var  = sq * (1.f / 256.f) - mean * mean;
    float rstd = rsqrtf(var + 1e-5f);
    bf16* y = out + (size_t)gw * INT_;
#pragma unroll
    for (int i = 0; i < 8; i++) {
        int d = lane + 32 * i;
        y[d] = __float2bfloat16((v[i] - mean) * rstd * s[d] + b[d]);
    }
}

// ==================== Flash attention, split-KV, f16x2-exp softmax ====================
// grid (N/64, B*H, 4 chunks), block 128 (4 warps). Scores arrive in log2 domain.
#define KT_PER_CHUNK 8

__global__ __launch_bounds__(128) void attn_part(const bf16* __restrict__ qk,
                                                 const __half* __restrict__ vh,
                                                 float* __restrict__ Opart,
                                                 float* __restrict__ ml)
{
    __shared__ __align__(16) bf16   Qs[64][72];
    __shared__ __align__(16) bf16   Ks[2][64][72];
    __shared__ __align__(16) __half Vs[2][64][72];

    const int tid  = threadIdx.x;
    const int lane = tid & 31;
    const int w    = tid >> 5;
    const int g  = lane >> 2;
    const int tg = lane & 3;
    const int bh = blockIdx.y;
    const int b = bh >> 2, h = bh & 3;
    const int q0 = blockIdx.x * 64;
    const int ck = blockIdx.z;
    const uint32_t ks_base = smem_u32(&Ks[0][0][0]);
    const uint32_t vs_base = smem_u32(&Vs[0][0][0]);

    auto issueKV = [&](int kt) {
        const int p = kt & 1;
        const size_t krow = (size_t)(b * N_ + ck * 512 + kt * 64);
        const bf16*  kb = qk + krow * 512 + 256 + h * 64;
        const __half* vb = vh + krow * 256 + h * 64;
#pragma unroll
        for (int i = 0; i < 4; i++) {
            int v = tid + i * 128;
            int r = v >> 3, s = v & 7;
            cp16(ks_base + (uint32_t)((p * 64 + r) * 72 + s * 8) * 2, kb + (size_t)r * 512 + s * 8);
            cp16(vs_base + (uint32_t)((p * 64 + r) * 72 + s * 8) * 2, vb + (size_t)r * 256 + s * 8);
        }
        CP_COMMIT();
    };

    issueKV(0);

    // load Q tile (sync loads)
    {
        const bf16* qb = qk + (size_t)(b * N_ + q0) * 512 + h * 64;
#pragma unroll
        for (int i = 0; i < 4; i++) {
            int v = tid + i * 128;
            int r = v >> 3, s = v & 7;
            *(uint4*)&Qs[r][s * 8] = *(const uint4*)(qb + (size_t)r * 512 + s * 8);
        }
    }
    __syncthreads();

    uint32_t qf[4][4];
    {
        const int r0 = w * 16 + g;
#pragma unroll
        for (int kc = 0; kc < 4; kc++) {
            qf[kc][0] = *(const uint32_t*)&Qs[r0    ][kc * 16 + tg * 2];
            qf[kc][1] = *(const uint32_t*)&Qs[r0 + 8][kc * 16 + tg * 2];
            qf[kc][2] = *(const uint32_t*)&Qs[r0    ][kc * 16 + 8 + tg * 2];
            qf[kc][3] = *(const uint32_t*)&Qs[r0 + 8][kc * 16 + 8 + tg * 2];
        }
    }

    const int q4 = lane >> 3;
    const int v_rowpart = (lane & 7) + 8 * (q4 & 1);
    const int v_colpart = 8 * (q4 >> 1);
    const uint32_t ONES2 = 0x3C003C00u;   // f16x2 {1,1}

    float m0 = -INFINITY, m1 = -INFINITY;
    float o[8][4], lacc[4];
#pragma unroll
    for (int nh = 0; nh < 8; nh++)
#pragma unroll
        for (int r = 0; r < 4; r++) o[nh][r] = 0.f;
#pragma unroll
    for (int r = 0; r < 4; r++) lacc[r] = 0.f;

    for (int kt = 0; kt < KT_PER_CHUNK; kt++) {
        const int p = kt & 1;
        if (kt + 1 < KT_PER_CHUNK) { issueKV(kt + 1); CP_WAIT(1); }
        else                       { CP_WAIT(0); }
        __syncthreads();

        // ---- S = Q K^T (log2 domain) ----
        float s[8][4];
#pragma unroll
        for (int na = 0; na < 8; na++)
#pragma unroll
            for (int r = 0; r < 4; r++) s[na][r] = 0.f;
#pragma unroll
        for (int kc = 0; kc < 4; kc++) {
#pragma unroll
            for (int na = 0; na < 8; na++) {
                const int rb = na * 8 + g;
                uint32_t b0 = *(const uint32_t*)&Ks[p][rb][kc * 16 + tg * 2];
                uint32_t b1 = *(const uint32_t*)&Ks[p][rb][kc * 16 + 8 + tg * 2];
                mma16816(s[na], qf[kc], b0, b1);
            }
        }

        // ---- online softmax: max ----
        float mt0 = -INFINITY, mt1 = -INFINITY;
#pragma unroll
        for (int na = 0; na < 8; na++) {
            mt0 = fmaxf(mt0, fmaxf(s[na][0], s[na][1]));
            mt1 = fmaxf(mt1, fmaxf(s[na][2], s[na][3]));
        }
#pragma unroll
        for (int x = 1; x <= 2; x <<= 1) {
            mt0 = fmaxf(mt0, __shfl_xor_sync(0xffffffffu, mt0, x));
            mt1 = fmaxf(mt1, __shfl_xor_sync(0xffffffffu, mt1, x));
        }
        float mn0 = fmaxf(m0, mt0), mn1 = fmaxf(m1, mt1);
        float al0 = exp2f(m0 - mn0), al1 = exp2f(m1 - mn1);
        m0 = mn0; m1 = mn1;

        // ---- P = exp2(S - m) via f16x2 MUFU; directly the A-fragment ----
        uint32_t pf[4][4];
#pragma unroll
        for (int kc = 0; kc < 4; kc++) {
            pf[kc][0] = ex2_h2(s[2 * kc][0] - mn0,     s[2 * kc][1] - mn0);
            pf[kc][1] = ex2_h2(s[2 * kc][2] - mn1,     s[2 * kc][3] - mn1);
            pf[kc][2] = ex2_h2(s[2 * kc + 1][0] - mn0, s[2 * kc + 1][1] - mn0);
            pf[kc][3] = ex2_h2(s[2 * kc + 1][2] - mn1, s[2 * kc + 1][3] - mn1);
        }

        // ---- rescale O and l ----
#pragma unroll
        for (int nh = 0; nh < 8; nh++) {
            o[nh][0] *= al0; o[nh][1] *= al0;
            o[nh][2] *= al1; o[nh][3] *= al1;
        }
        lacc[0] *= al0; lacc[1] *= al0;
        lacc[2] *= al1; lacc[3] *= al1;

        // ---- O += P V ; l += P 1 ----
        const uint32_t vpb = vs_base + (uint32_t)(p * 64 * 72) * 2;
#pragma unroll
        for (int kc = 0; kc < 4; kc++) {
            mma16816h(lacc, pf[kc], ONES2, ONES2);
#pragma unroll
            for (int nh = 0; nh < 8; nh += 2) {
                uint32_t addr = vpb +
                    (uint32_t)((16 * kc + v_rowpart) * 144 + (nh * 8 + v_colpart) * 2);
                uint32_t b0, b1, b2, b3;
                asm volatile(
                    "ldmatrix.sync.aligned.m8n8.x4.trans.shared.b16 {%0,%1,%2,%3}, [%4];"
                    : "=r"(b0), "=r"(b1), "=r"(b2), "=r"(b3) : "r"(addr));
                mma16816h(o[nh],     pf[kc], b0, b1);
                mma16816h(o[nh + 1], pf[kc], b2, b3);
            }
        }
        __syncthreads();
    }

    // ---- write partial O (unnormalized) + m,l ----
    const int r0l = w * 16 + g;
    float* Obase = Opart + ((size_t)(ck * 8 + bh) * N_ + q0) * 64;
#pragma unroll
    for (int nh = 0; nh < 8; nh++) {
        const int col = nh * 8 + tg * 2;
        *(float2*)(Obase + (size_t)r0l * 64 + col)       = make_float2(o[nh][0], o[nh][1]);
        *(float2*)(Obase + (size_t)(r0l + 8) * 64 + col) = make_float2(o[nh][2], o[nh][3]);
    }
    if (tg == 0) {
        size_t mi0 = ((size_t)(ck * 8 + bh) * N_ + q0 + r0l) * 2;
        size_t mi1 = ((size_t)(ck * 8 + bh) * N_ + q0 + r0l + 8) * 2;
        ml[mi0] = m0; ml[mi0 + 1] = lacc[0];
        ml[mi1] = m1; ml[mi1 + 1] = lacc[2];
    }
}

// ==================== attention combine ====================
__global__ __launch_bounds__(256) void attn_combine(const float* __restrict__ Opart,
                                                    const float* __restrict__ ml,
                                                    bf16* __restrict__ out)
{
    int gw   = blockIdx.x * 8 + (threadIdx.x >> 5);   // 0..16383
    int lane = threadIdx.x & 31;
    int bh  = gw >> 11;
    int row = gw & 2047;
    int b = bh >> 2, h = bh & 3;

    float m[4], l[4];
#pragma unroll
    for (int c = 0; c < 4; c++) {
        size_t idx = ((size_t)(c * 8 + bh) * N_ + row) * 2;
        m[c] = ml[idx]; l[c] = ml[idx + 1];
    }
    float ms = fmaxf(fmaxf(m[0], m[1]), fmaxf(m[2], m[3]));
    float wsum = 0.f, a0 = 0.f, a1 = 0.f;
#pragma unroll
    for (int c = 0; c < 4; c++) {
        float wc = exp2f(m[c] - ms);
        wsum += wc * l[c];
        float2 v = *(const float2*)(Opart + ((size_t)(c * 8 + bh) * N_ + row) * 64 + lane * 2);
        a0 += wc * v.x; a1 += wc * v.y;
    }
    float inv = 1.f / wsum;
    *(uint32_t*)(out + ((size_t)(b * N_ + row)) * INT_ + h * 64 + lane * 2) =
        packbf(a0 * inv, a1 * inv);
}

// ==================== host ====================
extern "C" void kernel_launch(void* const* d_in, const int* in_sizes, int n_in,
                              void* d_out, int out_size)
{
    (void)in_sizes; (void)n_in; (void)out_size;
    const float* x   = (const float*)d_in[0];
    const float* dw  = (const float*)d_in[1];
    const float* db  = (const float*)d_in[2];
    const float* nds = (const float*)d_in[3];
    const float* ndb = (const float*)d_in[4];
    const float* qw  = (const float*)d_in[5];
    const float* pw  = (const float*)d_in[6];
    const float* pb  = (const float*)d_in[7];
    const float* nms = (const float*)d_in[8];
    const float* nmb = (const float*)d_in[9];
    const float* m1w = (const float*)d_in[10];
    const float* m1b = (const float*)d_in[11];
    const float* m2w = (const float*)d_in[12];
    const float* m2b = (const float*)d_in[13];
    const float* uw  = (const float*)d_in[14];
    const float* ub  = (const float*)d_in[15];
    const float* gm  = (const float*)d_in[16];

    float *X, *Hb, *Opart, *mlp;
    bf16 *qkbf, *xbf, *hnbf, *attbf, *g1bf, *hbf;
    __half* vh;
    bf16 *wd, *wq, *wp, *w1, *w2, *wu;
    cudaGetSymbolAddress((void**)&X,     g_X);
    cudaGetSymbolAddress((void**)&Hb,    g_H);
    cudaGetSymbolAddress((void**)&Opart, g_Opart);
    cudaGetSymbolAddress((void**)&mlp,   g_ml);
    cudaGetSymbolAddress((void**)&qkbf,  g_qkbf);
    cudaGetSymbolAddress((void**)&vh,    g_vh);
    cudaGetSymbolAddress((void**)&xbf,   g_xbf);
    cudaGetSymbolAddress((void**)&hnbf,  g_hnbf);
    cudaGetSymbolAddress((void**)&attbf, g_attbf);
    cudaGetSymbolAddress((void**)&g1bf,  g_g1bf);
    cudaGetSymbolAddress((void**)&hbf,   g_hbf);
    cudaGetSymbolAddress((void**)&wd,    g_wdown);
    cudaGetSymbolAddress((void**)&wq,    g_wqkv);
    cudaGetSymbolAddress((void**)&wp,    g_wproj);
    cudaGetSymbolAddress((void**)&w1,    g_wm1);
    cudaGetSymbolAddress((void**)&w2,    g_wm2);
    cudaGetSymbolAddress((void**)&wu,    g_wup);

    const int SM_6464   = 2 * (64 + 64)  * 72 * 2;   // 36864
    const int SM_12864  = 2 * (128 + 64) * 72 * 2;   // 55296
    const int SM_128128 = 2 * (128 + 128)* 72 * 2;   // 73728
    cudaFuncSetAttribute(gemm_cp<0,64,64,32>,   cudaFuncAttributeMaxDynamicSharedMemorySize, SM_6464);
    cudaFuncSetAttribute(gemm_cp<2,64,64,32>,   cudaFuncAttributeMaxDynamicSharedMemorySize, SM_6464);
    cudaFuncSetAttribute(gemm_cp<1,128,64,32>,  cudaFuncAttributeMaxDynamicSharedMemorySize, SM_12864);
    cudaFuncSetAttribute(gemm_cp<5,128,128,64>, cudaFuncAttributeMaxDynamicSharedMemorySize, SM_128128);
    cudaFuncSetAttribute(gemm_cp<3,128,128,64>, cudaFuncAttributeMaxDynamicSharedMemorySize, SM_128128);

    // one batched convert for input x + all weights
    {
        ConvArgs a;
        const float* srcs[7] = {x, dw, qw, pw, m1w, m2w, uw};
        bf16* dsts[7] = {xbf, wd, wq, wp, w1, w2, wu};
        unsigned sizes[7] = {
            M_ * D_ / 4,
            (unsigned)(L_ * INT_ * D_ / 4),
            (unsigned)(L_ * 3 * INT_ * INT_ / 4),
            (unsigned)(L_ * INT_ * INT_ / 4),
            (unsigned)(L_ * HID_ * INT_ / 4),
            (unsigned)(L_ * INT_ * HID_ / 4),
            (unsigned)(L_ * D_ * INT_ / 4)};
        unsigned acc = 0;
        for (int i = 0; i < 7; i++) {
            a.src[i] = srcs[i]; a.dst[i] = dsts[i];
            acc += sizes[i]; a.end[i] = acc;
        }
        conv_all<<<(acc + 255) / 256, 256>>>(a, acc);
    }

    for (int l = 0; l < L_; l++) {
        const float* xin = (l == 0) ? x : X;
        float* xout = (l == L_ - 1) ? (float*)d_out : X;
        bf16* xbf_out = (l == L_ - 1) ? nullptr : xbf;

        // h = x @ down_w^T + down_b
        gemm_cp<0,64,64,32><<<dim3(INT_ / 64, M_ / 64), 128, SM_6464>>>(
            xbf, wd + (size_t)l * INT_ * D_, db + (size_t)l * INT_,
            nullptr, nullptr, Hb, nullptr, nullptr, D_, INT_);
        // hn = LN(h) -> bf16
        ln_kernel<<<(M_ * 32) / 256, 256>>>(Hb, nds + (size_t)l * INT_,
                                            ndb + (size_t)l * INT_, hnbf);
        // qkv = hn @ qkv_w^T  with fused rope/logn/scale epilogue
        gemm_cp<5,128,128,64><<<dim3(6, M_ / 128), 256, SM_128128>>>(
            hnbf, wq + (size_t)l * 3 * INT_ * INT_, nullptr,
            nullptr, nullptr, nullptr, qkbf, vh, INT_, 768);
        // attention: 4 KV chunks -> 1024 CTAs, then combine
        attn_part<<<dim3(N_ / 64, B_ * H_, 4), 128>>>(qkbf, vh, Opart, mlp);
        attn_combine<<<(8 * N_) / 8, 256>>>(Opart, mlp, attbf);
        // h = res + (o @ proj_w^T + proj_b)
        gemm_cp<2,64,64,32><<<dim3(INT_ / 64, M_ / 64), 128, SM_6464>>>(
            attbf, wp + (size_t)l * INT_ * INT_, pb + (size_t)l * INT_,
            Hb, nullptr, Hb, nullptr, nullptr, INT_, INT_);
        // m = LN(h) -> bf16
        ln_kernel<<<(M_ * 32) / 256, 256>>>(Hb, nms + (size_t)l * INT_,
                                            nmb + (size_t)l * INT_, hnbf);
        // g1 = gelu(m @ m1^T + b1) -> bf16 only
        gemm_cp<1,128,64,32><<<dim3(HID_ / 64, M_ / 128), 256, SM_12864>>>(
            hnbf, w1 + (size_t)l * HID_ * INT_, m1b + (size_t)l * HID_,
            nullptr, nullptr, nullptr, g1bf, nullptr, INT_, HID_);
        // h = h + (g1 @ m2^T + b2) -> fp32 Hb + bf16 hbf
        gemm_cp<2,64,64,32><<<dim3(INT_ / 64, M_ / 64), 128, SM_6464>>>(
            g1bf, w2 + (size_t)l * INT_ * HID_, m2b + (size_t)l * INT_,
            Hb, nullptr, Hb, hbf, nullptr, HID_, INT_);
        // x = shortcut + gamma * (h @ up^T + ub)
        gemm_cp<3,128,128,64><<<dim3(D_ / 128, M_ / 128), 256, SM_128128>>>(
            hbf, wu + (size_t)l * D_ * INT_, ub + (size_t)l * D_,
            xin, gm + (size_t)l * D_, xout, xbf_out, nullptr, INT_, D_);
    }
}

// round 11
// speedup vs baseline: 5.0860x; 1.0042x over previous
#include <cuda_runtime.h>
#include <cuda_bf16.h>
#include <cuda_fp16.h>
#include <math.h>
#include <stdint.h>

#define B_   2
#define N_   2048
#define D_   1024
#define INT_ 256
#define H_   4
#define HD_  64
#define HID_ 512
#define L_   6
#define M_   (B_*N_)   // 4096 rows

typedef __nv_bfloat16 bf16;

// ==================== scratch ====================
__device__ float g_X  [M_ * D_];
__device__ float g_H  [M_ * INT_];
__device__ bf16  g_qkbf[M_ * 512];           // [row][ Qh0..Qh3 | Kh0..Kh3 ] (rope+scale applied)
__device__ __half g_vh [M_ * 256];           // [row][ Vh0..Vh3 ] fp16
__device__ bf16  g_xbf [M_ * D_];
__device__ bf16  g_hnbf[M_ * INT_];
__device__ bf16  g_attbf[M_ * INT_];
__device__ bf16  g_g1bf[M_ * HID_];
__device__ bf16  g_hbf [M_ * INT_];
__device__ float g_Opart[4 * 8 * N_ * 64];   // [chunk][bh][row][64]
__device__ float g_ml   [4 * 8 * N_ * 2];    // [chunk][bh][row][{m,l}]  (m in log2 domain)
// bf16 weights
__device__ bf16 g_wdown[L_ * INT_ * D_];
__device__ bf16 g_wqkv [L_ * 3 * INT_ * INT_];
__device__ bf16 g_wproj[L_ * INT_ * INT_];
__device__ bf16 g_wm1  [L_ * HID_ * INT_];
__device__ bf16 g_wm2  [L_ * INT_ * HID_];
__device__ bf16 g_wup  [L_ * D_ * INT_];

// ==================== helpers ====================
__device__ __forceinline__ uint32_t packbf(float a, float b) {
    __nv_bfloat162 t = __floats2bfloat162_rn(a, b);
    return *reinterpret_cast<uint32_t*>(&t);
}
__device__ __forceinline__ void mma16816(float* d, const uint32_t* a, uint32_t b0, uint32_t b1) {
    asm volatile(
        "mma.sync.aligned.m16n8k16.row.col.f32.bf16.bf16.f32 "
        "{%0,%1,%2,%3}, {%4,%5,%6,%7}, {%8,%9}, {%0,%1,%2,%3};"
        : "+f"(d[0]), "+f"(d[1]), "+f"(d[2]), "+f"(d[3])
        : "r"(a[0]), "r"(a[1]), "r"(a[2]), "r"(a[3]), "r"(b0), "r"(b1));
}
__device__ __forceinline__ void mma16816h(float* d, const uint32_t* a, uint32_t b0, uint32_t b1) {
    asm volatile(
        "mma.sync.aligned.m16n8k16.row.col.f32.f16.f16.f32 "
        "{%0,%1,%2,%3}, {%4,%5,%6,%7}, {%8,%9}, {%0,%1,%2,%3};"
        : "+f"(d[0]), "+f"(d[1]), "+f"(d[2]), "+f"(d[3])
        : "r"(a[0]), "r"(a[1]), "r"(a[2]), "r"(a[3]), "r"(b0), "r"(b1));
}
// two exp2's in one MUFU op; input floats, output packed f16x2
__device__ __forceinline__ uint32_t ex2_h2(float a, float b) {
    __half2 h = __floats2half2_rn(a, b);
    uint32_t u = *reinterpret_cast<uint32_t*>(&h);
    asm("ex2.approx.f16x2 %0, %0;" : "+r"(u));
    return u;
}
__device__ __forceinline__ uint32_t smem_u32(const void* p) {
    uint32_t a;
    asm("{ .reg .u64 t; cvta.to.shared.u64 t, %1; cvt.u32.u64 %0, t; }" : "=r"(a) : "l"(p));
    return a;
}
__device__ __forceinline__ void cp16(uint32_t dst, const void* src) {
    asm volatile("cp.async.cg.shared.global [%0], [%1], 16;" :: "r"(dst), "l"(src));
}
#define CP_COMMIT() asm volatile("cp.async.commit_group;")
#define CP_WAIT(n)  asm volatile("cp.async.wait_group %0;" :: "n"(n))

// ==================== batched fp32 -> bf16 convert (one launch) ====================
struct ConvArgs {
    const float* src[7];
    bf16* dst[7];
    unsigned end[7];    // prefix ends, float4 units
};
__global__ __launch_bounds__(256) void conv_all(ConvArgs a, unsigned total) {
    unsigned f4 = blockIdx.x * 256 + threadIdx.x;
    if (f4 >= total) return;
    int s = 0;
#pragma unroll
    for (int i = 0; i < 6; i++) if (f4 >= a.end[s]) s++;
    unsigned lo = f4 - (s ? a.end[s - 1] : 0);
    float4 v = ((const float4*)a.src[s])[lo];
    uint2 u = make_uint2(packbf(v.x, v.y), packbf(v.z, v.w));
    ((uint2*)a.dst[s])[lo] = u;
}

// ==================== cp.async double-buffered mma GEMM ====================
// C[M,N] = A[M,K] @ W[N,K]^T. Tile BM x BN, warp tile WM x 32, K chunk 64.
// EPI: 0 = +bias -> fp32 C ; 1 = gelu(+bias) -> bf16 Cbf only ;
//      2 = res + (+bias) -> fp32 C (+ optional bf16 Cbf) ;
//      3 = res + gamma*(+bias) -> fp32 C (+ optional bf16 Cbf) ;
//      5 = fused qkv rope epilogue (BN=64 tiles) -> bf16 Q/K (Cbf, stride 512), f16 V (Vh, stride 256)
__device__ __forceinline__ float gelu_f(float x) {
    return 0.5f * x * (1.0f + erff(x * 0.70710678118654752440f));
}

template<int EPI, int BM, int BN, int WM>
__global__ __launch_bounds__((BM/WM)*(BN/32)*32) void gemm_cp(
    const bf16* __restrict__ A, const bf16* __restrict__ W,
    const float* __restrict__ bias, const float* __restrict__ res,
    const float* __restrict__ gamma, float* __restrict__ C,
    bf16* __restrict__ Cbf, __half* __restrict__ Vh, int K, int N)
{
    constexpr int WARPS_M = BM / WM;
    constexpr int THREADS = WARPS_M * (BN / 32) * 32;
    constexpr int MA = WM / 16;
    constexpr int ALOOP = BM * 8 / THREADS;
    constexpr int BLOOP = BN * 8 / THREADS;

    extern __shared__ bf16 sm[];
    bf16* As = sm;                    // [2][BM][72]
    bf16* Bs = sm + 2 * BM * 72;      // [2][BN][72]
    const uint32_t sA = smem_u32(As);
    const uint32_t sB = smem_u32(Bs);

    const int tid  = threadIdx.x;
    const int lane = tid & 31;
    const int wid  = tid >> 5;
    const int g  = lane >> 2;
    const int tg = lane & 3;
    const int wm = wid % WARPS_M;
    const int wn = wid / WARPS_M;
    const int bm = blockIdx.y * BM;
    const int bn = blockIdx.x * BN;

    float acc[MA][4][4];
#pragma unroll
    for (int ma = 0; ma < MA; ma++)
#pragma unroll
        for (int na = 0; na < 4; na++)
#pragma unroll
            for (int r = 0; r < 4; r++) acc[ma][na][r] = 0.f;

    const bf16* Ab = A + (size_t)bm * K;
    const bf16* Wb = W + (size_t)bn * K;
    const int CH = K >> 6;

    auto issue = [&](int c) {
        const int p = c & 1;
        const int kof = c * 64;
#pragma unroll
        for (int i = 0; i < ALOOP; i++) {
            int v = tid + i * THREADS;
            int r = v >> 3, s = v & 7;
            cp16(sA + (uint32_t)((p * BM + r) * 72 + s * 8) * 2,
                 Ab + (size_t)r * K + kof + s * 8);
        }
#pragma unroll
        for (int i = 0; i < BLOOP; i++) {
            int v = tid + i * THREADS;
            int r = v >> 3, s = v & 7;
            cp16(sB + (uint32_t)((p * BN + r) * 72 + s * 8) * 2,
                 Wb + (size_t)r * K + kof + s * 8);
        }
        CP_COMMIT();
    };

    issue(0);
    for (int c = 0; c < CH; c++) {
        const int p = c & 1;
        if (c + 1 < CH) { issue(c + 1); CP_WAIT(1); }
        else           { CP_WAIT(0); }
        __syncthreads();

        const bf16* Ap = As + p * BM * 72;
        const bf16* Bp = Bs + p * BN * 72;
#pragma unroll
        for (int kc = 0; kc < 4; kc++) {
            uint32_t bfr[4][2];
#pragma unroll
            for (int na = 0; na < 4; na++) {
                const int rb = wn * 32 + na * 8 + g;
                bfr[na][0] = *(const uint32_t*)&Bp[rb * 72 + kc * 16 + tg * 2];
                bfr[na][1] = *(const uint32_t*)&Bp[rb * 72 + kc * 16 + 8 + tg * 2];
            }
#pragma unroll
            for (int ma = 0; ma < MA; ma++) {
                const int r0 = wm * WM + ma * 16 + g;
                uint32_t af[4];
                af[0] = *(const uint32_t*)&Ap[r0 * 72 + kc * 16 + tg * 2];
                af[1] = *(const uint32_t*)&Ap[(r0 + 8) * 72 + kc * 16 + tg * 2];
                af[2] = *(const uint32_t*)&Ap[r0 * 72 + kc * 16 + 8 + tg * 2];
                af[3] = *(const uint32_t*)&Ap[(r0 + 8) * 72 + kc * 16 + 8 + tg * 2];
#pragma unroll
                for (int na = 0; na < 4; na++)
                    mma16816(acc[ma][na], af, bfr[na][0], bfr[na][1]);
            }
        }
        __syncthreads();
    }

    // ---------------- epilogue ----------------
    if (EPI == 5) {
        // qkv GEMM, BN=64 tiles: bn in {0..192}=Q, {256..448}=K, {512..704}=V.
        // Each tile spans exactly one head (heads are 64 wide).
        if (bn >= 512) {
            // V: direct fp16 store, layout [row][256]
#pragma unroll
            for (int ma = 0; ma < MA; ma++) {
                const int row0 = bm + wm * WM + ma * 16 + g;
#pragma unroll
                for (int na = 0; na < 4; na++) {
                    const int vcol = (bn - 512) + wn * 32 + na * 8 + tg * 2;
                    __half2 h0 = __floats2half2_rn(acc[ma][na][0], acc[ma][na][1]);
                    __half2 h1 = __floats2half2_rn(acc[ma][na][2], acc[ma][na][3]);
                    *(uint32_t*)(Vh + (size_t)row0 * 256 + vcol) = *reinterpret_cast<uint32_t*>(&h0);
                    *(uint32_t*)(Vh + (size_t)(row0 + 8) * 256 + vcol) = *reinterpret_cast<uint32_t*>(&h1);
                }
            }
        } else {
            // stage fp32 tile in smem, then rope pass (pairs (d, d+32) in-tile)
            float* fbuf = (float*)sm;   // [BM][68]
#pragma unroll
            for (int ma = 0; ma < MA; ma++) {
                const int r0 = wm * WM + ma * 16 + g;
#pragma unroll
                for (int na = 0; na < 4; na++) {
                    const int col = wn * 32 + na * 8 + tg * 2;
                    *(float2*)&fbuf[r0 * 68 + col]       = make_float2(acc[ma][na][0], acc[ma][na][1]);
                    *(float2*)&fbuf[(r0 + 8) * 68 + col] = make_float2(acc[ma][na][2], acc[ma][na][3]);
                }
            }
            __syncthreads();
            const float LOG2E = 1.4426950408889634f;
            const bool isQ = (bn < 256);
            constexpr int ITERS = BM * 32 / THREADS;   // pairs / threads
#pragma unroll 4
            for (int i = 0; i < ITERS; i++) {
                int pi = tid + i * THREADS;    // 0 .. BM*32-1
                int row = pi >> 5;
                int d  = pi & 31;
                float f0 = fbuf[row * 68 + d];
                float f1 = fbuf[row * 68 + d + 32];
                int n = (bm + row) & (N_ - 1);
                // inv_freq = 10000^(-d/32) = 2^(-d*log2(10000)/32)
                float ph = (float)n * exp2f((float)d * (-13.287712379549449f / 32.f));
                float sn, cs;
                sincosf(ph, &sn, &cs);
                float sc = 1.f;
                if (isQ) {
                    float lg = log2f((float)(n + 1)) * (1.f / 6.f);
                    sc = fmaxf(1.f, lg) * (0.125f * LOG2E);
                }
                size_t R = (size_t)(bm + row);
                Cbf[R * 512 + bn + d]      = __float2bfloat16((f0 * cs - f1 * sn) * sc);
                Cbf[R * 512 + bn + d + 32] = __float2bfloat16((f1 * cs + f0 * sn) * sc);
            }
        }
        return;
    }

#pragma unroll
    for (int ma = 0; ma < MA; ma++) {
        const int row0 = bm + wm * WM + ma * 16 + g;
        const int row1 = row0 + 8;
#pragma unroll
        for (int na = 0; na < 4; na++) {
            const int col = bn + wn * 32 + na * 8 + tg * 2;
            float bx = 0.f, by = 0.f;
            if (bias) {
                float2 b2 = *(const float2*)(bias + col);
                bx = b2.x; by = b2.y;
            }
            float v00 = acc[ma][na][0] + bx, v01 = acc[ma][na][1] + by;
            float v10 = acc[ma][na][2] + bx, v11 = acc[ma][na][3] + by;
            const size_t o0 = (size_t)row0 * N + col;
            const size_t o1 = (size_t)row1 * N + col;
            if (EPI == 1) {
                v00 = gelu_f(v00); v01 = gelu_f(v01);
                v10 = gelu_f(v10); v11 = gelu_f(v11);
            } else if (EPI == 2) {
                float2 r0 = *(const float2*)(res + o0);
                float2 r1 = *(const float2*)(res + o1);
                v00 += r0.x; v01 += r0.y; v10 += r1.x; v11 += r1.y;
            } else if (EPI == 3) {
                float2 r0 = *(const float2*)(res + o0);
                float2 r1 = *(const float2*)(res + o1);
                float2 g2 = *(const float2*)(gamma + col);
                v00 = r0.x + g2.x * v00; v01 = r0.y + g2.y * v01;
                v10 = r1.x + g2.x * v10; v11 = r1.y + g2.y * v11;
            }
            if (EPI != 1) {
                *(float2*)(C + o0) = make_float2(v00, v01);
                *(float2*)(C + o1) = make_float2(v10, v11);
            }
            if (EPI == 1 || Cbf != nullptr) {
                *(uint32_t*)(Cbf + o0) = packbf(v00, v01);
                *(uint32_t*)(Cbf + o1) = packbf(v10, v11);
            }
        }
    }
}

// ==================== LayerNorm (rows of 256) -> bf16 ====================
__global__ __launch_bounds__(256) void ln_kernel(
    const float* __restrict__ in, const float* __restrict__ s,
    const float* __restrict__ b, bf16* __restrict__ out)
{
    int gw   = (blockIdx.x * blockDim.x + threadIdx.x) >> 5;
    int lane = threadIdx.x & 31;
    if (gw >= M_) return;
    const float* x = in + (size_t)gw * INT_;
    float v[8], sum = 0.f, sq = 0.f;
#pragma unroll
    for (int i = 0; i < 8; i++) {
        v[i] = x[lane + 32 * i];
        sum += v[i]; sq += v[i] * v[i];
    }
#pragma unroll
    for (int o = 16; o > 0; o >>= 1) {
        sum += __shfl_xor_sync(0xffffffffu, sum, o);
        sq  += __shfl_xor_sync(0xffffffffu, sq,  o);
    }
    float mean = sum * (1.f / 256.f);
    float var  = sq * (1.f / 256.f) - mean * mean;
    float rstd = rsqrtf(var + 1e-5f);
    bf16* y = out + (size_t)gw * INT_;
#pragma unroll
    for (int i = 0; i < 8; i++) {
        int d = lane + 32 * i;
        y[d] = __float2bfloat16((v[i] - mean) * rstd * s[d] + b[d]);
    }
}

// ==================== Flash attention, split-KV, f16x2-exp softmax ====================
// grid (N/64, B*H, 4 chunks), block 128 (4 warps). Scores arrive in log2 domain.
#define KT_PER_CHUNK 8

__global__ __launch_bounds__(128) void attn_part(const bf16* __restrict__ qk,
                                                 const __half* __restrict__ vh,
                                                 float* __restrict__ Opart,
                                                 float* __restrict__ ml)
{
    __shared__ __align__(16) bf16   Qs[64][72];
    __shared__ __align__(16) bf16   Ks[2][64][72];
    __shared__ __align__(16) __half Vs[2][64][72];

    const int tid  = threadIdx.x;
    const int lane = tid & 31;
    const int w    = tid >> 5;
    const int g  = lane >> 2;
    const int tg = lane & 3;
    const int bh = blockIdx.y;
    const int b = bh >> 2, h = bh & 3;
    const int q0 = blockIdx.x * 64;
    const int ck = blockIdx.z;
    const uint32_t ks_base = smem_u32(&Ks[0][0][0]);
    const uint32_t vs_base = smem_u32(&Vs[0][0][0]);

    auto issueKV = [&](int kt) {
        const int p = kt & 1;
        const size_t krow = (size_t)(b * N_ + ck * 512 + kt * 64);
        const bf16*  kb = qk + krow * 512 + 256 + h * 64;
        const __half* vb = vh + krow * 256 + h * 64;
#pragma unroll
        for (int i = 0; i < 4; i++) {
            int v = tid + i * 128;
            int r = v >> 3, s = v & 7;
            cp16(ks_base + (uint32_t)((p * 64 + r) * 72 + s * 8) * 2, kb + (size_t)r * 512 + s * 8);
            cp16(vs_base + (uint32_t)((p * 64 + r) * 72 + s * 8) * 2, vb + (size_t)r * 256 + s * 8);
        }
        CP_COMMIT();
    };

    issueKV(0);

    // load Q tile (sync loads)
    {
        const bf16* qb = qk + (size_t)(b * N_ + q0) * 512 + h * 64;
#pragma unroll
        for (int i = 0; i < 4; i++) {
            int v = tid + i * 128;
            int r = v >> 3, s = v & 7;
            *(uint4*)&Qs[r][s * 8] = *(const uint4*)(qb + (size_t)r * 512 + s * 8);
        }
    }
    __syncthreads();

    uint32_t qf[4][4];
    {
        const int r0 = w * 16 + g;
#pragma unroll
        for (int kc = 0; kc < 4; kc++) {
            qf[kc][0] = *(const uint32_t*)&Qs[r0    ][kc * 16 + tg * 2];
            qf[kc][1] = *(const uint32_t*)&Qs[r0 + 8][kc * 16 + tg * 2];
            qf[kc][2] = *(const uint32_t*)&Qs[r0    ][kc * 16 + 8 + tg * 2];
            qf[kc][3] = *(const uint32_t*)&Qs[r0 + 8][kc * 16 + 8 + tg * 2];
        }
    }

    const int q4 = lane >> 3;
    const int v_rowpart = (lane & 7) + 8 * (q4 & 1);
    const int v_colpart = 8 * (q4 >> 1);
    const uint32_t ONES2 = 0x3C003C00u;   // f16x2 {1,1}

    float m0 = -INFINITY, m1 = -INFINITY;
    float o[8][4], lacc[4];
#pragma unroll
    for (int nh = 0; nh < 8; nh++)
#pragma unroll
        for (int r = 0; r < 4; r++) o[nh][r] = 0.f;
#pragma unroll
    for (int r = 0; r < 4; r++) lacc[r] = 0.f;

    for (int kt = 0; kt < KT_PER_CHUNK; kt++) {
        const int p = kt & 1;
        if (kt + 1 < KT_PER_CHUNK) { issueKV(kt + 1); CP_WAIT(1); }
        else                       { CP_WAIT(0); }
        __syncthreads();

        // ---- S = Q K^T (log2 domain) ----
        float s[8][4];
#pragma unroll
        for (int na = 0; na < 8; na++)
#pragma unroll
            for (int r = 0; r < 4; r++) s[na][r] = 0.f;
#pragma unroll
        for (int kc = 0; kc < 4; kc++) {
#pragma unroll
            for (int na = 0; na < 8; na++) {
                const int rb = na * 8 + g;
                uint32_t b0 = *(const uint32_t*)&Ks[p][rb][kc * 16 + tg * 2];
                uint32_t b1 = *(const uint32_t*)&Ks[p][rb][kc * 16 + 8 + tg * 2];
                mma16816(s[na], qf[kc], b0, b1);
            }
        }

        // ---- online softmax: max ----
        float mt0 = -INFINITY, mt1 = -INFINITY;
#pragma unroll
        for (int na = 0; na < 8; na++) {
            mt0 = fmaxf(mt0, fmaxf(s[na][0], s[na][1]));
            mt1 = fmaxf(mt1, fmaxf(s[na][2], s[na][3]));
        }
#pragma unroll
        for (int x = 1; x <= 2; x <<= 1) {
            mt0 = fmaxf(mt0, __shfl_xor_sync(0xffffffffu, mt0, x));
            mt1 = fmaxf(mt1, __shfl_xor_sync(0xffffffffu, mt1, x));
        }
        float mn0 = fmaxf(m0, mt0), mn1 = fmaxf(m1, mt1);
        float al0 = exp2f(m0 - mn0), al1 = exp2f(m1 - mn1);
        m0 = mn0; m1 = mn1;

        // ---- P = exp2(S - m) via f16x2 MUFU; directly the A-fragment ----
        uint32_t pf[4][4];
#pragma unroll
        for (int kc = 0; kc < 4; kc++) {
            pf[kc][0] = ex2_h2(s[2 * kc][0] - mn0,     s[2 * kc][1] - mn0);
            pf[kc][1] = ex2_h2(s[2 * kc][2] - mn1,     s[2 * kc][3] - mn1);
            pf[kc][2] = ex2_h2(s[2 * kc + 1][0] - mn0, s[2 * kc + 1][1] - mn0);
            pf[kc][3] = ex2_h2(s[2 * kc + 1][2] - mn1, s[2 * kc + 1][3] - mn1);
        }

        // ---- rescale O and l ----
#pragma unroll
        for (int nh = 0; nh < 8; nh++) {
            o[nh][0] *= al0; o[nh][1] *= al0;
            o[nh][2] *= al1; o[nh][3] *= al1;
        }
        lacc[0] *= al0; lacc[1] *= al0;
        lacc[2] *= al1; lacc[3] *= al1;

        // ---- O += P V ; l += P 1 ----
        const uint32_t vpb = vs_base + (uint32_t)(p * 64 * 72) * 2;
#pragma unroll
        for (int kc = 0; kc < 4; kc++) {
            mma16816h(lacc, pf[kc], ONES2, ONES2);
#pragma unroll
            for (int nh = 0; nh < 8; nh += 2) {
                uint32_t addr = vpb +
                    (uint32_t)((16 * kc + v_rowpart) * 144 + (nh * 8 + v_colpart) * 2);
                uint32_t b0, b1, b2, b3;
                asm volatile(
                    "ldmatrix.sync.aligned.m8n8.x4.trans.shared.b16 {%0,%1,%2,%3}, [%4];"
                    : "=r"(b0), "=r"(b1), "=r"(b2), "=r"(b3) : "r"(addr));
                mma16816h(o[nh],     pf[kc], b0, b1);
                mma16816h(o[nh + 1], pf[kc], b2, b3);
            }
        }
        __syncthreads();
    }

    // ---- write partial O (unnormalized) + m,l ----
    const int r0l = w * 16 + g;
    float* Obase = Opart + ((size_t)(ck * 8 + bh) * N_ + q0) * 64;
#pragma unroll
    for (int nh = 0; nh < 8; nh++) {
        const int col = nh * 8 + tg * 2;
        *(float2*)(Obase + (size_t)r0l * 64 + col)       = make_float2(o[nh][0], o[nh][1]);
        *(float2*)(Obase + (size_t)(r0l + 8) * 64 + col) = make_float2(o[nh][2], o[nh][3]);
    }
    if (tg == 0) {
        size_t mi0 = ((size_t)(ck * 8 + bh) * N_ + q0 + r0l) * 2;
        size_t mi1 = ((size_t)(ck * 8 + bh) * N_ + q0 + r0l + 8) * 2;
        ml[mi0] = m0; ml[mi0 + 1] = lacc[0];
        ml[mi1] = m1; ml[mi1 + 1] = lacc[2];
    }
}

// ==================== attention combine ====================
__global__ __launch_bounds__(256) void attn_combine(const float* __restrict__ Opart,
                                                    const float* __restrict__ ml,
                                                    bf16* __restrict__ out)
{
    int gw   = blockIdx.x * 8 + (threadIdx.x >> 5);   // 0..16383
    int lane = threadIdx.x & 31;
    int bh  = gw >> 11;
    int row = gw & 2047;
    int b = bh >> 2, h = bh & 3;

    float m[4], l[4];
#pragma unroll
    for (int c = 0; c < 4; c++) {
        size_t idx = ((size_t)(c * 8 + bh) * N_ + row) * 2;
        m[c] = ml[idx]; l[c] = ml[idx + 1];
    }
    float ms = fmaxf(fmaxf(m[0], m[1]), fmaxf(m[2], m[3]));
    float wsum = 0.f, a0 = 0.f, a1 = 0.f;
#pragma unroll
    for (int c = 0; c < 4; c++) {
        float wc = exp2f(m[c] - ms);
        wsum += wc * l[c];
        float2 v = *(const float2*)(Opart + ((size_t)(c * 8 + bh) * N_ + row) * 64 + lane * 2);
        a0 += wc * v.x; a1 += wc * v.y;
    }
    float inv = 1.f / wsum;
    *(uint32_t*)(out + ((size_t)(b * N_ + row)) * INT_ + h * 64 + lane * 2) =
        packbf(a0 * inv, a1 * inv);
}

// ==================== host ====================
extern "C" void kernel_launch(void* const* d_in, const int* in_sizes, int n_in,
                              void* d_out, int out_size)
{
    (void)in_sizes; (void)n_in; (void)out_size;
    const float* x   = (const float*)d_in[0];
    const float* dw  = (const float*)d_in[1];
    const float* db  = (const float*)d_in[2];
    const float* nds = (const float*)d_in[3];
    const float* ndb = (const float*)d_in[4];
    const float* qw  = (const float*)d_in[5];
    const float* pw  = (const float*)d_in[6];
    const float* pb  = (const float*)d_in[7];
    const float* nms = (const float*)d_in[8];
    const float* nmb = (const float*)d_in[9];
    const float* m1w = (const float*)d_in[10];
    const float* m1b = (const float*)d_in[11];
    const float* m2w = (const float*)d_in[12];
    const float* m2b = (const float*)d_in[13];
    const float* uw  = (const float*)d_in[14];
    const float* ub  = (const float*)d_in[15];
    const float* gm  = (const float*)d_in[16];

    float *X, *Hb, *Opart, *mlp;
    bf16 *qkbf, *xbf, *hnbf, *attbf, *g1bf, *hbf;
    __half* vh;
    bf16 *wd, *wq, *wp, *w1, *w2, *wu;
    cudaGetSymbolAddress((void**)&X,     g_X);
    cudaGetSymbolAddress((void**)&Hb,    g_H);
    cudaGetSymbolAddress((void**)&Opart, g_Opart);
    cudaGetSymbolAddress((void**)&mlp,   g_ml);
    cudaGetSymbolAddress((void**)&qkbf,  g_qkbf);
    cudaGetSymbolAddress((void**)&vh,    g_vh);
    cudaGetSymbolAddress((void**)&xbf,   g_xbf);
    cudaGetSymbolAddress((void**)&hnbf,  g_hnbf);
    cudaGetSymbolAddress((void**)&attbf, g_attbf);
    cudaGetSymbolAddress((void**)&g1bf,  g_g1bf);
    cudaGetSymbolAddress((void**)&hbf,   g_hbf);
    cudaGetSymbolAddress((void**)&wd,    g_wdown);
    cudaGetSymbolAddress((void**)&wq,    g_wqkv);
    cudaGetSymbolAddress((void**)&wp,    g_wproj);
    cudaGetSymbolAddress((void**)&w1,    g_wm1);
    cudaGetSymbolAddress((void**)&w2,    g_wm2);
    cudaGetSymbolAddress((void**)&wu,    g_wup);

    const int SM_6464  = 2 * (64 + 64)  * 72 * 2;   // 36864
    const int SM_12864 = 2 * (128 + 64) * 72 * 2;   // 55296
    cudaFuncSetAttribute(gemm_cp<0,64,64,32>,  cudaFuncAttributeMaxDynamicSharedMemorySize, SM_6464);
    cudaFuncSetAttribute(gemm_cp<2,64,64,32>,  cudaFuncAttributeMaxDynamicSharedMemorySize, SM_6464);
    cudaFuncSetAttribute(gemm_cp<1,64,64,32>,  cudaFuncAttributeMaxDynamicSharedMemorySize, SM_6464);
    cudaFuncSetAttribute(gemm_cp<5,128,64,64>, cudaFuncAttributeMaxDynamicSharedMemorySize, SM_12864);
    cudaFuncSetAttribute(gemm_cp<3,128,64,64>, cudaFuncAttributeMaxDynamicSharedMemorySize, SM_12864);

    // one batched convert for input x + all weights
    {
        ConvArgs a;
        const float* srcs[7] = {x, dw, qw, pw, m1w, m2w, uw};
        bf16* dsts[7] = {xbf, wd, wq, wp, w1, w2, wu};
        unsigned sizes[7] = {
            M_ * D_ / 4,
            (unsigned)(L_ * INT_ * D_ / 4),
            (unsigned)(L_ * 3 * INT_ * INT_ / 4),
            (unsigned)(L_ * INT_ * INT_ / 4),
            (unsigned)(L_ * HID_ * INT_ / 4),
            (unsigned)(L_ * INT_ * HID_ / 4),
            (unsigned)(L_ * D_ * INT_ / 4)};
        unsigned acc = 0;
        for (int i = 0; i < 7; i++) {
            a.src[i] = srcs[i]; a.dst[i] = dsts[i];
            acc += sizes[i]; a.end[i] = acc;
        }
        conv_all<<<(acc + 255) / 256, 256>>>(a, acc);
    }

    for (int l = 0; l < L_; l++) {
        const float* xin = (l == 0) ? x : X;
        float* xout = (l == L_ - 1) ? (float*)d_out : X;
        bf16* xbf_out = (l == L_ - 1) ? nullptr : xbf;

        // h = x @ down_w^T + down_b   [4096x256, K=1024] -> 256 CTAs
        gemm_cp<0,64,64,32><<<dim3(INT_ / 64, M_ / 64), 128, SM_6464>>>(
            xbf, wd + (size_t)l * INT_ * D_, db + (size_t)l * INT_,
            nullptr, nullptr, Hb, nullptr, nullptr, D_, INT_);
        // hn = LN(h) -> bf16
        ln_kernel<<<(M_ * 32) / 256, 256>>>(Hb, nds + (size_t)l * INT_,
                                            ndb + (size_t)l * INT_, hnbf);
        // qkv = hn @ qkv_w^T  with fused rope/logn/scale epilogue -> 384 CTAs
        gemm_cp<5,128,64,64><<<dim3(12, M_ / 128), 128, SM_12864>>>(
            hnbf, wq + (size_t)l * 3 * INT_ * INT_, nullptr,
            nullptr, nullptr, nullptr, qkbf, vh, INT_, 768);
        // attention: 4 KV chunks -> 1024 CTAs, then combine
        attn_part<<<dim3(N_ / 64, B_ * H_, 4), 128>>>(qkbf, vh, Opart, mlp);
        attn_combine<<<(8 * N_) / 8, 256>>>(Opart, mlp, attbf);
        // h = res + (o @ proj_w^T + proj_b)   -> 256 CTAs
        gemm_cp<2,64,64,32><<<dim3(INT_ / 64, M_ / 64), 128, SM_6464>>>(
            attbf, wp + (size_t)l * INT_ * INT_, pb + (size_t)l * INT_,
            Hb, nullptr, Hb, nullptr, nullptr, INT_, INT_);
        // m = LN(h) -> bf16
        ln_kernel<<<(M_ * 32) / 256, 256>>>(Hb, nms + (size_t)l * INT_,
                                            nmb + (size_t)l * INT_, hnbf);
        // g1 = gelu(m @ m1^T + b1) -> bf16 only   -> 512 CTAs
        gemm_cp<1,64,64,32><<<dim3(HID_ / 64, M_ / 64), 128, SM_6464>>>(
            hnbf, w1 + (size_t)l * HID_ * INT_, m1b + (size_t)l * HID_,
            nullptr, nullptr, nullptr, g1bf, nullptr, INT_, HID_);
        // h = h + (g1 @ m2^T + b2) -> fp32 Hb + bf16 hbf   -> 256 CTAs
        gemm_cp<2,64,64,32><<<dim3(INT_ / 64, M_ / 64), 128, SM_6464>>>(
            g1bf, w2 + (size_t)l * INT_ * HID_, m2b + (size_t)l * INT_,
            Hb, nullptr, Hb, hbf, nullptr, HID_, INT_);
        // x = shortcut + gamma * (h @ up^T + ub)   -> 512 CTAs
        gemm_cp<3,128,64,64><<<dim3(D_ / 64, M_ / 128), 128, SM_12864>>>(
            hbf, wu + (size_t)l * D_ * INT_, ub + (size_t)l * D_,
            xin, gm + (size_t)l * D_, xout, xbf_out, nullptr, INT_, D_);
    }
}

// round 12
// speedup vs baseline: 5.2037x; 1.0231x over previous
#include <cuda_runtime.h>
#include <cuda_bf16.h>
#include <cuda_fp16.h>
#include <math.h>
#include <stdint.h>

#define B_   2
#define N_   2048
#define D_   1024
#define INT_ 256
#define H_   4
#define HD_  64
#define HID_ 512
#define L_   6
#define M_   (B_*N_)   // 4096 rows

typedef __nv_bfloat16 bf16;

// ==================== scratch ====================
__device__ float g_X  [M_ * D_];
__device__ float g_H  [M_ * INT_];
__device__ bf16  g_qkbf[M_ * 512];           // [row][ Qh0..Qh3 | Kh0..Kh3 ] (rope+scale applied)
__device__ __half g_vh [M_ * 256];           // [row][ Vh0..Vh3 ] fp16
__device__ bf16  g_xbf [M_ * D_];
__device__ bf16  g_hnbf[M_ * INT_];
__device__ bf16  g_attbf[M_ * INT_];
__device__ bf16  g_g1bf[M_ * HID_];
__device__ bf16  g_hbf [M_ * INT_];
__device__ float g_Opart[2 * 8 * N_ * 64];   // [chunk][bh][row][64]
__device__ float g_ml   [2 * 8 * N_ * 2];    // [chunk][bh][row][{m,l}]  (m in log2 domain)
__device__ float2 g_cs  [N_ * 32];           // rope {cos,sin} per (n,d)
__device__ float  g_lns [N_];                // per-n q scale: max(1,log2(n+1)/6)*0.125*log2e
// bf16 weights
__device__ bf16 g_wdown[L_ * INT_ * D_];
__device__ bf16 g_wqkv [L_ * 3 * INT_ * INT_];
__device__ bf16 g_wproj[L_ * INT_ * INT_];
__device__ bf16 g_wm1  [L_ * HID_ * INT_];
__device__ bf16 g_wm2  [L_ * INT_ * HID_];
__device__ bf16 g_wup  [L_ * D_ * INT_];

// ==================== helpers ====================
__device__ __forceinline__ uint32_t packbf(float a, float b) {
    __nv_bfloat162 t = __floats2bfloat162_rn(a, b);
    return *reinterpret_cast<uint32_t*>(&t);
}
__device__ __forceinline__ void mma16816(float* d, const uint32_t* a, uint32_t b0, uint32_t b1) {
    asm volatile(
        "mma.sync.aligned.m16n8k16.row.col.f32.bf16.bf16.f32 "
        "{%0,%1,%2,%3}, {%4,%5,%6,%7}, {%8,%9}, {%0,%1,%2,%3};"
        : "+f"(d[0]), "+f"(d[1]), "+f"(d[2]), "+f"(d[3])
        : "r"(a[0]), "r"(a[1]), "r"(a[2]), "r"(a[3]), "r"(b0), "r"(b1));
}
__device__ __forceinline__ void mma16816h(float* d, const uint32_t* a, uint32_t b0, uint32_t b1) {
    asm volatile(
        "mma.sync.aligned.m16n8k16.row.col.f32.f16.f16.f32 "
        "{%0,%1,%2,%3}, {%4,%5,%6,%7}, {%8,%9}, {%0,%1,%2,%3};"
        : "+f"(d[0]), "+f"(d[1]), "+f"(d[2]), "+f"(d[3])
        : "r"(a[0]), "r"(a[1]), "r"(a[2]), "r"(a[3]), "r"(b0), "r"(b1));
}
#define LDSM4(r0, r1, r2, r3, addr) \
    asm volatile("ldmatrix.sync.aligned.m8n8.x4.shared.b16 {%0,%1,%2,%3}, [%4];" \
        : "=r"(r0), "=r"(r1), "=r"(r2), "=r"(r3) : "r"(addr))
// two exp2's in one MUFU op; input floats, output packed f16x2
__device__ __forceinline__ uint32_t ex2_h2(float a, float b) {
    __half2 h = __floats2half2_rn(a, b);
    uint32_t u = *reinterpret_cast<uint32_t*>(&h);
    asm("ex2.approx.f16x2 %0, %0;" : "+r"(u));
    return u;
}
__device__ __forceinline__ uint32_t smem_u32(const void* p) {
    uint32_t a;
    asm("{ .reg .u64 t; cvta.to.shared.u64 t, %1; cvt.u32.u64 %0, t; }" : "=r"(a) : "l"(p));
    return a;
}
__device__ __forceinline__ void cp16(uint32_t dst, const void* src) {
    asm volatile("cp.async.cg.shared.global [%0], [%1], 16;" :: "r"(dst), "l"(src));
}
#define CP_COMMIT() asm volatile("cp.async.commit_group;")
#define CP_WAIT(n)  asm volatile("cp.async.wait_group %0;" :: "n"(n))

// ==================== rope table init ====================
__global__ __launch_bounds__(256) void rope_init() {
    int i = blockIdx.x * 256 + threadIdx.x;   // < N_*32
    int n = i >> 5, d = i & 31;
    float ph = (float)n * exp2f((float)d * (-13.287712379549449f / 32.f));
    float sn, cs;
    sincosf(ph, &sn, &cs);
    g_cs[i] = make_float2(cs, sn);
    if (d == 0) {
        const float LOG2E = 1.4426950408889634f;
        g_lns[n] = fmaxf(1.f, log2f((float)(n + 1)) * (1.f / 6.f)) * (0.125f * LOG2E);
    }
}

// ==================== batched fp32 -> bf16 convert (one launch) ====================
struct ConvArgs {
    const float* src[7];
    bf16* dst[7];
    unsigned end[7];    // prefix ends, float4 units
};
__global__ __launch_bounds__(256) void conv_all(ConvArgs a, unsigned total) {
    unsigned f4 = blockIdx.x * 256 + threadIdx.x;
    if (f4 >= total) return;
    int s = 0;
#pragma unroll
    for (int i = 0; i < 6; i++) if (f4 >= a.end[s]) s++;
    unsigned lo = f4 - (s ? a.end[s - 1] : 0);
    float4 v = ((const float4*)a.src[s])[lo];
    uint2 u = make_uint2(packbf(v.x, v.y), packbf(v.z, v.w));
    ((uint2*)a.dst[s])[lo] = u;
}

// ==================== cp.async double-buffered mma GEMM (ldmatrix fragments) ====
// C[M,N] = A[M,K] @ W[N,K]^T. Tile BM x BN, warp tile WM x 32, K chunk 64.
// EPI: 0 = +bias -> fp32 C ; 1 = gelu(+bias) -> bf16 Cbf only ;
//      2 = res + (+bias) -> fp32 C (+ optional bf16 Cbf) ;
//      3 = res + gamma*(+bias) -> fp32 C (+ optional bf16 Cbf) ;
//      5 = fused qkv rope epilogue (BN=64 tiles); res = rope cs table, gamma = logn table
__device__ __forceinline__ float gelu_f(float x) {
    return 0.5f * x * (1.0f + erff(x * 0.70710678118654752440f));
}

template<int EPI, int BM, int BN, int WM>
__global__ __launch_bounds__((BM/WM)*(BN/32)*32) void gemm_cp(
    const bf16* __restrict__ A, const bf16* __restrict__ W,
    const float* __restrict__ bias, const float* __restrict__ res,
    const float* __restrict__ gamma, float* __restrict__ C,
    bf16* __restrict__ Cbf, __half* __restrict__ Vh, int K, int N)
{
    constexpr int WARPS_M = BM / WM;
    constexpr int THREADS = WARPS_M * (BN / 32) * 32;
    constexpr int MA = WM / 16;
    constexpr int ALOOP = BM * 8 / THREADS;
    constexpr int BLOOP = BN * 8 / THREADS;
    constexpr uint32_t ABYTES = BM * 72 * 2;
    constexpr uint32_t BBYTES = BN * 72 * 2;

    extern __shared__ bf16 sm[];
    bf16* As = sm;                    // [2][BM][72]
    bf16* Bs = sm + 2 * BM * 72;      // [2][BN][72]
    const uint32_t sA = smem_u32(As);
    const uint32_t sB = smem_u32(Bs);

    const int tid  = threadIdx.x;
    const int lane = tid & 31;
    const int wid  = tid >> 5;
    const int g  = lane >> 2;
    const int tg = lane & 3;
    const int wm = wid % WARPS_M;
    const int wn = wid / WARPS_M;
    const int bm = blockIdx.y * BM;
    const int bn = blockIdx.x * BN;

    // ldmatrix lane-part offsets (bytes)
    const uint32_t a_lo = (uint32_t)(((lane & 15) * 72 + ((lane >> 4) << 3)) * 2);
    const int q8 = lane >> 3;
    const uint32_t b_lo = (uint32_t)(((((q8 >> 1) << 3) + (lane & 7)) * 72 + ((q8 & 1) << 3)) * 2);

    float acc[MA][4][4];
#pragma unroll
    for (int ma = 0; ma < MA; ma++)
#pragma unroll
        for (int na = 0; na < 4; na++)
#pragma unroll
            for (int r = 0; r < 4; r++) acc[ma][na][r] = 0.f;

    const bf16* Ab = A + (size_t)bm * K;
    const bf16* Wb = W + (size_t)bn * K;
    const int CH = K >> 6;

    auto issue = [&](int c) {
        const int p = c & 1;
        const int kof = c * 64;
#pragma unroll
        for (int i = 0; i < ALOOP; i++) {
            int v = tid + i * THREADS;
            int r = v >> 3, s = v & 7;
            cp16(sA + (uint32_t)((p * BM + r) * 72 + s * 8) * 2,
                 Ab + (size_t)r * K + kof + s * 8);
        }
#pragma unroll
        for (int i = 0; i < BLOOP; i++) {
            int v = tid + i * THREADS;
            int r = v >> 3, s = v & 7;
            cp16(sB + (uint32_t)((p * BN + r) * 72 + s * 8) * 2,
                 Wb + (size_t)r * K + kof + s * 8);
        }
        CP_COMMIT();
    };

    issue(0);
    for (int c = 0; c < CH; c++) {
        const int p = c & 1;
        if (c + 1 < CH) { issue(c + 1); CP_WAIT(1); }
        else           { CP_WAIT(0); }
        __syncthreads();

        const uint32_t aBase = sA + (p ? ABYTES : 0u) + (uint32_t)(wm * WM) * 144 + a_lo;
        const uint32_t bBase = sB + (p ? BBYTES : 0u) + (uint32_t)(wn * 32) * 144 + b_lo;
#pragma unroll
        for (int kc = 0; kc < 4; kc++) {
            uint32_t b01[4], b23[4];
            LDSM4(b01[0], b01[1], b01[2], b01[3], bBase + kc * 32);
            LDSM4(b23[0], b23[1], b23[2], b23[3], bBase + 16 * 144 + kc * 32);
#pragma unroll
            for (int ma = 0; ma < MA; ma++) {
                uint32_t af[4];
                LDSM4(af[0], af[1], af[2], af[3], aBase + (uint32_t)(ma * 16) * 144 + kc * 32);
                mma16816(acc[ma][0], af, b01[0], b01[1]);
                mma16816(acc[ma][1], af, b01[2], b01[3]);
                mma16816(acc[ma][2], af, b23[0], b23[1]);
                mma16816(acc[ma][3], af, b23[2], b23[3]);
            }
        }
        __syncthreads();
    }

    // ---------------- epilogue ----------------
    if (EPI == 5) {
        // qkv GEMM, BN=64 tiles: bn in {0..192}=Q, {256..448}=K, {512..704}=V.
        if (bn >= 512) {
#pragma unroll
            for (int ma = 0; ma < MA; ma++) {
                const int row0 = bm + wm * WM + ma * 16 + g;
#pragma unroll
                for (int na = 0; na < 4; na++) {
                    const int vcol = (bn - 512) + wn * 32 + na * 8 + tg * 2;
                    __half2 h0 = __floats2half2_rn(acc[ma][na][0], acc[ma][na][1]);
                    __half2 h1 = __floats2half2_rn(acc[ma][na][2], acc[ma][na][3]);
                    *(uint32_t*)(Vh + (size_t)row0 * 256 + vcol) = *reinterpret_cast<uint32_t*>(&h0);
                    *(uint32_t*)(Vh + (size_t)(row0 + 8) * 256 + vcol) = *reinterpret_cast<uint32_t*>(&h1);
                }
            }
        } else {
            // stage fp32 tile in smem, then rope pass using precomputed tables
            float* fbuf = (float*)sm;   // [BM][68]
#pragma unroll
            for (int ma = 0; ma < MA; ma++) {
                const int r0 = wm * WM + ma * 16 + g;
#pragma unroll
                for (int na = 0; na < 4; na++) {
                    const int col = wn * 32 + na * 8 + tg * 2;
                    *(float2*)&fbuf[r0 * 68 + col]       = make_float2(acc[ma][na][0], acc[ma][na][1]);
                    *(float2*)&fbuf[(r0 + 8) * 68 + col] = make_float2(acc[ma][na][2], acc[ma][na][3]);
                }
            }
            __syncthreads();
            const float2* cst = (const float2*)res;
            const bool isQ = (bn < 256);
            constexpr int ITERS = BM * 32 / THREADS;
#pragma unroll 4
            for (int i = 0; i < ITERS; i++) {
                int pi = tid + i * THREADS;    // 0 .. BM*32-1
                int row = pi >> 5;
                int d  = pi & 31;
                float f0 = fbuf[row * 68 + d];
                float f1 = fbuf[row * 68 + d + 32];
                int n = (bm + row) & (N_ - 1);
                float2 t = cst[n * 32 + d];
                float sc = isQ ? gamma[n] : 1.f;
                size_t R = (size_t)(bm + row);
                Cbf[R * 512 + bn + d]      = __float2bfloat16((f0 * t.x - f1 * t.y) * sc);
                Cbf[R * 512 + bn + d + 32] = __float2bfloat16((f1 * t.x + f0 * t.y) * sc);
            }
        }
        return;
    }

#pragma unroll
    for (int ma = 0; ma < MA; ma++) {
        const int row0 = bm + wm * WM + ma * 16 + g;
        const int row1 = row0 + 8;
#pragma unroll
        for (int na = 0; na < 4; na++) {
            const int col = bn + wn * 32 + na * 8 + tg * 2;
            float bx = 0.f, by = 0.f;
            if (bias) {
                float2 b2 = *(const float2*)(bias + col);
                bx = b2.x; by = b2.y;
            }
            float v00 = acc[ma][na][0] + bx, v01 = acc[ma][na][1] + by;
            float v10 = acc[ma][na][2] + bx, v11 = acc[ma][na][3] + by;
            const size_t o0 = (size_t)row0 * N + col;
            const size_t o1 = (size_t)row1 * N + col;
            if (EPI == 1) {
                v00 = gelu_f(v00); v01 = gelu_f(v01);
                v10 = gelu_f(v10); v11 = gelu_f(v11);
            } else if (EPI == 2) {
                float2 r0 = *(const float2*)(res + o0);
                float2 r1 = *(const float2*)(res + o1);
                v00 += r0.x; v01 += r0.y; v10 += r1.x; v11 += r1.y;
            } else if (EPI == 3) {
                float2 r0 = *(const float2*)(res + o0);
                float2 r1 = *(const float2*)(res + o1);
                float2 g2 = *(const float2*)(gamma + col);
                v00 = r0.x + g2.x * v00; v01 = r0.y + g2.y * v01;
                v10 = r1.x + g2.x * v10; v11 = r1.y + g2.y * v11;
            }
            if (EPI != 1) {
                *(float2*)(C + o0) = make_float2(v00, v01);
                *(float2*)(C + o1) = make_float2(v10, v11);
            }
            if (EPI == 1 || Cbf != nullptr) {
                *(uint32_t*)(Cbf + o0) = packbf(v00, v01);
                *(uint32_t*)(Cbf + o1) = packbf(v10, v11);
            }
        }
    }
}

// ==================== LayerNorm (rows of 256) -> bf16 ====================
__global__ __launch_bounds__(256) void ln_kernel(
    const float* __restrict__ in, const float* __restrict__ s,
    const float* __restrict__ b, bf16* __restrict__ out)
{
    int gw   = (blockIdx.x * blockDim.x + threadIdx.x) >> 5;
    int lane = threadIdx.x & 31;
    if (gw >= M_) return;
    const float* x = in + (size_t)gw * INT_;
    float v[8], sum = 0.f, sq = 0.f;
#pragma unroll
    for (int i = 0; i < 8; i++) {
        v[i] = x[lane + 32 * i];
        sum += v[i]; sq += v[i] * v[i];
    }
#pragma unroll
    for (int o = 16; o > 0; o >>= 1) {
        sum += __shfl_xor_sync(0xffffffffu, sum, o);
        sq  += __shfl_xor_sync(0xffffffffu, sq,  o);
    }
    float mean = sum * (1.f / 256.f);
    float var  = sq * (1.f / 256.f) - mean * mean;
    float rstd = rsqrtf(var + 1e-5f);
    bf16* y = out + (size_t)gw * INT_;
#pragma unroll
    for (int i = 0; i < 8; i++) {
        int d = lane + 32 * i;
        y[d] = __float2bfloat16((v[i] - mean) * rstd * s[d] + b[d]);
    }
}

// ==================== Flash attention, split-KV (2 chunks), f16x2-exp ====
// grid (N/64, B*H, 2), block 128 (4 warps). Scores arrive in log2 domain.
#define KT_PER_CHUNK 16

__global__ __launch_bounds__(128) void attn_part(const bf16* __restrict__ qk,
                                                 const __half* __restrict__ vh,
                                                 float* __restrict__ Opart,
                                                 float* __restrict__ ml)
{
    __shared__ __align__(16) bf16   Qs[64][72];
    __shared__ __align__(16) bf16   Ks[2][64][72];
    __shared__ __align__(16) __half Vs[2][64][72];

    const int tid  = threadIdx.x;
    const int lane = tid & 31;
    const int w    = tid >> 5;
    const int g  = lane >> 2;
    const int tg = lane & 3;
    const int bh = blockIdx.y;
    const int b = bh >> 2, h = bh & 3;
    const int q0 = blockIdx.x * 64;
    const int ck = blockIdx.z;
    const uint32_t ks_base = smem_u32(&Ks[0][0][0]);
    const uint32_t vs_base = smem_u32(&Vs[0][0][0]);

    const int q8 = lane >> 3;
    const uint32_t k_lo = (uint32_t)(((((q8 >> 1) << 3) + (lane & 7)) * 72 + ((q8 & 1) << 3)) * 2);

    auto issueKV = [&](int kt) {
        const int p = kt & 1;
        const size_t krow = (size_t)(b * N_ + ck * (KT_PER_CHUNK * 64) + kt * 64);
        const bf16*  kb = qk + krow * 512 + 256 + h * 64;
        const __half* vb = vh + krow * 256 + h * 64;
#pragma unroll
        for (int i = 0; i < 4; i++) {
            int v = tid + i * 128;
            int r = v >> 3, s = v & 7;
            cp16(ks_base + (uint32_t)((p * 64 + r) * 72 + s * 8) * 2, kb + (size_t)r * 512 + s * 8);
            cp16(vs_base + (uint32_t)((p * 64 + r) * 72 + s * 8) * 2, vb + (size_t)r * 256 + s * 8);
        }
        CP_COMMIT();
    };

    issueKV(0);

    // load Q tile (sync loads)
    {
        const bf16* qb = qk + (size_t)(b * N_ + q0) * 512 + h * 64;
#pragma unroll
        for (int i = 0; i < 4; i++) {
            int v = tid + i * 128;
            int r = v >> 3, s = v & 7;
            *(uint4*)&Qs[r][s * 8] = *(const uint4*)(qb + (size_t)r * 512 + s * 8);
        }
    }
    __syncthreads();

    uint32_t qf[4][4];
    {
        const int r0 = w * 16 + g;
#pragma unroll
        for (int kc = 0; kc < 4; kc++) {
            qf[kc][0] = *(const uint32_t*)&Qs[r0    ][kc * 16 + tg * 2];
            qf[kc][1] = *(const uint32_t*)&Qs[r0 + 8][kc * 16 + tg * 2];
            qf[kc][2] = *(const uint32_t*)&Qs[r0    ][kc * 16 + 8 + tg * 2];
            qf[kc][3] = *(const uint32_t*)&Qs[r0 + 8][kc * 16 + 8 + tg * 2];
        }
    }

    const int q4 = lane >> 3;
    const int v_rowpart = (lane & 7) + 8 * (q4 & 1);
    const int v_colpart = 8 * (q4 >> 1);
    const uint32_t ONES2 = 0x3C003C00u;   // f16x2 {1,1}

    float m0 = -INFINITY, m1 = -INFINITY;
    float o[8][4], lacc[4];
#pragma unroll
    for (int nh = 0; nh < 8; nh++)
#pragma unroll
        for (int r = 0; r < 4; r++) o[nh][r] = 0.f;
#pragma unroll
    for (int r = 0; r < 4; r++) lacc[r] = 0.f;

    for (int kt = 0; kt < KT_PER_CHUNK; kt++) {
        const int p = kt & 1;
        if (kt + 1 < KT_PER_CHUNK) { issueKV(kt + 1); CP_WAIT(1); }
        else                       { CP_WAIT(0); }
        __syncthreads();

        // ---- S = Q K^T (log2 domain), K fragments via ldmatrix.x4 ----
        float s[8][4];
#pragma unroll
        for (int na = 0; na < 8; na++)
#pragma unroll
            for (int r = 0; r < 4; r++) s[na][r] = 0.f;
        const uint32_t kBase = ks_base + (uint32_t)(p * 64 * 144) + k_lo;
#pragma unroll
        for (int kc = 0; kc < 4; kc++) {
#pragma unroll
            for (int pr = 0; pr < 4; pr++) {
                uint32_t kb4[4];
                LDSM4(kb4[0], kb4[1], kb4[2], kb4[3],
                      kBase + (uint32_t)(pr * 16 * 144) + kc * 32);
                mma16816(s[2 * pr],     qf[kc], kb4[0], kb4[1]);
                mma16816(s[2 * pr + 1], qf[kc], kb4[2], kb4[3]);
            }
        }

        // ---- online softmax: max ----
        float mt0 = -INFINITY, mt1 = -INFINITY;
#pragma unroll
        for (int na = 0; na < 8; na++) {
            mt0 = fmaxf(mt0, fmaxf(s[na][0], s[na][1]));
            mt1 = fmaxf(mt1, fmaxf(s[na][2], s[na][3]));
        }
#pragma unroll
        for (int x = 1; x <= 2; x <<= 1) {
            mt0 = fmaxf(mt0, __shfl_xor_sync(0xffffffffu, mt0, x));
            mt1 = fmaxf(mt1, __shfl_xor_sync(0xffffffffu, mt1, x));
        }
        float mn0 = fmaxf(m0, mt0), mn1 = fmaxf(m1, mt1);
        float al0 = exp2f(m0 - mn0), al1 = exp2f(m1 - mn1);
        m0 = mn0; m1 = mn1;

        // ---- P = exp2(S - m) via f16x2 MUFU; directly the A-fragment ----
        uint32_t pf[4][4];
#pragma unroll
        for (int kc = 0; kc < 4; kc++) {
            pf[kc][0] = ex2_h2(s[2 * kc][0] - mn0,     s[2 * kc][1] - mn0);
            pf[kc][1] = ex2_h2(s[2 * kc][2] - mn1,     s[2 * kc][3] - mn1);
            pf[kc][2] = ex2_h2(s[2 * kc + 1][0] - mn0, s[2 * kc + 1][1] - mn0);
            pf[kc][3] = ex2_h2(s[2 * kc + 1][2] - mn1, s[2 * kc + 1][3] - mn1);
        }

        // ---- rescale O and l ----
#pragma unroll
        for (int nh = 0; nh < 8; nh++) {
            o[nh][0] *= al0; o[nh][1] *= al0;
            o[nh][2] *= al1; o[nh][3] *= al1;
        }
        lacc[0] *= al0; lacc[1] *= al0;
        lacc[2] *= al1; lacc[3] *= al1;

        // ---- O += P V ; l += P 1 ----
        const uint32_t vpb = vs_base + (uint32_t)(p * 64 * 72) * 2;
#pragma unroll
        for (int kc = 0; kc < 4; kc++) {
            mma16816h(lacc, pf[kc], ONES2, ONES2);
#pragma unroll
            for (int nh = 0; nh < 8; nh += 2) {
                uint32_t addr = vpb +
                    (uint32_t)((16 * kc + v_rowpart) * 144 + (nh * 8 + v_colpart) * 2);
                uint32_t b0, b1, b2, b3;
                asm volatile(
                    "ldmatrix.sync.aligned.m8n8.x4.trans.shared.b16 {%0,%1,%2,%3}, [%4];"
                    : "=r"(b0), "=r"(b1), "=r"(b2), "=r"(b3) : "r"(addr));
                mma16816h(o[nh],     pf[kc], b0, b1);
                mma16816h(o[nh + 1], pf[kc], b2, b3);
            }
        }
        __syncthreads();
    }

    // ---- write partial O (unnormalized) + m,l ----
    const int r0l = w * 16 + g;
    float* Obase = Opart + ((size_t)(ck * 8 + bh) * N_ + q0) * 64;
#pragma unroll
    for (int nh = 0; nh < 8; nh++) {
        const int col = nh * 8 + tg * 2;
        *(float2*)(Obase + (size_t)r0l * 64 + col)       = make_float2(o[nh][0], o[nh][1]);
        *(float2*)(Obase + (size_t)(r0l + 8) * 64 + col) = make_float2(o[nh][2], o[nh][3]);
    }
    if (tg == 0) {
        size_t mi0 = ((size_t)(ck * 8 + bh) * N_ + q0 + r0l) * 2;
        size_t mi1 = ((size_t)(ck * 8 + bh) * N_ + q0 + r0l + 8) * 2;
        ml[mi0] = m0; ml[mi0 + 1] = lacc[0];
        ml[mi1] = m1; ml[mi1 + 1] = lacc[2];
    }
}

// ==================== attention combine (2 chunks) ====================
__global__ __launch_bounds__(256) void attn_combine(const float* __restrict__ Opart,
                                                    const float* __restrict__ ml,
                                                    bf16* __restrict__ out)
{
    int gw   = blockIdx.x * 8 + (threadIdx.x >> 5);   // 0..16383
    int lane = threadIdx.x & 31;
    int bh  = gw >> 11;
    int row = gw & 2047;
    int b = bh >> 2, h = bh & 3;

    float m[2], l[2];
#pragma unroll
    for (int c = 0; c < 2; c++) {
        size_t idx = ((size_t)(c * 8 + bh) * N_ + row) * 2;
        m[c] = ml[idx]; l[c] = ml[idx + 1];
    }
    float ms = fmaxf(m[0], m[1]);
    float wsum = 0.f, a0 = 0.f, a1 = 0.f;
#pragma unroll
    for (int c = 0; c < 2; c++) {
        float wc = exp2f(m[c] - ms);
        wsum += wc * l[c];
        float2 v = *(const float2*)(Opart + ((size_t)(c * 8 + bh) * N_ + row) * 64 + lane * 2);
        a0 += wc * v.x; a1 += wc * v.y;
    }
    float inv = 1.f / wsum;
    *(uint32_t*)(out + ((size_t)(b * N_ + row)) * INT_ + h * 64 + lane * 2) =
        packbf(a0 * inv, a1 * inv);
}

// ==================== host ====================
extern "C" void kernel_launch(void* const* d_in, const int* in_sizes, int n_in,
                              void* d_out, int out_size)
{
    (void)in_sizes; (void)n_in; (void)out_size;
    const float* x   = (const float*)d_in[0];
    const float* dw  = (const float*)d_in[1];
    const float* db  = (const float*)d_in[2];
    const float* nds = (const float*)d_in[3];
    const float* ndb = (const float*)d_in[4];
    const float* qw  = (const float*)d_in[5];
    const float* pw  = (const float*)d_in[6];
    const float* pb  = (const float*)d_in[7];
    const float* nms = (const float*)d_in[8];
    const float* nmb = (const float*)d_in[9];
    const float* m1w = (const float*)d_in[10];
    const float* m1b = (const float*)d_in[11];
    const float* m2w = (const float*)d_in[12];
    const float* m2b = (const float*)d_in[13];
    const float* uw  = (const float*)d_in[14];
    const float* ub  = (const float*)d_in[15];
    const float* gm  = (const float*)d_in[16];

    float *X, *Hb, *Opart, *mlp, *cst, *lnt;
    bf16 *qkbf, *xbf, *hnbf, *attbf, *g1bf, *hbf;
    __half* vh;
    bf16 *wd, *wq, *wp, *w1, *w2, *wu;
    cudaGetSymbolAddress((void**)&X,     g_X);
    cudaGetSymbolAddress((void**)&Hb,    g_H);
    cudaGetSymbolAddress((void**)&Opart, g_Opart);
    cudaGetSymbolAddress((void**)&mlp,   g_ml);
    cudaGetSymbolAddress((void**)&cst,   g_cs);
    cudaGetSymbolAddress((void**)&lnt,   g_lns);
    cudaGetSymbolAddress((void**)&qkbf,  g_qkbf);
    cudaGetSymbolAddress((void**)&vh,    g_vh);
    cudaGetSymbolAddress((void**)&xbf,   g_xbf);
    cudaGetSymbolAddress((void**)&hnbf,  g_hnbf);
    cudaGetSymbolAddress((void**)&attbf, g_attbf);
    cudaGetSymbolAddress((void**)&g1bf,  g_g1bf);
    cudaGetSymbolAddress((void**)&hbf,   g_hbf);
    cudaGetSymbolAddress((void**)&wd,    g_wdown);
    cudaGetSymbolAddress((void**)&wq,    g_wqkv);
    cudaGetSymbolAddress((void**)&wp,    g_wproj);
    cudaGetSymbolAddress((void**)&w1,    g_wm1);
    cudaGetSymbolAddress((void**)&w2,    g_wm2);
    cudaGetSymbolAddress((void**)&wu,    g_wup);

    const int SM_6464  = 2 * (64 + 64)  * 72 * 2;   // 36864
    const int SM_12864 = 2 * (128 + 64) * 72 * 2;   // 55296
    cudaFuncSetAttribute(gemm_cp<0,64,64,32>,  cudaFuncAttributeMaxDynamicSharedMemorySize, SM_6464);
    cudaFuncSetAttribute(gemm_cp<2,64,64,32>,  cudaFuncAttributeMaxDynamicSharedMemorySize, SM_6464);
    cudaFuncSetAttribute(gemm_cp<1,64,64,32>,  cudaFuncAttributeMaxDynamicSharedMemorySize, SM_6464);
    cudaFuncSetAttribute(gemm_cp<5,128,64,64>, cudaFuncAttributeMaxDynamicSharedMemorySize, SM_12864);
    cudaFuncSetAttribute(gemm_cp<3,128,64,64>, cudaFuncAttributeMaxDynamicSharedMemorySize, SM_12864);

    // rope tables (deterministic; every call)
    rope_init<<<(N_ * 32) / 256, 256>>>();

    // one batched convert for input x + all weights
    {
        ConvArgs a;
        const float* srcs[7] = {x, dw, qw, pw, m1w, m2w, uw};
        bf16* dsts[7] = {xbf, wd, wq, wp, w1, w2, wu};
        unsigned sizes[7] = {
            M_ * D_ / 4,
            (unsigned)(L_ * INT_ * D_ / 4),
            (unsigned)(L_ * 3 * INT_ * INT_ / 4),
            (unsigned)(L_ * INT_ * INT_ / 4),
            (unsigned)(L_ * HID_ * INT_ / 4),
            (unsigned)(L_ * INT_ * HID_ / 4),
            (unsigned)(L_ * D_ * INT_ / 4)};
        unsigned acc = 0;
        for (int i = 0; i < 7; i++) {
            a.src[i] = srcs[i]; a.dst[i] = dsts[i];
            acc += sizes[i]; a.end[i] = acc;
        }
        conv_all<<<(acc + 255) / 256, 256>>>(a, acc);
    }

    for (int l = 0; l < L_; l++) {
        const float* xin = (l == 0) ? x : X;
        float* xout = (l == L_ - 1) ? (float*)d_out : X;
        bf16* xbf_out = (l == L_ - 1) ? nullptr : xbf;

        // h = x @ down_w^T + down_b   [4096x256, K=1024] -> 256 CTAs
        gemm_cp<0,64,64,32><<<dim3(INT_ / 64, M_ / 64), 128, SM_6464>>>(
            xbf, wd + (size_t)l * INT_ * D_, db + (size_t)l * INT_,
            nullptr, nullptr, Hb, nullptr, nullptr, D_, INT_);
        // hn = LN(h) -> bf16
        ln_kernel<<<(M_ * 32) / 256, 256>>>(Hb, nds + (size_t)l * INT_,
                                            ndb + (size_t)l * INT_, hnbf);
        // qkv = hn @ qkv_w^T  with fused rope epilogue (tables) -> 384 CTAs
        gemm_cp<5,128,64,64><<<dim3(12, M_ / 128), 128, SM_12864>>>(
            hnbf, wq + (size_t)l * 3 * INT_ * INT_, nullptr,
            cst, lnt, nullptr, qkbf, vh, INT_, 768);
        // attention: 2 KV chunks -> 512 CTAs, then combine
        attn_part<<<dim3(N_ / 64, B_ * H_, 2), 128>>>(qkbf, vh, Opart, mlp);
        attn_combine<<<(8 * N_) / 8, 256>>>(Opart, mlp, attbf);
        // h = res + (o @ proj_w^T + proj_b)   -> 256 CTAs
        gemm_cp<2,64,64,32><<<dim3(INT_ / 64, M_ / 64), 128, SM_6464>>>(
            attbf, wp + (size_t)l * INT_ * INT_, pb + (size_t)l * INT_,
            Hb, nullptr, Hb, nullptr, nullptr, INT_, INT_);
        // m = LN(h) -> bf16
        ln_kernel<<<(M_ * 32) / 256, 256>>>(Hb, nms + (size_t)l * INT_,
                                            nmb + (size_t)l * INT_, hnbf);
        // g1 = gelu(m @ m1^T + b1) -> bf16 only   -> 512 CTAs
        gemm_cp<1,64,64,32><<<dim3(HID_ / 64, M_ / 64), 128, SM_6464>>>(
            hnbf, w1 + (size_t)l * HID_ * INT_, m1b + (size_t)l * HID_,
            nullptr, nullptr, nullptr, g1bf, nullptr, INT_, HID_);
        // h = h + (g1 @ m2^T + b2) -> fp32 Hb + bf16 hbf   -> 256 CTAs
        gemm_cp<2,64,64,32><<<dim3(INT_ / 64, M_ / 64), 128, SM_6464>>>(
            g1bf, w2 + (size_t)l * INT_ * HID_, m2b + (size_t)l * INT_,
            Hb, nullptr, Hb, hbf, nullptr, HID_, INT_);
        // x = shortcut + gamma * (h @ up^T + ub)   -> 512 CTAs
        gemm_cp<3,128,64,64><<<dim3(D_ / 64, M_ / 128), 128, SM_12864>>>(
            hbf, wu + (size_t)l * D_ * INT_, ub + (size_t)l * D_,
            xin, gm + (size_t)l * D_, xout, xbf_out, nullptr, INT_, D_);
    }
}

// round 14
// speedup vs baseline: 5.3171x; 1.0218x over previous
#include <cuda_runtime.h>
#include <cuda_bf16.h>
#include <cuda_fp16.h>
#include <math.h>
#include <stdint.h>

#define B_   2
#define N_   2048
#define D_   1024
#define INT_ 256
#define H_   4
#define HD_  64
#define HID_ 512
#define L_   6
#define M_   (B_*N_)   // 4096 rows

typedef __nv_bfloat16 bf16;

// ==================== scratch ====================
__device__ float g_X  [M_ * D_];
__device__ float g_H  [M_ * INT_];
__device__ bf16  g_qkbf[M_ * 512];           // [row][ Qh0..Qh3 | Kh0..Kh3 ] (rope+scale applied)
__device__ __half g_vh [M_ * 256];           // [row][ Vh0..Vh3 ] fp16
__device__ bf16  g_xbf [M_ * D_];
__device__ bf16  g_hnbf[M_ * INT_];
__device__ bf16  g_attbf[M_ * INT_];
__device__ bf16  g_g1bf[M_ * HID_];
__device__ bf16  g_hbf [M_ * INT_];
__device__ float g_Opart[4 * 8 * N_ * 64];   // [chunk][bh][row][64]
__device__ float g_ml   [4 * 8 * N_ * 2];    // [chunk][bh][row][{m,l}]  (m in log2 domain)
__device__ float2 g_cs  [N_ * 32];           // rope {cos,sin} per (n,d)
__device__ float  g_lns [N_];                // per-n q scale: max(1,log2(n+1)/6)*0.125*log2e
// bf16 weights
__device__ bf16 g_wdown[L_ * INT_ * D_];
__device__ bf16 g_wqkv [L_ * 3 * INT_ * INT_];
__device__ bf16 g_wproj[L_ * INT_ * INT_];
__device__ bf16 g_wm1  [L_ * HID_ * INT_];
__device__ bf16 g_wm2  [L_ * INT_ * HID_];
__device__ bf16 g_wup  [L_ * D_ * INT_];

// ==================== helpers ====================
__device__ __forceinline__ uint32_t packbf(float a, float b) {
    __nv_bfloat162 t = __floats2bfloat162_rn(a, b);
    return *reinterpret_cast<uint32_t*>(&t);
}
__device__ __forceinline__ void mma16816(float* d, const uint32_t* a, uint32_t b0, uint32_t b1) {
    asm volatile(
        "mma.sync.aligned.m16n8k16.row.col.f32.bf16.bf16.f32 "
        "{%0,%1,%2,%3}, {%4,%5,%6,%7}, {%8,%9}, {%0,%1,%2,%3};"
        : "+f"(d[0]), "+f"(d[1]), "+f"(d[2]), "+f"(d[3])
        : "r"(a[0]), "r"(a[1]), "r"(a[2]), "r"(a[3]), "r"(b0), "r"(b1));
}
__device__ __forceinline__ void mma16816h(float* d, const uint32_t* a, uint32_t b0, uint32_t b1) {
    asm volatile(
        "mma.sync.aligned.m16n8k16.row.col.f32.f16.f16.f32 "
        "{%0,%1,%2,%3}, {%4,%5,%6,%7}, {%8,%9}, {%0,%1,%2,%3};"
        : "+f"(d[0]), "+f"(d[1]), "+f"(d[2]), "+f"(d[3])
        : "r"(a[0]), "r"(a[1]), "r"(a[2]), "r"(a[3]), "r"(b0), "r"(b1));
}
#define LDSM4(r0, r1, r2, r3, addr) \
    asm volatile("ldmatrix.sync.aligned.m8n8.x4.shared.b16 {%0,%1,%2,%3}, [%4];" \
        : "=r"(r0), "=r"(r1), "=r"(r2), "=r"(r3) : "r"(addr))
// two exp2's in one MUFU op; input floats, output packed f16x2
__device__ __forceinline__ uint32_t ex2_h2(float a, float b) {
    __half2 h = __floats2half2_rn(a, b);
    uint32_t u = *reinterpret_cast<uint32_t*>(&h);
    asm("ex2.approx.f16x2 %0, %0;" : "+r"(u));
    return u;
}
__device__ __forceinline__ uint32_t smem_u32(const void* p) {
    uint32_t a;
    asm("{ .reg .u64 t; cvta.to.shared.u64 t, %1; cvt.u32.u64 %0, t; }" : "=r"(a) : "l"(p));
    return a;
}
__device__ __forceinline__ void cp16(uint32_t dst, const void* src) {
    asm volatile("cp.async.cg.shared.global [%0], [%1], 16;" :: "r"(dst), "l"(src));
}
#define CP_COMMIT() asm volatile("cp.async.commit_group;")
#define CP_WAIT(n)  asm volatile("cp.async.wait_group %0;" :: "n"(n))

// ==================== rope table init ====================
__global__ __launch_bounds__(256) void rope_init() {
    int i = blockIdx.x * 256 + threadIdx.x;   // < N_*32
    int n = i >> 5, d = i & 31;
    float ph = (float)n * exp2f((float)d * (-13.287712379549449f / 32.f));
    float sn, cs;
    sincosf(ph, &sn, &cs);
    g_cs[i] = make_float2(cs, sn);
    if (d == 0) {
        const float LOG2E = 1.4426950408889634f;
        g_lns[n] = fmaxf(1.f, log2f((float)(n + 1)) * (1.f / 6.f)) * (0.125f * LOG2E);
    }
}

// ==================== batched fp32 -> bf16 convert (one launch) ====================
struct ConvArgs {
    const float* src[7];
    bf16* dst[7];
    unsigned end[7];    // prefix ends, float4 units
};
__global__ __launch_bounds__(256) void conv_all(ConvArgs a, unsigned total) {
    unsigned f4 = blockIdx.x * 256 + threadIdx.x;
    if (f4 >= total) return;
    int s = 0;
#pragma unroll
    for (int i = 0; i < 6; i++) if (f4 >= a.end[s]) s++;
    unsigned lo = f4 - (s ? a.end[s - 1] : 0);
    float4 v = ((const float4*)a.src[s])[lo];
    uint2 u = make_uint2(packbf(v.x, v.y), packbf(v.z, v.w));
    ((uint2*)a.dst[s])[lo] = u;
}

// ==================== cp.async double-buffered mma GEMM (ldmatrix fragments) ====
// C[M,N] = A[M,K] @ W[N,K]^T. Tile BM x BN, warp tile WM x 32, K chunk 64.
// EPI: 0 = +bias -> fp32 C ; 1 = gelu(+bias) -> bf16 Cbf only ;
//      2 = res + (+bias) -> fp32 C (+ optional bf16 Cbf) ;
//      3 = res + gamma*(+bias) -> fp32 C (+ optional bf16 Cbf) ;
//      5 = fused qkv rope epilogue (BN=64 tiles); res = rope cs table, gamma = logn table
__device__ __forceinline__ float gelu_f(float x) {
    return 0.5f * x * (1.0f + erff(x * 0.70710678118654752440f));
}

template<int EPI, int BM, int BN, int WM, int MINB>
__global__ __launch_bounds__((BM/WM)*(BN/32)*32, MINB) void gemm_cp(
    const bf16* __restrict__ A, const bf16* __restrict__ W,
    const float* __restrict__ bias, const float* __restrict__ res,
    const float* __restrict__ gamma, float* __restrict__ C,
    bf16* __restrict__ Cbf, __half* __restrict__ Vh, int K, int N)
{
    constexpr int WARPS_M = BM / WM;
    constexpr int THREADS = WARPS_M * (BN / 32) * 32;
    constexpr int MA = WM / 16;
    constexpr int ALOOP = BM * 8 / THREADS;
    constexpr int BLOOP = BN * 8 / THREADS;
    constexpr uint32_t ABYTES = BM * 72 * 2;
    constexpr uint32_t BBYTES = BN * 72 * 2;

    extern __shared__ bf16 sm[];
    bf16* As = sm;                    // [2][BM][72]
    bf16* Bs = sm + 2 * BM * 72;      // [2][BN][72]
    const uint32_t sA = smem_u32(As);
    const uint32_t sB = smem_u32(Bs);

    const int tid  = threadIdx.x;
    const int lane = tid & 31;
    const int wid  = tid >> 5;
    const int g  = lane >> 2;
    const int tg = lane & 3;
    const int wm = wid % WARPS_M;
    const int wn = wid / WARPS_M;
    const int bm = blockIdx.y * BM;
    const int bn = blockIdx.x * BN;

    // ldmatrix lane-part offsets (bytes)
    const uint32_t a_lo = (uint32_t)(((lane & 15) * 72 + ((lane >> 4) << 3)) * 2);
    const int q8 = lane >> 3;
    const uint32_t b_lo = (uint32_t)(((((q8 >> 1) << 3) + (lane & 7)) * 72 + ((q8 & 1) << 3)) * 2);

    float acc[MA][4][4];
#pragma unroll
    for (int ma = 0; ma < MA; ma++)
#pragma unroll
        for (int na = 0; na < 4; na++)
#pragma unroll
            for (int r = 0; r < 4; r++) acc[ma][na][r] = 0.f;

    const bf16* Ab = A + (size_t)bm * K;
    const bf16* Wb = W + (size_t)bn * K;
    const int CH = K >> 6;

    auto issue = [&](int c) {
        const int p = c & 1;
        const int kof = c * 64;
#pragma unroll
        for (int i = 0; i < ALOOP; i++) {
            int v = tid + i * THREADS;
            int r = v >> 3, s = v & 7;
            cp16(sA + (uint32_t)((p * BM + r) * 72 + s * 8) * 2,
                 Ab + (size_t)r * K + kof + s * 8);
        }
#pragma unroll
        for (int i = 0; i < BLOOP; i++) {
            int v = tid + i * THREADS;
            int r = v >> 3, s = v & 7;
            cp16(sB + (uint32_t)((p * BN + r) * 72 + s * 8) * 2,
                 Wb + (size_t)r * K + kof + s * 8);
        }
        CP_COMMIT();
    };

    issue(0);
    for (int c = 0; c < CH; c++) {
        const int p = c & 1;
        if (c + 1 < CH) { issue(c + 1); CP_WAIT(1); }
        else           { CP_WAIT(0); }
        __syncthreads();

        const uint32_t aBase = sA + (p ? ABYTES : 0u) + (uint32_t)(wm * WM) * 144 + a_lo;
        const uint32_t bBase = sB + (p ? BBYTES : 0u) + (uint32_t)(wn * 32) * 144 + b_lo;
#pragma unroll
        for (int kc = 0; kc < 4; kc++) {
            uint32_t b01[4], b23[4];
            LDSM4(b01[0], b01[1], b01[2], b01[3], bBase + kc * 32);
            LDSM4(b23[0], b23[1], b23[2], b23[3], bBase + 16 * 144 + kc * 32);
#pragma unroll
            for (int ma = 0; ma < MA; ma++) {
                uint32_t af[4];
                LDSM4(af[0], af[1], af[2], af[3], aBase + (uint32_t)(ma * 16) * 144 + kc * 32);
                mma16816(acc[ma][0], af, b01[0], b01[1]);
                mma16816(acc[ma][1], af, b01[2], b01[3]);
                mma16816(acc[ma][2], af, b23[0], b23[1]);
                mma16816(acc[ma][3], af, b23[2], b23[3]);
            }
        }
        __syncthreads();
    }

    // ---------------- epilogue ----------------
    if (EPI == 5) {
        // qkv GEMM, BN=64 tiles: bn in {0..192}=Q, {256..448}=K, {512..704}=V.
        if (bn >= 512) {
#pragma unroll
            for (int ma = 0; ma < MA; ma++) {
                const int row0 = bm + wm * WM + ma * 16 + g;
#pragma unroll
                for (int na = 0; na < 4; na++) {
                    const int vcol = (bn - 512) + wn * 32 + na * 8 + tg * 2;
                    __half2 h0 = __floats2half2_rn(acc[ma][na][0], acc[ma][na][1]);
                    __half2 h1 = __floats2half2_rn(acc[ma][na][2], acc[ma][na][3]);
                    *(uint32_t*)(Vh + (size_t)row0 * 256 + vcol) = *reinterpret_cast<uint32_t*>(&h0);
                    *(uint32_t*)(Vh + (size_t)(row0 + 8) * 256 + vcol) = *reinterpret_cast<uint32_t*>(&h1);
                }
            }
        } else {
            // stage fp32 tile in smem, then rope pass using precomputed tables
            float* fbuf = (float*)sm;   // [BM][68]
#pragma unroll
            for (int ma = 0; ma < MA; ma++) {
                const int r0 = wm * WM + ma * 16 + g;
#pragma unroll
                for (int na = 0; na < 4; na++) {
                    const int col = wn * 32 + na * 8 + tg * 2;
                    *(float2*)&fbuf[r0 * 68 + col]       = make_float2(acc[ma][na][0], acc[ma][na][1]);
                    *(float2*)&fbuf[(r0 + 8) * 68 + col] = make_float2(acc[ma][na][2], acc[ma][na][3]);
                }
            }
            __syncthreads();
            const float2* cst = (const float2*)res;
            const bool isQ = (bn < 256);
            constexpr int ITERS = BM * 32 / THREADS;
#pragma unroll 4
            for (int i = 0; i < ITERS; i++) {
                int pi = tid + i * THREADS;    // 0 .. BM*32-1
                int row = pi >> 5;
                int d  = pi & 31;
                float f0 = fbuf[row * 68 + d];
                float f1 = fbuf[row * 68 + d + 32];
                int n = (bm + row) & (N_ - 1);
                float2 t = cst[n * 32 + d];
                float sc = isQ ? gamma[n] : 1.f;
                size_t R = (size_t)(bm + row);
                Cbf[R * 512 + bn + d]      = __float2bfloat16((f0 * t.x - f1 * t.y) * sc);
                Cbf[R * 512 + bn + d + 32] = __float2bfloat16((f1 * t.x + f0 * t.y) * sc);
            }
        }
        return;
    }

#pragma unroll
    for (int ma = 0; ma < MA; ma++) {
        const int row0 = bm + wm * WM + ma * 16 + g;
        const int row1 = row0 + 8;
#pragma unroll
        for (int na = 0; na < 4; na++) {
            const int col = bn + wn * 32 + na * 8 + tg * 2;
            float bx = 0.f, by = 0.f;
            if (bias) {
                float2 b2 = *(const float2*)(bias + col);
                bx = b2.x; by = b2.y;
            }
            float v00 = acc[ma][na][0] + bx, v01 = acc[ma][na][1] + by;
            float v10 = acc[ma][na][2] + bx, v11 = acc[ma][na][3] + by;
            const size_t o0 = (size_t)row0 * N + col;
            const size_t o1 = (size_t)row1 * N + col;
            if (EPI == 1) {
                v00 = gelu_f(v00); v01 = gelu_f(v01);
                v10 = gelu_f(v10); v11 = gelu_f(v11);
            } else if (EPI == 2) {
                float2 r0 = *(const float2*)(res + o0);
                float2 r1 = *(const float2*)(res + o1);
                v00 += r0.x; v01 += r0.y; v10 += r1.x; v11 += r1.y;
            } else if (EPI == 3) {
                float2 r0 = *(const float2*)(res + o0);
                float2 r1 = *(const float2*)(res + o1);
                float2 g2 = *(const float2*)(gamma + col);
                v00 = r0.x + g2.x * v00; v01 = r0.y + g2.y * v01;
                v10 = r1.x + g2.x * v10; v11 = r1.y + g2.y * v11;
            }
            if (EPI != 1) {
                *(float2*)(C + o0) = make_float2(v00, v01);
                *(float2*)(C + o1) = make_float2(v10, v11);
            }
            if (EPI == 1 || Cbf != nullptr) {
                *(uint32_t*)(Cbf + o0) = packbf(v00, v01);
                *(uint32_t*)(Cbf + o1) = packbf(v10, v11);
            }
        }
    }
}

// ==================== LayerNorm (rows of 256) -> bf16, float4 path ==========
__global__ __launch_bounds__(256) void ln_kernel(
    const float* __restrict__ in, const float* __restrict__ s,
    const float* __restrict__ b, bf16* __restrict__ out)
{
    int gw   = (blockIdx.x * blockDim.x + threadIdx.x) >> 5;
    int lane = threadIdx.x & 31;
    if (gw >= M_) return;
    const float* x = in + (size_t)gw * INT_;
    float4 v0 = *(const float4*)(x + lane * 4);
    float4 v1 = *(const float4*)(x + 128 + lane * 4);
    float sum = v0.x + v0.y + v0.z + v0.w + v1.x + v1.y + v1.z + v1.w;
    float sq  = v0.x * v0.x + v0.y * v0.y + v0.z * v0.z + v0.w * v0.w
              + v1.x * v1.x + v1.y * v1.y + v1.z * v1.z + v1.w * v1.w;
#pragma unroll
    for (int o = 16; o > 0; o >>= 1) {
        sum += __shfl_xor_sync(0xffffffffu, sum, o);
        sq  += __shfl_xor_sync(0xffffffffu, sq,  o);
    }
    float mean = sum * (1.f / 256.f);
    float var  = sq * (1.f / 256.f) - mean * mean;
    float rstd = rsqrtf(var + 1e-5f);
    bf16* y = out + (size_t)gw * INT_;
#pragma unroll
    for (int half = 0; half < 2; half++) {
        float4 v = half ? v1 : v0;
        int col = half * 128 + lane * 4;
        float4 s4 = *(const float4*)(s + col);
        float4 b4 = *(const float4*)(b + col);
        uint2 u = make_uint2(
            packbf((v.x - mean) * rstd * s4.x + b4.x,
                   (v.y - mean) * rstd * s4.y + b4.y),
            packbf((v.z - mean) * rstd * s4.z + b4.z,
                   (v.w - mean) * rstd * s4.w + b4.w));
        *(uint2*)(y + col) = u;
    }
}

// ==================== Flash attention, split-KV (4 chunks), f16x2-exp ====
// grid (N/64, B*H, 4), block 128 (4 warps). Scores arrive in log2 domain.
#define KT_PER_CHUNK 8

__global__ __launch_bounds__(128) void attn_part(const bf16* __restrict__ qk,
                                                 const __half* __restrict__ vh,
                                                 float* __restrict__ Opart,
                                                 float* __restrict__ ml)
{
    __shared__ __align__(16) bf16   Qs[64][72];
    __shared__ __align__(16) bf16   Ks[2][64][72];
    __shared__ __align__(16) __half Vs[2][64][72];

    const int tid  = threadIdx.x;
    const int lane = tid & 31;
    const int w    = tid >> 5;
    const int g  = lane >> 2;
    const int tg = lane & 3;
    const int bh = blockIdx.y;
    const int b = bh >> 2, h = bh & 3;
    const int q0 = blockIdx.x * 64;
    const int ck = blockIdx.z;
    const uint32_t ks_base = smem_u32(&Ks[0][0][0]);
    const uint32_t vs_base = smem_u32(&Vs[0][0][0]);

    const int q8 = lane >> 3;
    const uint32_t k_lo = (uint32_t)(((((q8 >> 1) << 3) + (lane & 7)) * 72 + ((q8 & 1) << 3)) * 2);

    auto issueKV = [&](int kt) {
        const int p = kt & 1;
        const size_t krow = (size_t)(b * N_ + ck * (KT_PER_CHUNK * 64) + kt * 64);
        const bf16*  kb = qk + krow * 512 + 256 + h * 64;
        const __half* vb = vh + krow * 256 + h * 64;
#pragma unroll
        for (int i = 0; i < 4; i++) {
            int v = tid + i * 128;
            int r = v >> 3, s = v & 7;
            cp16(ks_base + (uint32_t)((p * 64 + r) * 72 + s * 8) * 2, kb + (size_t)r * 512 + s * 8);
            cp16(vs_base + (uint32_t)((p * 64 + r) * 72 + s * 8) * 2, vb + (size_t)r * 256 + s * 8);
        }
        CP_COMMIT();
    };

    issueKV(0);

    // load Q tile (sync loads)
    {
        const bf16* qb = qk + (size_t)(b * N_ + q0) * 512 + h * 64;
#pragma unroll
        for (int i = 0; i < 4; i++) {
            int v = tid + i * 128;
            int r = v >> 3, s = v & 7;
            *(uint4*)&Qs[r][s * 8] = *(const uint4*)(qb + (size_t)r * 512 + s * 8);
        }
    }
    __syncthreads();

    uint32_t qf[4][4];
    {
        const int r0 = w * 16 + g;
#pragma unroll
        for (int kc = 0; kc < 4; kc++) {
            qf[kc][0] = *(const uint32_t*)&Qs[r0    ][kc * 16 + tg * 2];
            qf[kc][1] = *(const uint32_t*)&Qs[r0 + 8][kc * 16 + tg * 2];
            qf[kc][2] = *(const uint32_t*)&Qs[r0    ][kc * 16 + 8 + tg * 2];
            qf[kc][3] = *(const uint32_t*)&Qs[r0 + 8][kc * 16 + 8 + tg * 2];
        }
    }

    const int q4 = lane >> 3;
    const int v_rowpart = (lane & 7) + 8 * (q4 & 1);
    const int v_colpart = 8 * (q4 >> 1);
    const uint32_t ONES2 = 0x3C003C00u;   // f16x2 {1,1}

    float m0 = -INFINITY, m1 = -INFINITY;
    float o[8][4], lacc[4];
#pragma unroll
    for (int nh = 0; nh < 8; nh++)
#pragma unroll
        for (int r = 0; r < 4; r++) o[nh][r] = 0.f;
#pragma unroll
    for (int r = 0; r < 4; r++) lacc[r] = 0.f;

    for (int kt = 0; kt < KT_PER_CHUNK; kt++) {
        const int p = kt & 1;
        if (kt + 1 < KT_PER_CHUNK) { issueKV(kt + 1); CP_WAIT(1); }
        else                       { CP_WAIT(0); }
        __syncthreads();

        // ---- S = Q K^T (log2 domain), K fragments via ldmatrix.x4 ----
        float s[8][4];
#pragma unroll
        for (int na = 0; na < 8; na++)
#pragma unroll
            for (int r = 0; r < 4; r++) s[na][r] = 0.f;
        const uint32_t kBase = ks_base + (uint32_t)(p * 64 * 144) + k_lo;
#pragma unroll
        for (int kc = 0; kc < 4; kc++) {
#pragma unroll
            for (int pr = 0; pr < 4; pr++) {
                uint32_t kb4[4];
                LDSM4(kb4[0], kb4[1], kb4[2], kb4[3],
                      kBase + (uint32_t)(pr * 16 * 144) + kc * 32);
                mma16816(s[2 * pr],     qf[kc], kb4[0], kb4[1]);
                mma16816(s[2 * pr + 1], qf[kc], kb4[2], kb4[3]);
            }
        }

        // ---- online softmax: max ----
        float mt0 = -INFINITY, mt1 = -INFINITY;
#pragma unroll
        for (int na = 0; na < 8; na++) {
            mt0 = fmaxf(mt0, fmaxf(s[na][0], s[na][1]));
            mt1 = fmaxf(mt1, fmaxf(s[na][2], s[na][3]));
        }
#pragma unroll
        for (int x = 1; x <= 2; x <<= 1) {
            mt0 = fmaxf(mt0, __shfl_xor_sync(0xffffffffu, mt0, x));
            mt1 = fmaxf(mt1, __shfl_xor_sync(0xffffffffu, mt1, x));
        }
        float mn0 = fmaxf(m0, mt0), mn1 = fmaxf(m1, mt1);
        float al0 = exp2f(m0 - mn0), al1 = exp2f(m1 - mn1);
        m0 = mn0; m1 = mn1;

        // ---- P = exp2(S - m) via f16x2 MUFU; directly the A-fragment ----
        uint32_t pf[4][4];
#pragma unroll
        for (int kc = 0; kc < 4; kc++) {
            pf[kc][0] = ex2_h2(s[2 * kc][0] - mn0,     s[2 * kc][1] - mn0);
            pf[kc][1] = ex2_h2(s[2 * kc][2] - mn1,     s[2 * kc][3] - mn1);
            pf[kc][2] = ex2_h2(s[2 * kc + 1][0] - mn0, s[2 * kc + 1][1] - mn0);
            pf[kc][3] = ex2_h2(s[2 * kc + 1][2] - mn1, s[2 * kc + 1][3] - mn1);
        }

        // ---- rescale O and l ----
#pragma unroll
        for (int nh = 0; nh < 8; nh++) {
            o[nh][0] *= al0; o[nh][1] *= al0;
            o[nh][2] *= al1; o[nh][3] *= al1;
        }
        lacc[0] *= al0; lacc[1] *= al0;
        lacc[2] *= al1; lacc[3] *= al1;

        // ---- O += P V ; l += P 1 ----
        const uint32_t vpb = vs_base + (uint32_t)(p * 64 * 72) * 2;
#pragma unroll
        for (int kc = 0; kc < 4; kc++) {
            mma16816h(lacc, pf[kc], ONES2, ONES2);
#pragma unroll
            for (int nh = 0; nh < 8; nh += 2) {
                uint32_t addr = vpb +
                    (uint32_t)((16 * kc + v_rowpart) * 144 + (nh * 8 + v_colpart) * 2);
                uint32_t b0, b1, b2, b3;
                asm volatile(
                    "ldmatrix.sync.aligned.m8n8.x4.trans.shared.b16 {%0,%1,%2,%3}, [%4];"
                    : "=r"(b0), "=r"(b1), "=r"(b2), "=r"(b3) : "r"(addr));
                mma16816h(o[nh],     pf[kc], b0, b1);
                mma16816h(o[nh + 1], pf[kc], b2, b3);
            }
        }
        __syncthreads();
    }

    // ---- write partial O (unnormalized) + m,l ----
    const int r0l = w * 16 + g;
    float* Obase = Opart + ((size_t)(ck * 8 + bh) * N_ + q0) * 64;
#pragma unroll
    for (int nh = 0; nh < 8; nh++) {
        const int col = nh * 8 + tg * 2;
        *(float2*)(Obase + (size_t)r0l * 64 + col)       = make_float2(o[nh][0], o[nh][1]);
        *(float2*)(Obase + (size_t)(r0l + 8) * 64 + col) = make_float2(o[nh][2], o[nh][3]);
    }
    if (tg == 0) {
        size_t mi0 = ((size_t)(ck * 8 + bh) * N_ + q0 + r0l) * 2;
        size_t mi1 = ((size_t)(ck * 8 + bh) * N_ + q0 + r0l + 8) * 2;
        ml[mi0] = m0; ml[mi0 + 1] = lacc[0];
        ml[mi1] = m1; ml[mi1 + 1] = lacc[2];
    }
}

// ==================== attention combine (4 chunks) ====================
__global__ __launch_bounds__(256) void attn_combine(const float* __restrict__ Opart,
                                                    const float* __restrict__ ml,
                                                    bf16* __restrict__ out)
{
    int gw   = blockIdx.x * 8 + (threadIdx.x >> 5);   // 0..16383
    int lane = threadIdx.x & 31;
    int bh  = gw >> 11;
    int row = gw & 2047;
    int b = bh >> 2, h = bh & 3;

    float m[4], l[4];
#pragma unroll
    for (int c = 0; c < 4; c++) {
        size_t idx = ((size_t)(c * 8 + bh) * N_ + row) * 2;
        m[c] = ml[idx]; l[c] = ml[idx + 1];
    }
    float ms = fmaxf(fmaxf(m[0], m[1]), fmaxf(m[2], m[3]));
    float wsum = 0.f, a0 = 0.f, a1 = 0.f;
#pragma unroll
    for (int c = 0; c < 4; c++) {
        float wc = exp2f(m[c] - ms);
        wsum += wc * l[c];
        float2 v = *(const float2*)(Opart + ((size_t)(c * 8 + bh) * N_ + row) * 64 + lane * 2);
        a0 += wc * v.x; a1 += wc * v.y;
    }
    float inv = 1.f / wsum;
    *(uint32_t*)(out + ((size_t)(b * N_ + row)) * INT_ + h * 64 + lane * 2) =
        packbf(a0 * inv, a1 * inv);
}

// ==================== host ====================
extern "C" void kernel_launch(void* const* d_in, const int* in_sizes, int n_in,
                              void* d_out, int out_size)
{
    (void)in_sizes; (void)n_in; (void)out_size;
    const float* x   = (const float*)d_in[0];
    const float* dw  = (const float*)d_in[1];
    const float* db  = (const float*)d_in[2];
    const float* nds = (const float*)d_in[3];
    const float* ndb = (const float*)d_in[4];
    const float* qw  = (const float*)d_in[5];
    const float* pw  = (const float*)d_in[6];
    const float* pb  = (const float*)d_in[7];
    const float* nms = (const float*)d_in[8];
    const float* nmb = (const float*)d_in[9];
    const float* m1w = (const float*)d_in[10];
    const float* m1b = (const float*)d_in[11];
    const float* m2w = (const float*)d_in[12];
    const float* m2b = (const float*)d_in[13];
    const float* uw  = (const float*)d_in[14];
    const float* ub  = (const float*)d_in[15];
    const float* gm  = (const float*)d_in[16];

    float *X, *Hb, *Opart, *mlp, *cst, *lnt;
    bf16 *qkbf, *xbf, *hnbf, *attbf, *g1bf, *hbf;
    __half* vh;
    bf16 *wd, *wq, *wp, *w1, *w2, *wu;
    cudaGetSymbolAddress((void**)&X,     g_X);
    cudaGetSymbolAddress((void**)&Hb,    g_H);
    cudaGetSymbolAddress((void**)&Opart, g_Opart);
    cudaGetSymbolAddress((void**)&mlp,   g_ml);
    cudaGetSymbolAddress((void**)&cst,   g_cs);
    cudaGetSymbolAddress((void**)&lnt,   g_lns);
    cudaGetSymbolAddress((void**)&qkbf,  g_qkbf);
    cudaGetSymbolAddress((void**)&vh,    g_vh);
    cudaGetSymbolAddress((void**)&xbf,   g_xbf);
    cudaGetSymbolAddress((void**)&hnbf,  g_hnbf);
    cudaGetSymbolAddress((void**)&attbf, g_attbf);
    cudaGetSymbolAddress((void**)&g1bf,  g_g1bf);
    cudaGetSymbolAddress((void**)&hbf,   g_hbf);
    cudaGetSymbolAddress((void**)&wd,    g_wdown);
    cudaGetSymbolAddress((void**)&wq,    g_wqkv);
    cudaGetSymbolAddress((void**)&wp,    g_wproj);
    cudaGetSymbolAddress((void**)&w1,    g_wm1);
    cudaGetSymbolAddress((void**)&w2,    g_wm2);
    cudaGetSymbolAddress((void**)&wu,    g_wup);

    const int SM_6464  = 2 * (64 + 64)  * 72 * 2;   // 36864
    const int SM_12864 = 2 * (128 + 64) * 72 * 2;   // 55296
    cudaFuncSetAttribute(gemm_cp<0,64,64,32,6>,  cudaFuncAttributeMaxDynamicSharedMemorySize, SM_6464);
    cudaFuncSetAttribute(gemm_cp<2,64,64,32,6>,  cudaFuncAttributeMaxDynamicSharedMemorySize, SM_6464);
    cudaFuncSetAttribute(gemm_cp<1,64,64,32,6>,  cudaFuncAttributeMaxDynamicSharedMemorySize, SM_6464);
    cudaFuncSetAttribute(gemm_cp<5,128,64,64,5>, cudaFuncAttributeMaxDynamicSharedMemorySize, SM_12864);
    cudaFuncSetAttribute(gemm_cp<3,128,64,64,5>, cudaFuncAttributeMaxDynamicSharedMemorySize, SM_12864);

    // rope tables (deterministic; every call)
    rope_init<<<(N_ * 32) / 256, 256>>>();

    // one batched convert for input x + all weights
    {
        ConvArgs a;
        const float* srcs[7] = {x, dw, qw, pw, m1w, m2w, uw};
        bf16* dsts[7] = {xbf, wd, wq, wp, w1, w2, wu};
        unsigned sizes[7] = {
            M_ * D_ / 4,
            (unsigned)(L_ * INT_ * D_ / 4),
            (unsigned)(L_ * 3 * INT_ * INT_ / 4),
            (unsigned)(L_ * INT_ * INT_ / 4),
            (unsigned)(L_ * HID_ * INT_ / 4),
            (unsigned)(L_ * INT_ * HID_ / 4),
            (unsigned)(L_ * D_ * INT_ / 4)};
        unsigned acc = 0;
        for (int i = 0; i < 7; i++) {
            a.src[i] = srcs[i]; a.dst[i] = dsts[i];
            acc += sizes[i]; a.end[i] = acc;
        }
        conv_all<<<(acc + 255) / 256, 256>>>(a, acc);
    }

    for (int l = 0; l < L_; l++) {
        const float* xin = (l == 0) ? x : X;
        float* xout = (l == L_ - 1) ? (float*)d_out : X;
        bf16* xbf_out = (l == L_ - 1) ? nullptr : xbf;

        // h = x @ down_w^T + down_b   [4096x256, K=1024] -> 256 CTAs
        gemm_cp<0,64,64,32,6><<<dim3(INT_ / 64, M_ / 64), 128, SM_6464>>>(
            xbf, wd + (size_t)l * INT_ * D_, db + (size_t)l * INT_,
            nullptr, nullptr, Hb, nullptr, nullptr, D_, INT_);
        // hn = LN(h) -> bf16
        ln_kernel<<<(M_ * 32) / 256, 256>>>(Hb, nds + (size_t)l * INT_,
                                            ndb + (size_t)l * INT_, hnbf);
        // qkv = hn @ qkv_w^T  with fused rope epilogue (tables) -> 384 CTAs
        gemm_cp<5,128,64,64,5><<<dim3(12, M_ / 128), 128, SM_12864>>>(
            hnbf, wq + (size_t)l * 3 * INT_ * INT_, nullptr,
            cst, lnt, nullptr, qkbf, vh, INT_, 768);
        // attention: 4 KV chunks -> 1024 CTAs, then combine
        attn_part<<<dim3(N_ / 64, B_ * H_, 4), 128>>>(qkbf, vh, Opart, mlp);
        attn_combine<<<(8 * N_) / 8, 256>>>(Opart, mlp, attbf);
        // h = res + (o @ proj_w^T + proj_b)   -> 256 CTAs
        gemm_cp<2,64,64,32,6><<<dim3(INT_ / 64, M_ / 64), 128, SM_6464>>>(
            attbf, wp + (size_t)l * INT_ * INT_, pb + (size_t)l * INT_,
            Hb, nullptr, Hb, nullptr, nullptr, INT_, INT_);
        // m = LN(h) -> bf16
        ln_kernel<<<(M_ * 32) / 256, 256>>>(Hb, nms + (size_t)l * INT_,
                                            nmb + (size_t)l * INT_, hnbf);
        // g1 = gelu(m @ m1^T + b1) -> bf16 only   -> 512 CTAs
        gemm_cp<1,64,64,32,6><<<dim3(HID_ / 64, M_ / 64), 128, SM_6464>>>(
            hnbf, w1 + (size_t)l * HID_ * INT_, m1b + (size_t)l * HID_,
            nullptr, nullptr, nullptr, g1bf, nullptr, INT_, HID_);
        // h = h + (g1 @ m2^T + b2) -> fp32 Hb + bf16 hbf   -> 256 CTAs
        gemm_cp<2,64,64,32,6><<<dim3(INT_ / 64, M_ / 64), 128, SM_6464>>>(
            g1bf, w2 + (size_t)l * INT_ * HID_, m2b + (size_t)l * INT_,
            Hb, nullptr, Hb, hbf, nullptr, HID_, INT_);
        // x = shortcut + gamma * (h @ up^T + ub)   -> 512 CTAs
        gemm_cp<3,128,64,64,5><<<dim3(D_ / 64, M_ / 128), 128, SM_12864>>>(
            hbf, wu + (size_t)l * D_ * INT_, ub + (size_t)l * D_,
            xin, gm + (size_t)l * D_, xout, xbf_out, nullptr, INT_, D_);
    }
}

// round 15
// speedup vs baseline: 5.4295x; 1.0211x over previous
#include <cuda_runtime.h>
#include <cuda_bf16.h>
#include <cuda_fp16.h>
#include <math.h>
#include <stdint.h>

#define B_   2
#define N_   2048
#define D_   1024
#define INT_ 256
#define H_   4
#define HD_  64
#define HID_ 512
#define L_   6
#define M_   (B_*N_)   // 4096 rows

typedef __nv_bfloat16 bf16;

// ==================== scratch ====================
__device__ float g_X  [M_ * D_];
__device__ float g_H  [M_ * INT_];
__device__ bf16  g_qkbf[M_ * 512];           // [row][ Qh0..Qh3 | Kh0..Kh3 ] (rope+scale applied)
__device__ __half g_vh [M_ * 256];           // [row][ Vh0..Vh3 ] fp16
__device__ bf16  g_xbf [M_ * D_];
__device__ bf16  g_hnbf[M_ * INT_];
__device__ bf16  g_attbf[M_ * INT_];
__device__ bf16  g_g1bf[M_ * HID_];
__device__ bf16  g_hbf [M_ * INT_];
__device__ __half g_Opart[4 * 8 * N_ * 64]; // [chunk][bh][row][64] fp16
__device__ float g_ml   [4 * 8 * N_ * 2];    // [chunk][bh][row][{m,l}]  (m in log2 domain)
__device__ float2 g_cs  [N_ * 32];           // rope {cos,sin} per (n,d)
__device__ float  g_lns [N_];                // per-n q scale: max(1,log2(n+1)/6)*0.125*log2e
// bf16 weights
__device__ bf16 g_wdown[L_ * INT_ * D_];
__device__ bf16 g_wqkv [L_ * 3 * INT_ * INT_];
__device__ bf16 g_wproj[L_ * INT_ * INT_];
__device__ bf16 g_wm1  [L_ * HID_ * INT_];
__device__ bf16 g_wm2  [L_ * INT_ * HID_];
__device__ bf16 g_wup  [L_ * D_ * INT_];

// ==================== helpers ====================
__device__ __forceinline__ uint32_t packbf(float a, float b) {
    __nv_bfloat162 t = __floats2bfloat162_rn(a, b);
    return *reinterpret_cast<uint32_t*>(&t);
}
__device__ __forceinline__ uint32_t packh(float a, float b) {
    __half2 t = __floats2half2_rn(a, b);
    return *reinterpret_cast<uint32_t*>(&t);
}
__device__ __forceinline__ void mma16816(float* d, const uint32_t* a, uint32_t b0, uint32_t b1) {
    asm volatile(
        "mma.sync.aligned.m16n8k16.row.col.f32.bf16.bf16.f32 "
        "{%0,%1,%2,%3}, {%4,%5,%6,%7}, {%8,%9}, {%0,%1,%2,%3};"
        : "+f"(d[0]), "+f"(d[1]), "+f"(d[2]), "+f"(d[3])
        : "r"(a[0]), "r"(a[1]), "r"(a[2]), "r"(a[3]), "r"(b0), "r"(b1));
}
__device__ __forceinline__ void mma16816h(float* d, const uint32_t* a, uint32_t b0, uint32_t b1) {
    asm volatile(
        "mma.sync.aligned.m16n8k16.row.col.f32.f16.f16.f32 "
        "{%0,%1,%2,%3}, {%4,%5,%6,%7}, {%8,%9}, {%0,%1,%2,%3};"
        : "+f"(d[0]), "+f"(d[1]), "+f"(d[2]), "+f"(d[3])
        : "r"(a[0]), "r"(a[1]), "r"(a[2]), "r"(a[3]), "r"(b0), "r"(b1));
}
#define LDSM4(r0, r1, r2, r3, addr) \
    asm volatile("ldmatrix.sync.aligned.m8n8.x4.shared.b16 {%0,%1,%2,%3}, [%4];" \
        : "=r"(r0), "=r"(r1), "=r"(r2), "=r"(r3) : "r"(addr))
// two exp2's in one MUFU op; input floats, output packed f16x2
__device__ __forceinline__ uint32_t ex2_h2(float a, float b) {
    __half2 h = __floats2half2_rn(a, b);
    uint32_t u = *reinterpret_cast<uint32_t*>(&h);
    asm("ex2.approx.f16x2 %0, %0;" : "+r"(u));
    return u;
}
__device__ __forceinline__ uint32_t smem_u32(const void* p) {
    uint32_t a;
    asm("{ .reg .u64 t; cvta.to.shared.u64 t, %1; cvt.u32.u64 %0, t; }" : "=r"(a) : "l"(p));
    return a;
}
__device__ __forceinline__ void cp16(uint32_t dst, const void* src) {
    asm volatile("cp.async.cg.shared.global [%0], [%1], 16;" :: "r"(dst), "l"(src));
}
#define CP_COMMIT() asm volatile("cp.async.commit_group;")
#define CP_WAIT(n)  asm volatile("cp.async.wait_group %0;" :: "n"(n))

// ==================== rope table init ====================
__global__ __launch_bounds__(256) void rope_init() {
    int i = blockIdx.x * 256 + threadIdx.x;   // < N_*32
    int n = i >> 5, d = i & 31;
    float ph = (float)n * exp2f((float)d * (-13.287712379549449f / 32.f));
    float sn, cs;
    sincosf(ph, &sn, &cs);
    g_cs[i] = make_float2(cs, sn);
    if (d == 0) {
        const float LOG2E = 1.4426950408889634f;
        g_lns[n] = fmaxf(1.f, log2f((float)(n + 1)) * (1.f / 6.f)) * (0.125f * LOG2E);
    }
}

// ==================== batched fp32 -> bf16 convert (one launch) ====================
struct ConvArgs {
    const float* src[7];
    bf16* dst[7];
    unsigned end[7];    // prefix ends, float4 units
};
__global__ __launch_bounds__(256) void conv_all(ConvArgs a, unsigned total) {
    unsigned f4 = blockIdx.x * 256 + threadIdx.x;
    if (f4 >= total) return;
    int s = 0;
#pragma unroll
    for (int i = 0; i < 6; i++) if (f4 >= a.end[s]) s++;
    unsigned lo = f4 - (s ? a.end[s - 1] : 0);
    float4 v = ((const float4*)a.src[s])[lo];
    uint2 u = make_uint2(packbf(v.x, v.y), packbf(v.z, v.w));
    ((uint2*)a.dst[s])[lo] = u;
}

// ==================== 3-stage cp.async mma GEMM (ldmatrix fragments) ====
// C[M,N] = A[M,K] @ W[N,K]^T. Tile 64x64, 4 warps (warp 32x32), K chunk 64.
// EPI: 0 = +bias -> fp32 C ; 1 = gelu(+bias) -> bf16 Cbf only ;
//      2 = res + (+bias) -> fp32 C (+ optional bf16 Cbf) ;
//      3 = res + gamma*(+bias) -> fp32 C (+ optional bf16 Cbf) ;
//      5 = fused qkv rope epilogue (BN=64 tiles); res = rope cs table, gamma = logn table
__device__ __forceinline__ float gelu_f(float x) {
    return 0.5f * x * (1.0f + erff(x * 0.70710678118654752440f));
}

#define BM_ 64
#define BN_ 64
#define WM_G 32
#define GTHREADS 128

template<int EPI>
__global__ __launch_bounds__(GTHREADS, 4) void gemm_cp(
    const bf16* __restrict__ A, const bf16* __restrict__ W,
    const float* __restrict__ bias, const float* __restrict__ res,
    const float* __restrict__ gamma, float* __restrict__ C,
    bf16* __restrict__ Cbf, __half* __restrict__ Vh, int K, int N)
{
    constexpr int MA = WM_G / 16;                  // 2
    constexpr int ALOOP = BM_ * 8 / GTHREADS;      // 4
    constexpr int BLOOP = BN_ * 8 / GTHREADS;      // 4
    constexpr uint32_t ABYTES = BM_ * 72 * 2;
    constexpr uint32_t BBYTES = BN_ * 72 * 2;

    extern __shared__ bf16 sm[];
    bf16* As = sm;                    // [3][BM][72]
    bf16* Bs = sm + 3 * BM_ * 72;     // [3][BN][72]
    const uint32_t sA = smem_u32(As);
    const uint32_t sB = smem_u32(Bs);

    const int tid  = threadIdx.x;
    const int lane = tid & 31;
    const int wid  = tid >> 5;
    const int g  = lane >> 2;
    const int tg = lane & 3;
    const int wm = wid & 1;          // 2 warps in M
    const int wn = wid >> 1;         // 2 warps in N
    const int bm = blockIdx.y * BM_;
    const int bn = blockIdx.x * BN_;

    // ldmatrix lane-part offsets (bytes)
    const uint32_t a_lo = (uint32_t)(((lane & 15) * 72 + ((lane >> 4) << 3)) * 2);
    const int q8 = lane >> 3;
    const uint32_t b_lo = (uint32_t)(((((q8 >> 1) << 3) + (lane & 7)) * 72 + ((q8 & 1) << 3)) * 2);

    float acc[MA][4][4];
#pragma unroll
    for (int ma = 0; ma < MA; ma++)
#pragma unroll
        for (int na = 0; na < 4; na++)
#pragma unroll
            for (int r = 0; r < 4; r++) acc[ma][na][r] = 0.f;

    const bf16* Ab = A + (size_t)bm * K;
    const bf16* Wb = W + (size_t)bn * K;
    const int CH = K >> 6;

    auto issue = [&](int c) {
        const int st = c % 3;
        const int kof = c * 64;
#pragma unroll
        for (int i = 0; i < ALOOP; i++) {
            int v = tid + i * GTHREADS;
            int r = v >> 3, s = v & 7;
            cp16(sA + (uint32_t)((st * BM_ + r) * 72 + s * 8) * 2,
                 Ab + (size_t)r * K + kof + s * 8);
        }
#pragma unroll
        for (int i = 0; i < BLOOP; i++) {
            int v = tid + i * GTHREADS;
            int r = v >> 3, s = v & 7;
            cp16(sB + (uint32_t)((st * BN_ + r) * 72 + s * 8) * 2,
                 Wb + (size_t)r * K + kof + s * 8);
        }
        CP_COMMIT();
    };

    issue(0);
    issue(1);
    for (int c = 0; c < CH; c++) {
        if (c + 1 < CH) { CP_WAIT(1); }
        else            { CP_WAIT(0); }
        __syncthreads();
        if (c + 2 < CH) issue(c + 2);

        const int st = c % 3;
        const uint32_t aBase = sA + (uint32_t)st * ABYTES + (uint32_t)(wm * WM_G) * 144 + a_lo;
        const uint32_t bBase = sB + (uint32_t)st * BBYTES + (uint32_t)(wn * 32) * 144 + b_lo;
#pragma unroll
        for (int kc = 0; kc < 4; kc++) {
            uint32_t b01[4], b23[4];
            LDSM4(b01[0], b01[1], b01[2], b01[3], bBase + kc * 32);
            LDSM4(b23[0], b23[1], b23[2], b23[3], bBase + 16 * 144 + kc * 32);
#pragma unroll
            for (int ma = 0; ma < MA; ma++) {
                uint32_t af[4];
                LDSM4(af[0], af[1], af[2], af[3], aBase + (uint32_t)(ma * 16) * 144 + kc * 32);
                mma16816(acc[ma][0], af, b01[0], b01[1]);
                mma16816(acc[ma][1], af, b01[2], b01[3]);
                mma16816(acc[ma][2], af, b23[0], b23[1]);
                mma16816(acc[ma][3], af, b23[2], b23[3]);
            }
        }
    }
    __syncthreads();   // protect smem reuse in EPI5; orders last reads

    // ---------------- epilogue ----------------
    if (EPI == 5) {
        // qkv GEMM, BN=64 tiles: bn in {0..192}=Q, {256..448}=K, {512..704}=V.
        if (bn >= 512) {
#pragma unroll
            for (int ma = 0; ma < MA; ma++) {
                const int row0 = bm + wm * WM_G + ma * 16 + g;
#pragma unroll
                for (int na = 0; na < 4; na++) {
                    const int vcol = (bn - 512) + wn * 32 + na * 8 + tg * 2;
                    *(uint32_t*)(Vh + (size_t)row0 * 256 + vcol) = packh(acc[ma][na][0], acc[ma][na][1]);
                    *(uint32_t*)(Vh + (size_t)(row0 + 8) * 256 + vcol) = packh(acc[ma][na][2], acc[ma][na][3]);
                }
            }
        } else {
            // stage fp32 tile in smem, then rope pass using precomputed tables
            float* fbuf = (float*)sm;   // [BM][68] = 17.4 KB
#pragma unroll
            for (int ma = 0; ma < MA; ma++) {
                const int r0 = wm * WM_G + ma * 16 + g;
#pragma unroll
                for (int na = 0; na < 4; na++) {
                    const int col = wn * 32 + na * 8 + tg * 2;
                    *(float2*)&fbuf[r0 * 68 + col]       = make_float2(acc[ma][na][0], acc[ma][na][1]);
                    *(float2*)&fbuf[(r0 + 8) * 68 + col] = make_float2(acc[ma][na][2], acc[ma][na][3]);
                }
            }
            __syncthreads();
            const float2* cst = (const float2*)res;
            const bool isQ = (bn < 256);
            constexpr int ITERS = BM_ * 32 / GTHREADS;   // 16
#pragma unroll 4
            for (int i = 0; i < ITERS; i++) {
                int pi = tid + i * GTHREADS;    // 0 .. BM*32-1
                int row = pi >> 5;
                int d  = pi & 31;
                float f0 = fbuf[row * 68 + d];
                float f1 = fbuf[row * 68 + d + 32];
                int n = (bm + row) & (N_ - 1);
                float2 t = cst[n * 32 + d];
                float sc = isQ ? gamma[n] : 1.f;
                size_t R = (size_t)(bm + row);
                Cbf[R * 512 + bn + d]      = __float2bfloat16((f0 * t.x - f1 * t.y) * sc);
                Cbf[R * 512 + bn + d + 32] = __float2bfloat16((f1 * t.x + f0 * t.y) * sc);
            }
        }
        return;
    }

#pragma unroll
    for (int ma = 0; ma < MA; ma++) {
        const int row0 = bm + wm * WM_G + ma * 16 + g;
        const int row1 = row0 + 8;
#pragma unroll
        for (int na = 0; na < 4; na++) {
            const int col = bn + wn * 32 + na * 8 + tg * 2;
            float bx = 0.f, by = 0.f;
            if (bias) {
                float2 b2 = *(const float2*)(bias + col);
                bx = b2.x; by = b2.y;
            }
            float v00 = acc[ma][na][0] + bx, v01 = acc[ma][na][1] + by;
            float v10 = acc[ma][na][2] + bx, v11 = acc[ma][na][3] + by;
            const size_t o0 = (size_t)row0 * N + col;
            const size_t o1 = (size_t)row1 * N + col;
            if (EPI == 1) {
                v00 = gelu_f(v00); v01 = gelu_f(v01);
                v10 = gelu_f(v10); v11 = gelu_f(v11);
            } else if (EPI == 2) {
                float2 r0 = *(const float2*)(res + o0);
                float2 r1 = *(const float2*)(res + o1);
                v00 += r0.x; v01 += r0.y; v10 += r1.x; v11 += r1.y;
            } else if (EPI == 3) {
                float2 r0 = *(const float2*)(res + o0);
                float2 r1 = *(const float2*)(res + o1);
                float2 g2 = *(const float2*)(gamma + col);
                v00 = r0.x + g2.x * v00; v01 = r0.y + g2.y * v01;
                v10 = r1.x + g2.x * v10; v11 = r1.y + g2.y * v11;
            }
            if (EPI != 1) {
                *(float2*)(C + o0) = make_float2(v00, v01);
                *(float2*)(C + o1) = make_float2(v10, v11);
            }
            if (EPI == 1 || Cbf != nullptr) {
                *(uint32_t*)(Cbf + o0) = packbf(v00, v01);
                *(uint32_t*)(Cbf + o1) = packbf(v10, v11);
            }
        }
    }
}

// ==================== LayerNorm (rows of 256) -> bf16, float4 path ==========
__global__ __launch_bounds__(256) void ln_kernel(
    const float* __restrict__ in, const float* __restrict__ s,
    const float* __restrict__ b, bf16* __restrict__ out)
{
    int gw   = (blockIdx.x * blockDim.x + threadIdx.x) >> 5;
    int lane = threadIdx.x & 31;
    if (gw >= M_) return;
    const float* x = in + (size_t)gw * INT_;
    float4 v0 = *(const float4*)(x + lane * 4);
    float4 v1 = *(const float4*)(x + 128 + lane * 4);
    float sum = v0.x + v0.y + v0.z + v0.w + v1.x + v1.y + v1.z + v1.w;
    float sq  = v0.x * v0.x + v0.y * v0.y + v0.z * v0.z + v0.w * v0.w
              + v1.x * v1.x + v1.y * v1.y + v1.z * v1.z + v1.w * v1.w;
#pragma unroll
    for (int o = 16; o > 0; o >>= 1) {
        sum += __shfl_xor_sync(0xffffffffu, sum, o);
        sq  += __shfl_xor_sync(0xffffffffu, sq,  o);
    }
    float mean = sum * (1.f / 256.f);
    float var  = sq * (1.f / 256.f) - mean * mean;
    float rstd = rsqrtf(var + 1e-5f);
    bf16* y = out + (size_t)gw * INT_;
#pragma unroll
    for (int half = 0; half < 2; half++) {
        float4 v = half ? v1 : v0;
        int col = half * 128 + lane * 4;
        float4 s4 = *(const float4*)(s + col);
        float4 b4 = *(const float4*)(b + col);
        uint2 u = make_uint2(
            packbf((v.x - mean) * rstd * s4.x + b4.x,
                   (v.y - mean) * rstd * s4.y + b4.y),
            packbf((v.z - mean) * rstd * s4.z + b4.z,
                   (v.w - mean) * rstd * s4.w + b4.w));
        *(uint2*)(y + col) = u;
    }
}

// ==================== Flash attention, split-KV (4 chunks), f16x2-exp ====
// grid (N/64, B*H, 4), block 128 (4 warps). Scores arrive in log2 domain.
#define KT_PER_CHUNK 8

__global__ __launch_bounds__(128) void attn_part(const bf16* __restrict__ qk,
                                                 const __half* __restrict__ vh,
                                                 __half* __restrict__ Opart,
                                                 float* __restrict__ ml)
{
    __shared__ __align__(16) bf16   Qs[64][72];
    __shared__ __align__(16) bf16   Ks[2][64][72];
    __shared__ __align__(16) __half Vs[2][64][72];

    const int tid  = threadIdx.x;
    const int lane = tid & 31;
    const int w    = tid >> 5;
    const int g  = lane >> 2;
    const int tg = lane & 3;
    const int bh = blockIdx.y;
    const int b = bh >> 2, h = bh & 3;
    const int q0 = blockIdx.x * 64;
    const int ck = blockIdx.z;
    const uint32_t ks_base = smem_u32(&Ks[0][0][0]);
    const uint32_t vs_base = smem_u32(&Vs[0][0][0]);

    const int q8 = lane >> 3;
    const uint32_t k_lo = (uint32_t)(((((q8 >> 1) << 3) + (lane & 7)) * 72 + ((q8 & 1) << 3)) * 2);

    auto issueKV = [&](int kt) {
        const int p = kt & 1;
        const size_t krow = (size_t)(b * N_ + ck * (KT_PER_CHUNK * 64) + kt * 64);
        const bf16*  kb = qk + krow * 512 + 256 + h * 64;
        const __half* vb = vh + krow * 256 + h * 64;
#pragma unroll
        for (int i = 0; i < 4; i++) {
            int v = tid + i * 128;
            int r = v >> 3, s = v & 7;
            cp16(ks_base + (uint32_t)((p * 64 + r) * 72 + s * 8) * 2, kb + (size_t)r * 512 + s * 8);
            cp16(vs_base + (uint32_t)((p * 64 + r) * 72 + s * 8) * 2, vb + (size_t)r * 256 + s * 8);
        }
        CP_COMMIT();
    };

    issueKV(0);

    // load Q tile (sync loads)
    {
        const bf16* qb = qk + (size_t)(b * N_ + q0) * 512 + h * 64;
#pragma unroll
        for (int i = 0; i < 4; i++) {
            int v = tid + i * 128;
            int r = v >> 3, s = v & 7;
            *(uint4*)&Qs[r][s * 8] = *(const uint4*)(qb + (size_t)r * 512 + s * 8);
        }
    }
    __syncthreads();

    uint32_t qf[4][4];
    {
        const int r0 = w * 16 + g;
#pragma unroll
        for (int kc = 0; kc < 4; kc++) {
            qf[kc][0] = *(const uint32_t*)&Qs[r0    ][kc * 16 + tg * 2];
            qf[kc][1] = *(const uint32_t*)&Qs[r0 + 8][kc * 16 + tg * 2];
            qf[kc][2] = *(const uint32_t*)&Qs[r0    ][kc * 16 + 8 + tg * 2];
            qf[kc][3] = *(const uint32_t*)&Qs[r0 + 8][kc * 16 + 8 + tg * 2];
        }
    }

    const int q4 = lane >> 3;
    const int v_rowpart = (lane & 7) + 8 * (q4 & 1);
    const int v_colpart = 8 * (q4 >> 1);
    const uint32_t ONES2 = 0x3C003C00u;   // f16x2 {1,1}

    float m0 = -INFINITY, m1 = -INFINITY;
    float o[8][4], lacc[4];
#pragma unroll
    for (int nh = 0; nh < 8; nh++)
#pragma unroll
        for (int r = 0; r < 4; r++) o[nh][r] = 0.f;
#pragma unroll
    for (int r = 0; r < 4; r++) lacc[r] = 0.f;

    for (int kt = 0; kt < KT_PER_CHUNK; kt++) {
        const int p = kt & 1;
        if (kt + 1 < KT_PER_CHUNK) { issueKV(kt + 1); CP_WAIT(1); }
        else                       { CP_WAIT(0); }
        __syncthreads();

        // ---- S = Q K^T (log2 domain), K fragments via ldmatrix.x4 ----
        float s[8][4];
#pragma unroll
        for (int na = 0; na < 8; na++)
#pragma unroll
            for (int r = 0; r < 4; r++) s[na][r] = 0.f;
        const uint32_t kBase = ks_base + (uint32_t)(p * 64 * 144) + k_lo;
#pragma unroll
        for (int kc = 0; kc < 4; kc++) {
#pragma unroll
            for (int pr = 0; pr < 4; pr++) {
                uint32_t kb4[4];
                LDSM4(kb4[0], kb4[1], kb4[2], kb4[3],
                      kBase + (uint32_t)(pr * 16 * 144) + kc * 32);
                mma16816(s[2 * pr],     qf[kc], kb4[0], kb4[1]);
                mma16816(s[2 * pr + 1], qf[kc], kb4[2], kb4[3]);
            }
        }

        // ---- online softmax: max ----
        float mt0 = -INFINITY, mt1 = -INFINITY;
#pragma unroll
        for (int na = 0; na < 8; na++) {
            mt0 = fmaxf(mt0, fmaxf(s[na][0], s[na][1]));
            mt1 = fmaxf(mt1, fmaxf(s[na][2], s[na][3]));
        }
#pragma unroll
        for (int x = 1; x <= 2; x <<= 1) {
            mt0 = fmaxf(mt0, __shfl_xor_sync(0xffffffffu, mt0, x));
            mt1 = fmaxf(mt1, __shfl_xor_sync(0xffffffffu, mt1, x));
        }
        float mn0 = fmaxf(m0, mt0), mn1 = fmaxf(m1, mt1);
        float al0 = exp2f(m0 - mn0), al1 = exp2f(m1 - mn1);
        m0 = mn0; m1 = mn1;

        // ---- P = exp2(S - m) via f16x2 MUFU; directly the A-fragment ----
        uint32_t pf[4][4];
#pragma unroll
        for (int kc = 0; kc < 4; kc++) {
            pf[kc][0] = ex2_h2(s[2 * kc][0] - mn0,     s[2 * kc][1] - mn0);
            pf[kc][1] = ex2_h2(s[2 * kc][2] - mn1,     s[2 * kc][3] - mn1);
            pf[kc][2] = ex2_h2(s[2 * kc + 1][0] - mn0, s[2 * kc + 1][1] - mn0);
            pf[kc][3] = ex2_h2(s[2 * kc + 1][2] - mn1, s[2 * kc + 1][3] - mn1);
        }

        // ---- rescale O and l ----
#pragma unroll
        for (int nh = 0; nh < 8; nh++) {
            o[nh][0] *= al0; o[nh][1] *= al0;
            o[nh][2] *= al1; o[nh][3] *= al1;
        }
        lacc[0] *= al0; lacc[1] *= al0;
        lacc[2] *= al1; lacc[3] *= al1;

        // ---- O += P V ; l += P 1 ----
        const uint32_t vpb = vs_base + (uint32_t)(p * 64 * 72) * 2;
#pragma unroll
        for (int kc = 0; kc < 4; kc++) {
            mma16816h(lacc, pf[kc], ONES2, ONES2);
#pragma unroll
            for (int nh = 0; nh < 8; nh += 2) {
                uint32_t addr = vpb +
                    (uint32_t)((16 * kc + v_rowpart) * 144 + (nh * 8 + v_colpart) * 2);
                uint32_t b0, b1, b2, b3;
                asm volatile(
                    "ldmatrix.sync.aligned.m8n8.x4.trans.shared.b16 {%0,%1,%2,%3}, [%4];"
                    : "=r"(b0), "=r"(b1), "=r"(b2), "=r"(b3) : "r"(addr));
                mma16816h(o[nh],     pf[kc], b0, b1);
                mma16816h(o[nh + 1], pf[kc], b2, b3);
            }
        }
        __syncthreads();
    }

    // ---- write partial O (unnormalized, fp16) + m,l ----
    const int r0l = w * 16 + g;
    __half* Obase = Opart + ((size_t)(ck * 8 + bh) * N_ + q0) * 64;
#pragma unroll
    for (int nh = 0; nh < 8; nh++) {
        const int col = nh * 8 + tg * 2;
        *(uint32_t*)(Obase + (size_t)r0l * 64 + col)       = packh(o[nh][0], o[nh][1]);
        *(uint32_t*)(Obase + (size_t)(r0l + 8) * 64 + col) = packh(o[nh][2], o[nh][3]);
    }
    if (tg == 0) {
        size_t mi0 = ((size_t)(ck * 8 + bh) * N_ + q0 + r0l) * 2;
        size_t mi1 = ((size_t)(ck * 8 + bh) * N_ + q0 + r0l + 8) * 2;
        ml[mi0] = m0; ml[mi0 + 1] = lacc[0];
        ml[mi1] = m1; ml[mi1 + 1] = lacc[2];
    }
}

// ==================== attention combine (4 chunks, fp16 partials) ==========
__global__ __launch_bounds__(256) void attn_combine(const __half* __restrict__ Opart,
                                                    const float* __restrict__ ml,
                                                    bf16* __restrict__ out)
{
    int gw   = blockIdx.x * 8 + (threadIdx.x >> 5);   // 0..16383
    int lane = threadIdx.x & 31;
    int bh  = gw >> 11;
    int row = gw & 2047;
    int b = bh >> 2, h = bh & 3;

    float m[4], l[4];
#pragma unroll
    for (int c = 0; c < 4; c++) {
        size_t idx = ((size_t)(c * 8 + bh) * N_ + row) * 2;
        m[c] = ml[idx]; l[c] = ml[idx + 1];
    }
    float ms = fmaxf(fmaxf(m[0], m[1]), fmaxf(m[2], m[3]));
    float wsum = 0.f, a0 = 0.f, a1 = 0.f;
#pragma unroll
    for (int c = 0; c < 4; c++) {
        float wc = exp2f(m[c] - ms);
        wsum += wc * l[c];
        __half2 hv = *(const __half2*)(Opart + ((size_t)(c * 8 + bh) * N_ + row) * 64 + lane * 2);
        float2 v = __half22float2(hv);
        a0 += wc * v.x; a1 += wc * v.y;
    }
    float inv = 1.f / wsum;
    *(uint32_t*)(out + ((size_t)(b * N_ + row)) * INT_ + h * 64 + lane * 2) =
        packbf(a0 * inv, a1 * inv);
}

// ==================== host ====================
extern "C" void kernel_launch(void* const* d_in, const int* in_sizes, int n_in,
                              void* d_out, int out_size)
{
    (void)in_sizes; (void)n_in; (void)out_size;
    const float* x   = (const float*)d_in[0];
    const float* dw  = (const float*)d_in[1];
    const float* db  = (const float*)d_in[2];
    const float* nds = (const float*)d_in[3];
    const float* ndb = (const float*)d_in[4];
    const float* qw  = (const float*)d_in[5];
    const float* pw  = (const float*)d_in[6];
    const float* pb  = (const float*)d_in[7];
    const float* nms = (const float*)d_in[8];
    const float* nmb = (const float*)d_in[9];
    const float* m1w = (const float*)d_in[10];
    const float* m1b = (const float*)d_in[11];
    const float* m2w = (const float*)d_in[12];
    const float* m2b = (const float*)d_in[13];
    const float* uw  = (const float*)d_in[14];
    const float* ub  = (const float*)d_in[15];
    const float* gm  = (const float*)d_in[16];

    float *X, *Hb, *mlp, *cst, *lnt;
    __half *Opart;
    bf16 *qkbf, *xbf, *hnbf, *attbf, *g1bf, *hbf;
    __half* vh;
    bf16 *wd, *wq, *wp, *w1, *w2, *wu;
    cudaGetSymbolAddress((void**)&X,     g_X);
    cudaGetSymbolAddress((void**)&Hb,    g_H);
    cudaGetSymbolAddress((void**)&Opart, g_Opart);
    cudaGetSymbolAddress((void**)&mlp,   g_ml);
    cudaGetSymbolAddress((void**)&cst,   g_cs);
    cudaGetSymbolAddress((void**)&lnt,   g_lns);
    cudaGetSymbolAddress((void**)&qkbf,  g_qkbf);
    cudaGetSymbolAddress((void**)&vh,    g_vh);
    cudaGetSymbolAddress((void**)&xbf,   g_xbf);
    cudaGetSymbolAddress((void**)&hnbf,  g_hnbf);
    cudaGetSymbolAddress((void**)&attbf, g_attbf);
    cudaGetSymbolAddress((void**)&g1bf,  g_g1bf);
    cudaGetSymbolAddress((void**)&hbf,   g_hbf);
    cudaGetSymbolAddress((void**)&wd,    g_wdown);
    cudaGetSymbolAddress((void**)&wq,    g_wqkv);
    cudaGetSymbolAddress((void**)&wp,    g_wproj);
    cudaGetSymbolAddress((void**)&w1,    g_wm1);
    cudaGetSymbolAddress((void**)&w2,    g_wm2);
    cudaGetSymbolAddress((void**)&wu,    g_wup);

    const int SM3 = 3 * (BM_ + BN_) * 72 * 2;   // 55296
    cudaFuncSetAttribute(gemm_cp<0>, cudaFuncAttributeMaxDynamicSharedMemorySize, SM3);
    cudaFuncSetAttribute(gemm_cp<1>, cudaFuncAttributeMaxDynamicSharedMemorySize, SM3);
    cudaFuncSetAttribute(gemm_cp<2>, cudaFuncAttributeMaxDynamicSharedMemorySize, SM3);
    cudaFuncSetAttribute(gemm_cp<3>, cudaFuncAttributeMaxDynamicSharedMemorySize, SM3);
    cudaFuncSetAttribute(gemm_cp<5>, cudaFuncAttributeMaxDynamicSharedMemorySize, SM3);

    // rope tables (deterministic; every call)
    rope_init<<<(N_ * 32) / 256, 256>>>();

    // one batched convert for input x + all weights
    {
        ConvArgs a;
        const float* srcs[7] = {x, dw, qw, pw, m1w, m2w, uw};
        bf16* dsts[7] = {xbf, wd, wq, wp, w1, w2, wu};
        unsigned sizes[7] = {
            M_ * D_ / 4,
            (unsigned)(L_ * INT_ * D_ / 4),
            (unsigned)(L_ * 3 * INT_ * INT_ / 4),
            (unsigned)(L_ * INT_ * INT_ / 4),
            (unsigned)(L_ * HID_ * INT_ / 4),
            (unsigned)(L_ * INT_ * HID_ / 4),
            (unsigned)(L_ * D_ * INT_ / 4)};
        unsigned acc = 0;
        for (int i = 0; i < 7; i++) {
            a.src[i] = srcs[i]; a.dst[i] = dsts[i];
            acc += sizes[i]; a.end[i] = acc;
        }
        conv_all<<<(acc + 255) / 256, 256>>>(a, acc);
    }

    for (int l = 0; l < L_; l++) {
        const float* xin = (l == 0) ? x : X;
        float* xout = (l == L_ - 1) ? (float*)d_out : X;
        bf16* xbf_out = (l == L_ - 1) ? nullptr : xbf;

        // h = x @ down_w^T + down_b   [4096x256, K=1024] -> 256 CTAs
        gemm_cp<0><<<dim3(INT_ / 64, M_ / 64), GTHREADS, SM3>>>(
            xbf, wd + (size_t)l * INT_ * D_, db + (size_t)l * INT_,
            nullptr, nullptr, Hb, nullptr, nullptr, D_, INT_);
        // hn = LN(h) -> bf16
        ln_kernel<<<(M_ * 32) / 256, 256>>>(Hb, nds + (size_t)l * INT_,
                                            ndb + (size_t)l * INT_, hnbf);
        // qkv = hn @ qkv_w^T  with fused rope epilogue (tables) -> 768 CTAs
        gemm_cp<5><<<dim3(12, M_ / 64), GTHREADS, SM3>>>(
            hnbf, wq + (size_t)l * 3 * INT_ * INT_, nullptr,
            cst, lnt, nullptr, qkbf, vh, INT_, 768);
        // attention: 4 KV chunks -> 1024 CTAs, then combine
        attn_part<<<dim3(N_ / 64, B_ * H_, 4), 128>>>(qkbf, vh, Opart, mlp);
        attn_combine<<<(8 * N_) / 8, 256>>>(Opart, mlp, attbf);
        // h = res + (o @ proj_w^T + proj_b)   -> 256 CTAs
        gemm_cp<2><<<dim3(INT_ / 64, M_ / 64), GTHREADS, SM3>>>(
            attbf, wp + (size_t)l * INT_ * INT_, pb + (size_t)l * INT_,
            Hb, nullptr, Hb, nullptr, nullptr, INT_, INT_);
        // m = LN(h) -> bf16
        ln_kernel<<<(M_ * 32) / 256, 256>>>(Hb, nms + (size_t)l * INT_,
                                            nmb + (size_t)l * INT_, hnbf);
        // g1 = gelu(m @ m1^T + b1) -> bf16 only   -> 512 CTAs
        gemm_cp<1><<<dim3(HID_ / 64, M_ / 64), GTHREADS, SM3>>>(
            hnbf, w1 + (size_t)l * HID_ * INT_, m1b + (size_t)l * HID_,
            nullptr, nullptr, nullptr, g1bf, nullptr, INT_, HID_);
        // h = h + (g1 @ m2^T + b2) -> fp32 Hb + bf16 hbf   -> 256 CTAs
        gemm_cp<2><<<dim3(INT_ / 64, M_ / 64), GTHREADS, SM3>>>(
            g1bf, w2 + (size_t)l * INT_ * HID_, m2b + (size_t)l * INT_,
            Hb, nullptr, Hb, hbf, nullptr, HID_, INT_);
        // x = shortcut + gamma * (h @ up^T + ub)   -> 1024 CTAs
        gemm_cp<3><<<dim3(D_ / 64, M_ / 64), GTHREADS, SM3>>>(
            hbf, wu + (size_t)l * D_ * INT_, ub + (size_t)l * D_,
            xin, gm + (size_t)l * D_, xout, xbf_out, nullptr, INT_, D_);
    }
}